// round 1
// baseline (speedup 1.0000x reference)
#include <cuda_runtime.h>
#include <cuda_bf16.h>
#include <math.h>

#define Bn 2
#define Sn 2048
#define Dn 2048
#define HQn 32
#define HKVn 8
#define HDn 64
#define QPKn 4
#define ROWS (Bn * Sn)      // 4096
#define NG   (Bn * HQn)     // 64 batched attention "heads" (b, hkv, qpk)

// ---------------- scratch (device globals; no allocation) ----------------
__device__ float g_xn[ROWS * Dn];                        // 33.5 MB
__device__ float g_q[ROWS * (HQn * HDn)];                // 33.5 MB
__device__ float g_k[ROWS * (HKVn * HDn)];               // 8.4 MB
__device__ float g_v[ROWS * (HKVn * HDn)];               // 8.4 MB
__device__ float g_sc[(size_t)NG * Sn * Sn];             // 1.07 GB  s[g][T][t] -> p
__device__ float g_attn[ROWS * (HQn * HDn)];             // 33.5 MB

// ---------------- LayerNorm (two-pass) ----------------
__global__ void ln_kernel(const float* __restrict__ x,
                          const float* __restrict__ gamma,
                          const float* __restrict__ beta,
                          float* __restrict__ xn) {
    const int row = blockIdx.x;
    const float* xr = x + (size_t)row * Dn;
    float* outr = xn + (size_t)row * Dn;
    __shared__ float red[256];
    const int tid = threadIdx.x;

    float s = 0.f;
    for (int c = tid; c < Dn; c += 256) s += xr[c];
    red[tid] = s; __syncthreads();
    for (int off = 128; off > 0; off >>= 1) {
        if (tid < off) red[tid] += red[tid + off];
        __syncthreads();
    }
    const float mu = red[0] * (1.0f / Dn);
    __syncthreads();

    float v = 0.f;
    for (int c = tid; c < Dn; c += 256) { float d = xr[c] - mu; v += d * d; }
    red[tid] = v; __syncthreads();
    for (int off = 128; off > 0; off >>= 1) {
        if (tid < off) red[tid] += red[tid + off];
        __syncthreads();
    }
    const float rstd = rsqrtf(red[0] * (1.0f / Dn) + 1e-5f);
    __syncthreads();

    for (int c = tid; c < Dn; c += 256)
        outr[c] = (xr[c] - mu) * rstd * gamma[c] + beta[c];
}

// ---------------- generic NN GEMM: C = scale*(A[MxK] @ B[KxN] + bias) ----------------
// BM=BN=64, BK=16, 256 threads, 4x4 per thread. M,N,K multiples of 64/16.
__global__ void gemm_nn(const float* __restrict__ A, const float* __restrict__ B,
                        const float* __restrict__ bias, float* __restrict__ C,
                        int M, int N, int K, float scale) {
    __shared__ float As[64][17];
    __shared__ float Bs[16][65];
    const int tid = threadIdx.x;
    const int ty = tid >> 4, tx = tid & 15;
    const int m0 = blockIdx.y * 64, n0 = blockIdx.x * 64;

    float acc[4][4] = {};
    for (int k0 = 0; k0 < K; k0 += 16) {
        #pragma unroll
        for (int i = 0; i < 4; i++) {
            int idx = tid + i * 256;
            int r = idx >> 4, c = idx & 15;
            As[r][c] = A[(size_t)(m0 + r) * K + k0 + c];
        }
        #pragma unroll
        for (int i = 0; i < 4; i++) {
            int idx = tid + i * 256;
            int r = idx >> 6, c = idx & 63;
            Bs[r][c] = B[(size_t)(k0 + r) * N + n0 + c];
        }
        __syncthreads();
        #pragma unroll
        for (int kk = 0; kk < 16; kk++) {
            float a[4], b[4];
            #pragma unroll
            for (int i = 0; i < 4; i++) a[i] = As[ty * 4 + i][kk];
            #pragma unroll
            for (int j = 0; j < 4; j++) b[j] = Bs[kk][tx * 4 + j];
            #pragma unroll
            for (int i = 0; i < 4; i++)
                #pragma unroll
                for (int j = 0; j < 4; j++)
                    acc[i][j] = fmaf(a[i], b[j], acc[i][j]);
        }
        __syncthreads();
    }
    #pragma unroll
    for (int i = 0; i < 4; i++)
        #pragma unroll
        for (int j = 0; j < 4; j++) {
            int n = n0 + tx * 4 + j;
            float bi = bias ? bias[n] : 0.f;
            C[(size_t)(m0 + ty * 4 + i) * N + n] = scale * (acc[i][j] + bi);
        }
}

// ---------------- scores: s[g][T][t] = k_T . q_t  (NT batched) ----------------
__global__ void scores_kernel(const float* __restrict__ Q, const float* __restrict__ Km,
                              float* __restrict__ Sc) {
    const int g = blockIdx.z;
    const int b = g >> 5;          // /32
    const int hq = g & 31;         // h*4+q
    const int h = hq >> 2;
    const int T0 = blockIdx.y * 64;
    const int t0 = blockIdx.x * 64;
    if (t0 + 63 < T0) return;      // fully masked tile

    const float* Ab = Km + (size_t)(b * Sn + T0) * (HKVn * HDn) + h * HDn; // rows T, ld=512
    const float* Bb = Q  + (size_t)(b * Sn + t0) * (HQn * HDn) + hq * HDn; // rows t, ld=2048

    __shared__ float As[64][17];
    __shared__ float Bs[64][17];
    const int tid = threadIdx.x;
    const int ty = tid >> 4, tx = tid & 15;

    float acc[4][4] = {};
    #pragma unroll
    for (int k0 = 0; k0 < HDn; k0 += 16) {
        #pragma unroll
        for (int i = 0; i < 4; i++) {
            int idx = tid + i * 256;
            int r = idx >> 4, c = idx & 15;
            As[r][c] = Ab[(size_t)r * (HKVn * HDn) + k0 + c];
            Bs[r][c] = Bb[(size_t)r * (HQn * HDn) + k0 + c];
        }
        __syncthreads();
        #pragma unroll
        for (int kk = 0; kk < 16; kk++) {
            float a[4], b2[4];
            #pragma unroll
            for (int i = 0; i < 4; i++) a[i] = As[ty * 4 + i][kk];
            #pragma unroll
            for (int j = 0; j < 4; j++) b2[j] = Bs[tx * 4 + j][kk];
            #pragma unroll
            for (int i = 0; i < 4; i++)
                #pragma unroll
                for (int j = 0; j < 4; j++)
                    acc[i][j] = fmaf(a[i], b2[j], acc[i][j]);
        }
        __syncthreads();
    }
    #pragma unroll
    for (int i = 0; i < 4; i++)
        #pragma unroll
        for (int j = 0; j < 4; j++)
            Sc[((size_t)g * Sn + (T0 + ty * 4 + i)) * Sn + t0 + tx * 4 + j] = acc[i][j];
}

// ---------------- per-key-column softmax over queries t >= T (in place) ----------------
__global__ void softmax_col(float* __restrict__ Sc) {
    const int T = blockIdx.x;
    const int g = blockIdx.y;
    float* row = Sc + ((size_t)g * Sn + T) * Sn;
    const int tid = threadIdx.x;
    __shared__ float red[256];

    float m = -INFINITY;
    for (int t = T + tid; t < Sn; t += 256) m = fmaxf(m, row[t]);
    red[tid] = m; __syncthreads();
    for (int off = 128; off > 0; off >>= 1) {
        if (tid < off) red[tid] = fmaxf(red[tid], red[tid + off]);
        __syncthreads();
    }
    m = red[0]; __syncthreads();

    float s = 0.f;
    for (int t = T + tid; t < Sn; t += 256) s += __expf(row[t] - m);
    red[tid] = s; __syncthreads();
    for (int off = 128; off > 0; off >>= 1) {
        if (tid < off) red[tid] += red[tid + off];
        __syncthreads();
    }
    const float invl = 1.0f / red[0];

    for (int t = tid; t < Sn; t += 256)
        row[t] = (t >= T) ? __expf(row[t] - m) * invl : 0.f;
}

// ---------------- out[g][t][d] = sum_T p[g][T][t] * v[T][d]  (TN batched) ----------------
__global__ void attn_out(const float* __restrict__ Sc, const float* __restrict__ V,
                         float* __restrict__ O) {
    const int g = blockIdx.z;
    const int b = g >> 5;
    const int hq = g & 31;
    const int h = hq >> 2;
    const int t0 = blockIdx.y * 64;

    __shared__ float Ps[16][65];
    __shared__ float Vs[16][65];
    const int tid = threadIdx.x;
    const int ty = tid >> 4, tx = tid & 15;

    float acc[4][4] = {};
    const int kmax = t0 + 64;  // only T <= t0+63 contribute (p zero above)
    for (int T0 = 0; T0 < kmax; T0 += 16) {
        #pragma unroll
        for (int i = 0; i < 4; i++) {
            int idx = tid + i * 256;
            int r = idx >> 6, c = idx & 63;
            Ps[r][c] = Sc[((size_t)g * Sn + (T0 + r)) * Sn + t0 + c];
            Vs[r][c] = V[(size_t)(b * Sn + T0 + r) * (HKVn * HDn) + h * HDn + c];
        }
        __syncthreads();
        #pragma unroll
        for (int kk = 0; kk < 16; kk++) {
            float a[4], v2[4];
            #pragma unroll
            for (int i = 0; i < 4; i++) a[i] = Ps[kk][ty * 4 + i];
            #pragma unroll
            for (int j = 0; j < 4; j++) v2[j] = Vs[kk][tx * 4 + j];
            #pragma unroll
            for (int i = 0; i < 4; i++)
                #pragma unroll
                for (int j = 0; j < 4; j++)
                    acc[i][j] = fmaf(a[i], v2[j], acc[i][j]);
        }
        __syncthreads();
    }
    #pragma unroll
    for (int i = 0; i < 4; i++)
        #pragma unroll
        for (int j = 0; j < 4; j++)
            O[(size_t)(b * Sn + t0 + ty * 4 + i) * (HQn * HDn) + hq * HDn + tx * 4 + j] = acc[i][j];
}

// ---------------- launch ----------------
extern "C" void kernel_launch(void* const* d_in, const int* in_sizes, int n_in,
                              void* d_out, int out_size) {
    const float* x    = (const float*)d_in[0];
    const float* ln_g = (const float*)d_in[1];
    const float* ln_b = (const float*)d_in[2];
    const float* Wq   = (const float*)d_in[3];
    const float* bq   = (const float*)d_in[4];
    const float* Wk   = (const float*)d_in[5];
    const float* bk   = (const float*)d_in[6];
    const float* Wv   = (const float*)d_in[7];
    const float* bv   = (const float*)d_in[8];
    const float* Wo   = (const float*)d_in[9];
    const float* bo   = (const float*)d_in[10];
    float* out = (float*)d_out;

    float *xn, *q, *k, *v, *sc, *attn;
    cudaGetSymbolAddress((void**)&xn,   g_xn);
    cudaGetSymbolAddress((void**)&q,    g_q);
    cudaGetSymbolAddress((void**)&k,    g_k);
    cudaGetSymbolAddress((void**)&v,    g_v);
    cudaGetSymbolAddress((void**)&sc,   g_sc);
    cudaGetSymbolAddress((void**)&attn, g_attn);

    ln_kernel<<<ROWS, 256>>>(x, ln_g, ln_b, xn);

    gemm_nn<<<dim3(2048 / 64, ROWS / 64), 256>>>(xn, Wq, bq, q, ROWS, 2048, 2048, 0.125f);
    gemm_nn<<<dim3(512 / 64,  ROWS / 64), 256>>>(xn, Wk, bk, k, ROWS, 512, 2048, 1.0f);
    gemm_nn<<<dim3(512 / 64,  ROWS / 64), 256>>>(xn, Wv, bv, v, ROWS, 512, 2048, 1.0f);

    scores_kernel<<<dim3(Sn / 64, Sn / 64, NG), 256>>>(q, k, sc);
    softmax_col<<<dim3(Sn, NG), 256>>>(sc);
    attn_out<<<dim3(1, Sn / 64, NG), 256>>>(sc, v, attn);

    gemm_nn<<<dim3(2048 / 64, ROWS / 64), 256>>>(attn, Wo, bo, out, ROWS, 2048, 2048, 1.0f);
}

// round 3
// speedup vs baseline: 3.0879x; 3.0879x over previous
#include <cuda_runtime.h>
#include <cuda_bf16.h>
#include <cstdint>
#include <math.h>

#define Bn 2
#define Sn 2048
#define Dn 2048
#define HQn 32
#define HKVn 8
#define HDn 64
#define ROWS (Bn * Sn)      // 4096
#define NG   (Bn * HQn)     // 64 attention "heads" (b, hkv*qpk)

// ---------------- scratch (device globals; no allocation) ----------------
__device__ float g_xn[ROWS * Dn];
__device__ float g_q[ROWS * (HQn * HDn)];
__device__ float g_k[ROWS * (HKVn * HDn)];
__device__ float g_v[ROWS * (HKVn * HDn)];
__device__ float g_sc[(size_t)NG * Sn * Sn];   // s[g][T][t] -> p
__device__ float g_attn[ROWS * (HQn * HDn)];

// ---------------- tf32 helpers ----------------
__device__ __forceinline__ float f2tf(float x) {
    uint32_t r;
    asm("cvt.rna.tf32.f32 %0, %1;" : "=r"(r) : "f"(x));
    return __uint_as_float(r);
}
__device__ __forceinline__ float4 cvt4(float4 v) {
    v.x = f2tf(v.x); v.y = f2tf(v.y); v.z = f2tf(v.z); v.w = f2tf(v.w);
    return v;
}
__device__ __forceinline__ void mma8(float* c, const uint32_t* a, uint32_t b0, uint32_t b1) {
    asm volatile(
        "mma.sync.aligned.m16n8k8.row.col.f32.tf32.tf32.f32 "
        "{%0,%1,%2,%3}, {%4,%5,%6,%7}, {%8,%9}, {%0,%1,%2,%3};"
        : "+f"(c[0]), "+f"(c[1]), "+f"(c[2]), "+f"(c[3])
        : "r"(a[0]), "r"(a[1]), "r"(a[2]), "r"(a[3]), "r"(b0), "r"(b1));
}
#define F2U(x) __float_as_uint(x)

// ---------------- LayerNorm ----------------
__global__ void ln_kernel(const float* __restrict__ x,
                          const float* __restrict__ gamma,
                          const float* __restrict__ beta,
                          float* __restrict__ xn) {
    const int row = blockIdx.x;
    const float* xr = x + (size_t)row * Dn;
    float* outr = xn + (size_t)row * Dn;
    __shared__ float red[256];
    const int tid = threadIdx.x;

    float s = 0.f;
    for (int c = tid; c < Dn; c += 256) s += xr[c];
    red[tid] = s; __syncthreads();
    for (int off = 128; off > 0; off >>= 1) {
        if (tid < off) red[tid] += red[tid + off];
        __syncthreads();
    }
    const float mu = red[0] * (1.0f / Dn);
    __syncthreads();

    float v = 0.f;
    for (int c = tid; c < Dn; c += 256) { float d = xr[c] - mu; v += d * d; }
    red[tid] = v; __syncthreads();
    for (int off = 128; off > 0; off >>= 1) {
        if (tid < off) red[tid] += red[tid + off];
        __syncthreads();
    }
    const float rstd = rsqrtf(red[0] * (1.0f / Dn) + 1e-5f);
    __syncthreads();

    for (int c = tid; c < Dn; c += 256)
        outr[c] = (xr[c] - mu) * rstd * gamma[c] + beta[c];
}

// ---------------- tf32 NN GEMM: C = scale*(A[MxK]@B[KxN] + bias) ----------------
// BM=128, BN=128, BK=16, 256 threads (8 warps 4x2), warp tile 32x64.
__global__ __launch_bounds__(256) void gemm_nn_tf32(
    const float* __restrict__ A, const float* __restrict__ B,
    const float* __restrict__ bias, float* __restrict__ C,
    int M, int N, int K, float scale)
{
    __shared__ float As[2][128][20];   // stride 20 = 4 mod 32 -> conflict-free a-frags
    __shared__ float Bs[2][16][136];   // stride 136 = 8 mod 32 -> conflict-free b-frags

    const int tid = threadIdx.x;
    const int lane = tid & 31, wid = tid >> 5;
    const int warp_m = wid & 3, warp_n = wid >> 2;
    const int m0 = blockIdx.y * 128, n0 = blockIdx.x * 128;

    const int ar = tid >> 2, ac = (tid & 3) * 4;   // A: 64 rows/pass x2
    const int br = tid >> 5, bc = (tid & 31) * 4;  // B: 8 rows/pass x2

    const int lr = lane >> 2, lc = lane & 3;

    float acc[2][8][4];
    #pragma unroll
    for (int i = 0; i < 2; i++)
        #pragma unroll
        for (int j = 0; j < 8; j++)
            #pragma unroll
            for (int q = 0; q < 4; q++) acc[i][j][q] = 0.f;

    // prologue: load k-tile 0 into buffer 0
    {
        float4 a0 = cvt4(*(const float4*)&A[(size_t)(m0 + ar) * K + ac]);
        float4 a1 = cvt4(*(const float4*)&A[(size_t)(m0 + ar + 64) * K + ac]);
        float4 b0 = cvt4(*(const float4*)&B[(size_t)br * N + n0 + bc]);
        float4 b1 = cvt4(*(const float4*)&B[(size_t)(br + 8) * N + n0 + bc]);
        *(float4*)&As[0][ar][ac] = a0;
        *(float4*)&As[0][ar + 64][ac] = a1;
        *(float4*)&Bs[0][br][bc] = b0;
        *(float4*)&Bs[0][br + 8][bc] = b1;
    }
    __syncthreads();

    const int KT = K / 16;
    int cur = 0;
    for (int kt = 0; kt < KT; kt++) {
        float4 a0, a1, b0, b1;
        const bool has = (kt + 1 < KT);
        if (has) {
            const int k0 = (kt + 1) * 16;
            a0 = *(const float4*)&A[(size_t)(m0 + ar) * K + k0 + ac];
            a1 = *(const float4*)&A[(size_t)(m0 + ar + 64) * K + k0 + ac];
            b0 = *(const float4*)&B[(size_t)(k0 + br) * N + n0 + bc];
            b1 = *(const float4*)&B[(size_t)(k0 + br + 8) * N + n0 + bc];
        }
        #pragma unroll
        for (int ks = 0; ks < 2; ks++) {
            const int k8 = ks * 8;
            uint32_t af[2][4];
            #pragma unroll
            for (int im = 0; im < 2; im++) {
                const int m = warp_m * 32 + im * 16 + lr;
                af[im][0] = F2U(As[cur][m][k8 + lc]);
                af[im][1] = F2U(As[cur][m + 8][k8 + lc]);
                af[im][2] = F2U(As[cur][m][k8 + lc + 4]);
                af[im][3] = F2U(As[cur][m + 8][k8 + lc + 4]);
            }
            #pragma unroll
            for (int jn = 0; jn < 8; jn++) {
                const int n = warp_n * 64 + jn * 8 + lr;
                uint32_t bf0 = F2U(Bs[cur][k8 + lc][n]);
                uint32_t bf1 = F2U(Bs[cur][k8 + lc + 4][n]);
                #pragma unroll
                for (int im = 0; im < 2; im++)
                    mma8(acc[im][jn], af[im], bf0, bf1);
            }
        }
        if (has) {
            const int nxt = cur ^ 1;
            *(float4*)&As[nxt][ar][ac] = cvt4(a0);
            *(float4*)&As[nxt][ar + 64][ac] = cvt4(a1);
            *(float4*)&Bs[nxt][br][bc] = cvt4(b0);
            *(float4*)&Bs[nxt][br + 8][bc] = cvt4(b1);
            __syncthreads();
            cur = nxt;
        }
    }

    #pragma unroll
    for (int im = 0; im < 2; im++)
        #pragma unroll
        for (int jn = 0; jn < 8; jn++) {
            const int row = m0 + warp_m * 32 + im * 16 + lr;
            const int col = n0 + warp_n * 64 + jn * 8 + lc * 2;
            const float bb0 = bias[col], bb1 = bias[col + 1];
            float2 v0 = make_float2(scale * (acc[im][jn][0] + bb0),
                                    scale * (acc[im][jn][1] + bb1));
            float2 v1 = make_float2(scale * (acc[im][jn][2] + bb0),
                                    scale * (acc[im][jn][3] + bb1));
            *(float2*)&C[(size_t)row * N + col] = v0;
            *(float2*)&C[(size_t)(row + 8) * N + col] = v1;
        }
}

// ---------------- scores: s[g][T][t] = k_T . q_t (tf32 mma) ----------------
// 64x64 tile per block, K=64 single pass, 128 threads (4 warps 2x2), warp 32x32.
__global__ __launch_bounds__(128) void scores_tf32(
    const float* __restrict__ Q, const float* __restrict__ Km,
    float* __restrict__ Sc)
{
    const int g = blockIdx.z;
    const int b = g >> 5, hq = g & 31, h = hq >> 2;
    const int T0 = blockIdx.y * 64;
    const int t0 = blockIdx.x * 64;
    if (t0 + 63 < T0) return;

    __shared__ float Ks[64][68];   // 68 = 4 mod 32
    __shared__ float Qs[64][68];

    const int tid = threadIdx.x;
    const int lane = tid & 31, wid = tid >> 5;
    const int warp_m = wid & 1, warp_n = wid >> 1;
    const int lr = lane >> 2, lc = lane & 3;

    {
        const int r = tid >> 4, c = (tid & 15) * 4;
        #pragma unroll
        for (int p = 0; p < 8; p++) {
            const int row = p * 8 + r;
            *(float4*)&Ks[row][c] =
                cvt4(*(const float4*)&Km[(size_t)(b * Sn + T0 + row) * (HKVn * HDn) + h * HDn + c]);
            *(float4*)&Qs[row][c] =
                cvt4(*(const float4*)&Q[(size_t)(b * Sn + t0 + row) * (HQn * HDn) + hq * HDn + c]);
        }
    }
    __syncthreads();

    float acc[2][4][4];
    #pragma unroll
    for (int i = 0; i < 2; i++)
        #pragma unroll
        for (int j = 0; j < 4; j++)
            #pragma unroll
            for (int q = 0; q < 4; q++) acc[i][j][q] = 0.f;

    #pragma unroll
    for (int ks = 0; ks < 8; ks++) {
        const int k8 = ks * 8;
        uint32_t af[2][4];
        #pragma unroll
        for (int im = 0; im < 2; im++) {
            const int m = warp_m * 32 + im * 16 + lr;
            af[im][0] = F2U(Ks[m][k8 + lc]);
            af[im][1] = F2U(Ks[m + 8][k8 + lc]);
            af[im][2] = F2U(Ks[m][k8 + lc + 4]);
            af[im][3] = F2U(Ks[m + 8][k8 + lc + 4]);
        }
        #pragma unroll
        for (int jn = 0; jn < 4; jn++) {
            const int n = warp_n * 32 + jn * 8 + lr;
            uint32_t bf0 = F2U(Qs[n][k8 + lc]);
            uint32_t bf1 = F2U(Qs[n][k8 + lc + 4]);
            #pragma unroll
            for (int im = 0; im < 2; im++)
                mma8(acc[im][jn], af[im], bf0, bf1);
        }
    }

    #pragma unroll
    for (int im = 0; im < 2; im++)
        #pragma unroll
        for (int jn = 0; jn < 4; jn++) {
            const int row = T0 + warp_m * 32 + im * 16 + lr;
            const int col = t0 + warp_n * 32 + jn * 8 + lc * 2;
            *(float2*)&Sc[((size_t)g * Sn + row) * Sn + col] =
                make_float2(acc[im][jn][0], acc[im][jn][1]);
            *(float2*)&Sc[((size_t)g * Sn + row + 8) * Sn + col] =
                make_float2(acc[im][jn][2], acc[im][jn][3]);
        }
}

// ---------------- per-key-column softmax over queries t >= T (1R + 1W) ----------------
__global__ __launch_bounds__(256) void softmax_col(float* __restrict__ Sc) {
    const int T = blockIdx.x;
    const int g = blockIdx.y;
    float* row = Sc + ((size_t)g * Sn + T) * Sn;
    const int tid = threadIdx.x;
    __shared__ float red[256];

    float v[8];
    const int base = tid * 8;
    *(float4*)&v[0] = *(const float4*)&row[base];
    *(float4*)&v[4] = *(const float4*)&row[base + 4];

    float m = -INFINITY;
    #pragma unroll
    for (int i = 0; i < 8; i++)
        if (base + i >= T) m = fmaxf(m, v[i]);
    red[tid] = m; __syncthreads();
    for (int off = 128; off > 0; off >>= 1) {
        if (tid < off) red[tid] = fmaxf(red[tid], red[tid + off]);
        __syncthreads();
    }
    m = red[0]; __syncthreads();

    float s = 0.f;
    #pragma unroll
    for (int i = 0; i < 8; i++) {
        float e = (base + i >= T) ? __expf(v[i] - m) : 0.f;
        v[i] = e;
        s += e;
    }
    red[tid] = s; __syncthreads();
    for (int off = 128; off > 0; off >>= 1) {
        if (tid < off) red[tid] += red[tid + off];
        __syncthreads();
    }
    const float inv = 1.0f / red[0];

    #pragma unroll
    for (int i = 0; i < 8; i++) v[i] *= inv;
    *(float4*)&row[base] = *(float4*)&v[0];
    *(float4*)&row[base + 4] = *(float4*)&v[4];
}

// ---------------- out[g][t][d] = sum_T p[g][T][t] * v[T][d] (tf32 mma) ----------------
// C tile 64(t)x64(d), K-loop over T in 64-chunks up to t0+64. 128 threads, 4 warps 2x2.
__global__ __launch_bounds__(128) void attnout_tf32(
    const float* __restrict__ Sc, const float* __restrict__ V,
    float* __restrict__ O)
{
    const int g = blockIdx.y;
    const int b = g >> 5, hq = g & 31, h = hq >> 2;
    const int t0 = blockIdx.x * 64;

    __shared__ float Ss[64][72];   // [T][t], stride 72 = 8 mod 32
    __shared__ float Vs[64][72];   // [T][d]

    const int tid = threadIdx.x;
    const int lane = tid & 31, wid = tid >> 5;
    const int warp_m = wid & 1, warp_n = wid >> 1;
    const int lr = lane >> 2, lc = lane & 3;

    float acc[2][4][4];
    #pragma unroll
    for (int i = 0; i < 2; i++)
        #pragma unroll
        for (int j = 0; j < 4; j++)
            #pragma unroll
            for (int q = 0; q < 4; q++) acc[i][j][q] = 0.f;

    const int kmax = t0 + 64;
    const int r = tid >> 4, c = (tid & 15) * 4;

    for (int T0 = 0; T0 < kmax; T0 += 64) {
        __syncthreads();
        #pragma unroll
        for (int p = 0; p < 8; p++) {
            const int row = p * 8 + r;
            *(float4*)&Ss[row][c] =
                cvt4(*(const float4*)&Sc[((size_t)g * Sn + T0 + row) * Sn + t0 + c]);
            *(float4*)&Vs[row][c] =
                cvt4(*(const float4*)&V[(size_t)(b * Sn + T0 + row) * (HKVn * HDn) + h * HDn + c]);
        }
        __syncthreads();

        #pragma unroll
        for (int ks = 0; ks < 8; ks++) {
            const int k8 = ks * 8;
            uint32_t af[2][4];
            #pragma unroll
            for (int im = 0; im < 2; im++) {
                const int t = warp_m * 32 + im * 16 + lr;    // m index
                af[im][0] = F2U(Ss[k8 + lc][t]);
                af[im][1] = F2U(Ss[k8 + lc][t + 8]);
                af[im][2] = F2U(Ss[k8 + lc + 4][t]);
                af[im][3] = F2U(Ss[k8 + lc + 4][t + 8]);
            }
            #pragma unroll
            for (int jn = 0; jn < 4; jn++) {
                const int d = warp_n * 32 + jn * 8 + lr;     // n index
                uint32_t bf0 = F2U(Vs[k8 + lc][d]);
                uint32_t bf1 = F2U(Vs[k8 + lc + 4][d]);
                #pragma unroll
                for (int im = 0; im < 2; im++)
                    mma8(acc[im][jn], af[im], bf0, bf1);
            }
        }
    }

    #pragma unroll
    for (int im = 0; im < 2; im++)
        #pragma unroll
        for (int jn = 0; jn < 4; jn++) {
            const int row = t0 + warp_m * 32 + im * 16 + lr;
            const int col = hq * HDn + warp_n * 32 + jn * 8 + lc * 2;
            *(float2*)&O[(size_t)(b * Sn + row) * (HQn * HDn) + col] =
                make_float2(acc[im][jn][0], acc[im][jn][1]);
            *(float2*)&O[(size_t)(b * Sn + row + 8) * (HQn * HDn) + col] =
                make_float2(acc[im][jn][2], acc[im][jn][3]);
        }
}

// ---------------- launch ----------------
extern "C" void kernel_launch(void* const* d_in, const int* in_sizes, int n_in,
                              void* d_out, int out_size) {
    const float* x    = (const float*)d_in[0];
    const float* ln_g = (const float*)d_in[1];
    const float* ln_b = (const float*)d_in[2];
    const float* Wq   = (const float*)d_in[3];
    const float* bq   = (const float*)d_in[4];
    const float* Wk   = (const float*)d_in[5];
    const float* bk   = (const float*)d_in[6];
    const float* Wv   = (const float*)d_in[7];
    const float* bv   = (const float*)d_in[8];
    const float* Wo   = (const float*)d_in[9];
    const float* bo   = (const float*)d_in[10];
    float* out = (float*)d_out;

    float *xn, *q, *k, *v, *sc, *attn;
    cudaGetSymbolAddress((void**)&xn,   g_xn);
    cudaGetSymbolAddress((void**)&q,    g_q);
    cudaGetSymbolAddress((void**)&k,    g_k);
    cudaGetSymbolAddress((void**)&v,    g_v);
    cudaGetSymbolAddress((void**)&sc,   g_sc);
    cudaGetSymbolAddress((void**)&attn, g_attn);

    ln_kernel<<<ROWS, 256>>>(x, ln_g, ln_b, xn);

    gemm_nn_tf32<<<dim3(2048 / 128, ROWS / 128), 256>>>(xn, Wq, bq, q, ROWS, 2048, 2048, 0.125f);
    gemm_nn_tf32<<<dim3(512 / 128,  ROWS / 128), 256>>>(xn, Wk, bk, k, ROWS, 512, 2048, 1.0f);
    gemm_nn_tf32<<<dim3(512 / 128,  ROWS / 128), 256>>>(xn, Wv, bv, v, ROWS, 512, 2048, 1.0f);

    scores_tf32<<<dim3(Sn / 64, Sn / 64, NG), 128>>>(q, k, sc);
    softmax_col<<<dim3(Sn, NG), 256>>>(sc);
    attnout_tf32<<<dim3(Sn / 64, NG), 128>>>(sc, v, attn);

    gemm_nn_tf32<<<dim3(2048 / 128, ROWS / 128), 256>>>(attn, Wo, bo, out, ROWS, 2048, 2048, 1.0f);
}

// round 4
// speedup vs baseline: 3.3610x; 1.0884x over previous
#include <cuda_runtime.h>
#include <cuda_bf16.h>
#include <cstdint>
#include <math.h>

#define Bn 2
#define Sn 2048
#define Dn 2048
#define HQn 32
#define HKVn 8
#define HDn 64
#define ROWS (Bn * Sn)      // 4096
#define NG   (Bn * HQn)     // 64 attention "heads" (b, hkv*qpk)

// ---------------- scratch (device globals; no allocation) ----------------
__device__ float g_xn[ROWS * Dn];
__device__ float g_q[ROWS * (HQn * HDn)];
__device__ float g_k[ROWS * (HKVn * HDn)];
__device__ float g_v[ROWS * (HKVn * HDn)];
__device__ float g_sc[(size_t)NG * Sn * Sn];       // raw scores s[g][T][t]
__device__ float g_attn[ROWS * (HQn * HDn)];
__device__ unsigned int g_mkey[NG * Sn];           // encoded column max
__device__ float g_m[NG * Sn];                     // decoded max
__device__ float g_zi[NG * Sn];                    // 1 / sum exp

// ---------------- tf32 helpers ----------------
__device__ __forceinline__ float f2tf(float x) {
    uint32_t r;
    asm("cvt.rna.tf32.f32 %0, %1;" : "=r"(r) : "f"(x));
    return __uint_as_float(r);
}
__device__ __forceinline__ float4 cvt4(float4 v) {
    v.x = f2tf(v.x); v.y = f2tf(v.y); v.z = f2tf(v.z); v.w = f2tf(v.w);
    return v;
}
__device__ __forceinline__ void mma8(float* c, const uint32_t* a, uint32_t b0, uint32_t b1) {
    asm volatile(
        "mma.sync.aligned.m16n8k8.row.col.f32.tf32.tf32.f32 "
        "{%0,%1,%2,%3}, {%4,%5,%6,%7}, {%8,%9}, {%0,%1,%2,%3};"
        : "+f"(c[0]), "+f"(c[1]), "+f"(c[2]), "+f"(c[3])
        : "r"(a[0]), "r"(a[1]), "r"(a[2]), "r"(a[3]), "r"(b0), "r"(b1));
}
#define F2U(x) __float_as_uint(x)

// monotone float->uint encoding (order-preserving)
__device__ __forceinline__ unsigned int fenc(float f) {
    unsigned int u = __float_as_uint(f);
    return (u & 0x80000000u) ? ~u : (u | 0x80000000u);
}
__device__ __forceinline__ float fdec(unsigned int k) {
    unsigned int u = (k & 0x80000000u) ? (k & 0x7fffffffu) : ~k;
    return __uint_as_float(u);
}
#define NEG_INF_KEY 0x007fffffu   // fenc(-inf)

// ---------------- LayerNorm ----------------
__global__ void ln_kernel(const float* __restrict__ x,
                          const float* __restrict__ gamma,
                          const float* __restrict__ beta,
                          float* __restrict__ xn) {
    const int row = blockIdx.x;
    const float* xr = x + (size_t)row * Dn;
    float* outr = xn + (size_t)row * Dn;
    __shared__ float red[256];
    const int tid = threadIdx.x;

    float s = 0.f;
    for (int c = tid; c < Dn; c += 256) s += xr[c];
    red[tid] = s; __syncthreads();
    for (int off = 128; off > 0; off >>= 1) {
        if (tid < off) red[tid] += red[tid + off];
        __syncthreads();
    }
    const float mu = red[0] * (1.0f / Dn);
    __syncthreads();

    float v = 0.f;
    for (int c = tid; c < Dn; c += 256) { float d = xr[c] - mu; v += d * d; }
    red[tid] = v; __syncthreads();
    for (int off = 128; off > 0; off >>= 1) {
        if (tid < off) red[tid] += red[tid + off];
        __syncthreads();
    }
    const float rstd = rsqrtf(red[0] * (1.0f / Dn) + 1e-5f);
    __syncthreads();

    for (int c = tid; c < Dn; c += 256)
        outr[c] = (xr[c] - mu) * rstd * gamma[c] + beta[c];
}

// ---------------- init stats ----------------
__global__ void init_stats(unsigned int* __restrict__ mkey) {
    const int i = blockIdx.x * 256 + threadIdx.x;
    if (i < NG * Sn) mkey[i] = NEG_INF_KEY;
}

// ---------------- tf32 NN GEMM ----------------
__global__ __launch_bounds__(256, 2) void gemm_nn_tf32(
    const float* __restrict__ A, const float* __restrict__ B,
    const float* __restrict__ bias, float* __restrict__ C,
    int M, int N, int K, float scale)
{
    __shared__ float As[2][128][20];
    __shared__ float Bs[2][16][136];

    const int tid = threadIdx.x;
    const int lane = tid & 31, wid = tid >> 5;
    const int warp_m = wid & 3, warp_n = wid >> 2;
    const int m0 = blockIdx.y * 128, n0 = blockIdx.x * 128;

    const int ar = tid >> 2, ac = (tid & 3) * 4;
    const int br = tid >> 5, bc = (tid & 31) * 4;
    const int lr = lane >> 2, lc = lane & 3;

    float acc[2][8][4];
    #pragma unroll
    for (int i = 0; i < 2; i++)
        #pragma unroll
        for (int j = 0; j < 8; j++)
            #pragma unroll
            for (int q = 0; q < 4; q++) acc[i][j][q] = 0.f;

    {
        float4 a0 = cvt4(*(const float4*)&A[(size_t)(m0 + ar) * K + ac]);
        float4 a1 = cvt4(*(const float4*)&A[(size_t)(m0 + ar + 64) * K + ac]);
        float4 b0 = cvt4(*(const float4*)&B[(size_t)br * N + n0 + bc]);
        float4 b1 = cvt4(*(const float4*)&B[(size_t)(br + 8) * N + n0 + bc]);
        *(float4*)&As[0][ar][ac] = a0;
        *(float4*)&As[0][ar + 64][ac] = a1;
        *(float4*)&Bs[0][br][bc] = b0;
        *(float4*)&Bs[0][br + 8][bc] = b1;
    }
    __syncthreads();

    const int KT = K / 16;
    int cur = 0;
    for (int kt = 0; kt < KT; kt++) {
        float4 a0, a1, b0, b1;
        const bool has = (kt + 1 < KT);
        if (has) {
            const int k0 = (kt + 1) * 16;
            a0 = *(const float4*)&A[(size_t)(m0 + ar) * K + k0 + ac];
            a1 = *(const float4*)&A[(size_t)(m0 + ar + 64) * K + k0 + ac];
            b0 = *(const float4*)&B[(size_t)(k0 + br) * N + n0 + bc];
            b1 = *(const float4*)&B[(size_t)(k0 + br + 8) * N + n0 + bc];
        }
        #pragma unroll
        for (int ks = 0; ks < 2; ks++) {
            const int k8 = ks * 8;
            uint32_t af[2][4];
            #pragma unroll
            for (int im = 0; im < 2; im++) {
                const int m = warp_m * 32 + im * 16 + lr;
                af[im][0] = F2U(As[cur][m][k8 + lc]);
                af[im][1] = F2U(As[cur][m + 8][k8 + lc]);
                af[im][2] = F2U(As[cur][m][k8 + lc + 4]);
                af[im][3] = F2U(As[cur][m + 8][k8 + lc + 4]);
            }
            #pragma unroll
            for (int jn = 0; jn < 8; jn++) {
                const int n = warp_n * 64 + jn * 8 + lr;
                uint32_t bf0 = F2U(Bs[cur][k8 + lc][n]);
                uint32_t bf1 = F2U(Bs[cur][k8 + lc + 4][n]);
                #pragma unroll
                for (int im = 0; im < 2; im++)
                    mma8(acc[im][jn], af[im], bf0, bf1);
            }
        }
        if (has) {
            const int nxt = cur ^ 1;
            *(float4*)&As[nxt][ar][ac] = cvt4(a0);
            *(float4*)&As[nxt][ar + 64][ac] = cvt4(a1);
            *(float4*)&Bs[nxt][br][bc] = cvt4(b0);
            *(float4*)&Bs[nxt][br + 8][bc] = cvt4(b1);
            __syncthreads();
            cur = nxt;
        }
    }

    #pragma unroll
    for (int im = 0; im < 2; im++)
        #pragma unroll
        for (int jn = 0; jn < 8; jn++) {
            const int row = m0 + warp_m * 32 + im * 16 + lr;
            const int col = n0 + warp_n * 64 + jn * 8 + lc * 2;
            const float bb0 = bias[col], bb1 = bias[col + 1];
            float2 v0 = make_float2(scale * (acc[im][jn][0] + bb0),
                                    scale * (acc[im][jn][1] + bb1));
            float2 v1 = make_float2(scale * (acc[im][jn][2] + bb0),
                                    scale * (acc[im][jn][3] + bb1));
            *(float2*)&C[(size_t)row * N + col] = v0;
            *(float2*)&C[(size_t)(row + 8) * N + col] = v1;
        }
}

// ---------------- scores + column-max partials ----------------
__global__ __launch_bounds__(128) void scores_tf32(
    const float* __restrict__ Q, const float* __restrict__ Km,
    float* __restrict__ Sc, unsigned int* __restrict__ mkey)
{
    const int g = blockIdx.z;
    const int b = g >> 5, hq = g & 31, h = hq >> 2;
    const int T0 = blockIdx.y * 64;
    const int t0 = blockIdx.x * 64;
    if (t0 + 63 < T0) return;

    __shared__ float Ks[64][68];
    __shared__ float Qs[64][68];

    const int tid = threadIdx.x;
    const int lane = tid & 31, wid = tid >> 5;
    const int warp_m = wid & 1, warp_n = wid >> 1;
    const int lr = lane >> 2, lc = lane & 3;

    {
        const int r = tid >> 4, c = (tid & 15) * 4;
        #pragma unroll
        for (int p = 0; p < 8; p++) {
            const int row = p * 8 + r;
            *(float4*)&Ks[row][c] =
                cvt4(*(const float4*)&Km[(size_t)(b * Sn + T0 + row) * (HKVn * HDn) + h * HDn + c]);
            *(float4*)&Qs[row][c] =
                cvt4(*(const float4*)&Q[(size_t)(b * Sn + t0 + row) * (HQn * HDn) + hq * HDn + c]);
        }
    }
    __syncthreads();

    float acc[2][4][4];
    #pragma unroll
    for (int i = 0; i < 2; i++)
        #pragma unroll
        for (int j = 0; j < 4; j++)
            #pragma unroll
            for (int q = 0; q < 4; q++) acc[i][j][q] = 0.f;

    #pragma unroll
    for (int ks = 0; ks < 8; ks++) {
        const int k8 = ks * 8;
        uint32_t af[2][4];
        #pragma unroll
        for (int im = 0; im < 2; im++) {
            const int m = warp_m * 32 + im * 16 + lr;
            af[im][0] = F2U(Ks[m][k8 + lc]);
            af[im][1] = F2U(Ks[m + 8][k8 + lc]);
            af[im][2] = F2U(Ks[m][k8 + lc + 4]);
            af[im][3] = F2U(Ks[m + 8][k8 + lc + 4]);
        }
        #pragma unroll
        for (int jn = 0; jn < 4; jn++) {
            const int n = warp_n * 32 + jn * 8 + lr;
            uint32_t bf0 = F2U(Qs[n][k8 + lc]);
            uint32_t bf1 = F2U(Qs[n][k8 + lc + 4]);
            #pragma unroll
            for (int im = 0; im < 2; im++)
                mma8(acc[im][jn], af[im], bf0, bf1);
        }
    }

    // store raw scores + accumulate per-column(T) max over valid t >= T
    #pragma unroll
    for (int im = 0; im < 2; im++) {
        float mx0 = -INFINITY, mx1 = -INFINITY;     // for rows T, T+8
        const int rowT0 = T0 + warp_m * 32 + im * 16 + lr;
        #pragma unroll
        for (int jn = 0; jn < 4; jn++) {
            const int col = t0 + warp_n * 32 + jn * 8 + lc * 2;
            *(float2*)&Sc[((size_t)g * Sn + rowT0) * Sn + col] =
                make_float2(acc[im][jn][0], acc[im][jn][1]);
            *(float2*)&Sc[((size_t)g * Sn + rowT0 + 8) * Sn + col] =
                make_float2(acc[im][jn][2], acc[im][jn][3]);
            if (col     >= rowT0) mx0 = fmaxf(mx0, acc[im][jn][0]);
            if (col + 1 >= rowT0) mx0 = fmaxf(mx0, acc[im][jn][1]);
            if (col     >= rowT0 + 8) mx1 = fmaxf(mx1, acc[im][jn][2]);
            if (col + 1 >= rowT0 + 8) mx1 = fmaxf(mx1, acc[im][jn][3]);
        }
        // reduce across the 4 lanes sharing a row (lc = lane & 3)
        #pragma unroll
        for (int off = 1; off < 4; off <<= 1) {
            mx0 = fmaxf(mx0, __shfl_xor_sync(0xffffffffu, mx0, off));
            mx1 = fmaxf(mx1, __shfl_xor_sync(0xffffffffu, mx1, off));
        }
        if (lc == 0) {
            if (mx0 > -INFINITY) atomicMax(&mkey[g * Sn + rowT0], fenc(mx0));
            if (mx1 > -INFINITY) atomicMax(&mkey[g * Sn + rowT0 + 8], fenc(mx1));
        }
    }
}

// ---------------- column stats: m (decode) + 1/sum exp  ----------------
__global__ __launch_bounds__(256) void zinv_kernel(
    const float* __restrict__ Sc, const unsigned int* __restrict__ mkey,
    float* __restrict__ gm, float* __restrict__ gzi)
{
    const int T = blockIdx.x;
    const int g = blockIdx.y;
    const float* row = Sc + ((size_t)g * Sn + T) * Sn;
    const int tid = threadIdx.x;
    __shared__ float red[256];

    const float m = fdec(mkey[g * Sn + T]);

    float s = 0.f;
    const int base = tid * 8;
    float v[8];
    *(float4*)&v[0] = *(const float4*)&row[base];
    *(float4*)&v[4] = *(const float4*)&row[base + 4];
    #pragma unroll
    for (int i = 0; i < 8; i++)
        if (base + i >= T) s += __expf(v[i] - m);

    red[tid] = s; __syncthreads();
    for (int off = 128; off > 0; off >>= 1) {
        if (tid < off) red[tid] += red[tid + off];
        __syncthreads();
    }
    if (tid == 0) {
        gm[g * Sn + T] = m;
        gzi[g * Sn + T] = 1.0f / red[0];
    }
}

// ---------------- attn out with inline softmax apply ----------------
__global__ __launch_bounds__(128) void attnout_tf32(
    const float* __restrict__ Sc, const float* __restrict__ V,
    const float* __restrict__ gm, const float* __restrict__ gzi,
    float* __restrict__ O)
{
    const int g = blockIdx.y;
    const int b = g >> 5, hq = g & 31, h = hq >> 2;
    const int t0 = blockIdx.x * 64;

    __shared__ float Ss[64][72];   // [T][t] = p
    __shared__ float Vs[64][72];   // [T][d]

    const int tid = threadIdx.x;
    const int lane = tid & 31, wid = tid >> 5;
    const int warp_m = wid & 1, warp_n = wid >> 1;
    const int lr = lane >> 2, lc = lane & 3;

    float acc[2][4][4];
    #pragma unroll
    for (int i = 0; i < 2; i++)
        #pragma unroll
        for (int j = 0; j < 4; j++)
            #pragma unroll
            for (int q = 0; q < 4; q++) acc[i][j][q] = 0.f;

    const int kmax = t0 + 64;
    const int r = tid >> 4, c = (tid & 15) * 4;

    for (int T0 = 0; T0 < kmax; T0 += 64) {
        __syncthreads();
        #pragma unroll
        for (int p = 0; p < 8; p++) {
            const int row = p * 8 + r;
            const int T = T0 + row;
            const float m = gm[g * Sn + T];
            const float zi = gzi[g * Sn + T];
            float4 sv = *(const float4*)&Sc[((size_t)g * Sn + T) * Sn + t0 + c];
            sv.x = (t0 + c + 0 >= T) ? __expf(sv.x - m) * zi : 0.f;
            sv.y = (t0 + c + 1 >= T) ? __expf(sv.y - m) * zi : 0.f;
            sv.z = (t0 + c + 2 >= T) ? __expf(sv.z - m) * zi : 0.f;
            sv.w = (t0 + c + 3 >= T) ? __expf(sv.w - m) * zi : 0.f;
            *(float4*)&Ss[row][c] = cvt4(sv);
            *(float4*)&Vs[row][c] =
                cvt4(*(const float4*)&V[(size_t)(b * Sn + T) * (HKVn * HDn) + h * HDn + c]);
        }
        __syncthreads();

        #pragma unroll
        for (int ks = 0; ks < 8; ks++) {
            const int k8 = ks * 8;
            uint32_t af[2][4];
            #pragma unroll
            for (int im = 0; im < 2; im++) {
                const int t = warp_m * 32 + im * 16 + lr;
                af[im][0] = F2U(Ss[k8 + lc][t]);
                af[im][1] = F2U(Ss[k8 + lc][t + 8]);
                af[im][2] = F2U(Ss[k8 + lc + 4][t]);
                af[im][3] = F2U(Ss[k8 + lc + 4][t + 8]);
            }
            #pragma unroll
            for (int jn = 0; jn < 4; jn++) {
                const int d = warp_n * 32 + jn * 8 + lr;
                uint32_t bf0 = F2U(Vs[k8 + lc][d]);
                uint32_t bf1 = F2U(Vs[k8 + lc + 4][d]);
                #pragma unroll
                for (int im = 0; im < 2; im++)
                    mma8(acc[im][jn], af[im], bf0, bf1);
            }
        }
    }

    #pragma unroll
    for (int im = 0; im < 2; im++)
        #pragma unroll
        for (int jn = 0; jn < 4; jn++) {
            const int row = t0 + warp_m * 32 + im * 16 + lr;
            const int col = hq * HDn + warp_n * 32 + jn * 8 + lc * 2;
            *(float2*)&O[(size_t)(b * Sn + row) * (HQn * HDn) + col] =
                make_float2(acc[im][jn][0], acc[im][jn][1]);
            *(float2*)&O[(size_t)(b * Sn + row + 8) * (HQn * HDn) + col] =
                make_float2(acc[im][jn][2], acc[im][jn][3]);
        }
}

// ---------------- launch ----------------
extern "C" void kernel_launch(void* const* d_in, const int* in_sizes, int n_in,
                              void* d_out, int out_size) {
    const float* x    = (const float*)d_in[0];
    const float* ln_g = (const float*)d_in[1];
    const float* ln_b = (const float*)d_in[2];
    const float* Wq   = (const float*)d_in[3];
    const float* bq   = (const float*)d_in[4];
    const float* Wk   = (const float*)d_in[5];
    const float* bk   = (const float*)d_in[6];
    const float* Wv   = (const float*)d_in[7];
    const float* bv   = (const float*)d_in[8];
    const float* Wo   = (const float*)d_in[9];
    const float* bo   = (const float*)d_in[10];
    float* out = (float*)d_out;

    float *xn, *q, *k, *v, *sc, *attn, *m, *zi;
    unsigned int* mkey;
    cudaGetSymbolAddress((void**)&xn,   g_xn);
    cudaGetSymbolAddress((void**)&q,    g_q);
    cudaGetSymbolAddress((void**)&k,    g_k);
    cudaGetSymbolAddress((void**)&v,    g_v);
    cudaGetSymbolAddress((void**)&sc,   g_sc);
    cudaGetSymbolAddress((void**)&attn, g_attn);
    cudaGetSymbolAddress((void**)&mkey, g_mkey);
    cudaGetSymbolAddress((void**)&m,    g_m);
    cudaGetSymbolAddress((void**)&zi,   g_zi);

    ln_kernel<<<ROWS, 256>>>(x, ln_g, ln_b, xn);
    init_stats<<<(NG * Sn + 255) / 256, 256>>>(mkey);

    gemm_nn_tf32<<<dim3(2048 / 128, ROWS / 128), 256>>>(xn, Wq, bq, q, ROWS, 2048, 2048, 0.125f);
    gemm_nn_tf32<<<dim3(512 / 128,  ROWS / 128), 256>>>(xn, Wk, bk, k, ROWS, 512, 2048, 1.0f);
    gemm_nn_tf32<<<dim3(512 / 128,  ROWS / 128), 256>>>(xn, Wv, bv, v, ROWS, 512, 2048, 1.0f);

    scores_tf32<<<dim3(Sn / 64, Sn / 64, NG), 128>>>(q, k, sc, mkey);
    zinv_kernel<<<dim3(Sn, NG), 256>>>(sc, mkey, m, zi);
    attnout_tf32<<<dim3(Sn / 64, NG), 128>>>(sc, v, m, zi, attn);

    gemm_nn_tf32<<<dim3(2048 / 128, ROWS / 128), 256>>>(attn, Wo, bo, out, ROWS, 2048, 2048, 1.0f);
}

// round 5
// speedup vs baseline: 4.0863x; 1.2158x over previous
#include <cuda_runtime.h>
#include <cuda_bf16.h>
#include <cstdint>
#include <math.h>

#define Bn 2
#define Sn 2048
#define Dn 2048
#define HQn 32
#define HKVn 8
#define HDn 64
#define ROWS (Bn * Sn)      // 4096
#define NG   (Bn * HQn)     // 64 attention "heads" (b, hkv*qpk)
#define NTB  (Sn / 64)      // 32 tiles along sequence

// ---------------- scratch (device globals; no allocation) ----------------
__device__ float g_xn[ROWS * Dn];
__device__ float g_q[ROWS * (HQn * HDn)];
__device__ float g_k[ROWS * (HKVn * HDn)];
__device__ float g_v[ROWS * (HKVn * HDn)];
__device__ float g_attn[ROWS * (HQn * HDn)];
__device__ float g_m[NG * Sn];                     // per-key-column max
__device__ float g_zi[NG * Sn];                    // 1 / sum exp

// ---------------- tf32 helpers ----------------
__device__ __forceinline__ float f2tf(float x) {
    uint32_t r;
    asm("cvt.rna.tf32.f32 %0, %1;" : "=r"(r) : "f"(x));
    return __uint_as_float(r);
}
__device__ __forceinline__ float4 cvt4(float4 v) {
    v.x = f2tf(v.x); v.y = f2tf(v.y); v.z = f2tf(v.z); v.w = f2tf(v.w);
    return v;
}
__device__ __forceinline__ void mma8(float* c, const uint32_t* a, uint32_t b0, uint32_t b1) {
    asm volatile(
        "mma.sync.aligned.m16n8k8.row.col.f32.tf32.tf32.f32 "
        "{%0,%1,%2,%3}, {%4,%5,%6,%7}, {%8,%9}, {%0,%1,%2,%3};"
        : "+f"(c[0]), "+f"(c[1]), "+f"(c[2]), "+f"(c[3])
        : "r"(a[0]), "r"(a[1]), "r"(a[2]), "r"(a[3]), "r"(b0), "r"(b1));
}
#define F2U(x) __float_as_uint(x)
#define NEGBIG (-1e30f)

// ---------------- LayerNorm ----------------
__global__ void ln_kernel(const float* __restrict__ x,
                          const float* __restrict__ gamma,
                          const float* __restrict__ beta,
                          float* __restrict__ xn) {
    const int row = blockIdx.x;
    const float* xr = x + (size_t)row * Dn;
    float* outr = xn + (size_t)row * Dn;
    __shared__ float red[256];
    const int tid = threadIdx.x;

    float s = 0.f;
    for (int c = tid; c < Dn; c += 256) s += xr[c];
    red[tid] = s; __syncthreads();
    for (int off = 128; off > 0; off >>= 1) {
        if (tid < off) red[tid] += red[tid + off];
        __syncthreads();
    }
    const float mu = red[0] * (1.0f / Dn);
    __syncthreads();

    float v = 0.f;
    for (int c = tid; c < Dn; c += 256) { float d = xr[c] - mu; v += d * d; }
    red[tid] = v; __syncthreads();
    for (int off = 128; off > 0; off >>= 1) {
        if (tid < off) red[tid] += red[tid + off];
        __syncthreads();
    }
    const float rstd = rsqrtf(red[0] * (1.0f / Dn) + 1e-5f);
    __syncthreads();

    for (int c = tid; c < Dn; c += 256)
        outr[c] = (xr[c] - mu) * rstd * gamma[c] + beta[c];
}

// ---------------- tf32 NN GEMM ----------------
__global__ __launch_bounds__(256, 2) void gemm_nn_tf32(
    const float* __restrict__ A, const float* __restrict__ B,
    const float* __restrict__ bias, float* __restrict__ C,
    int M, int N, int K, float scale)
{
    __shared__ float As[2][128][20];
    __shared__ float Bs[2][16][136];

    const int tid = threadIdx.x;
    const int lane = tid & 31, wid = tid >> 5;
    const int warp_m = wid & 3, warp_n = wid >> 2;
    const int m0 = blockIdx.y * 128, n0 = blockIdx.x * 128;

    const int ar = tid >> 2, ac = (tid & 3) * 4;
    const int br = tid >> 5, bc = (tid & 31) * 4;
    const int lr = lane >> 2, lc = lane & 3;

    float acc[2][8][4];
    #pragma unroll
    for (int i = 0; i < 2; i++)
        #pragma unroll
        for (int j = 0; j < 8; j++)
            #pragma unroll
            for (int q = 0; q < 4; q++) acc[i][j][q] = 0.f;

    {
        float4 a0 = cvt4(*(const float4*)&A[(size_t)(m0 + ar) * K + ac]);
        float4 a1 = cvt4(*(const float4*)&A[(size_t)(m0 + ar + 64) * K + ac]);
        float4 b0 = cvt4(*(const float4*)&B[(size_t)br * N + n0 + bc]);
        float4 b1 = cvt4(*(const float4*)&B[(size_t)(br + 8) * N + n0 + bc]);
        *(float4*)&As[0][ar][ac] = a0;
        *(float4*)&As[0][ar + 64][ac] = a1;
        *(float4*)&Bs[0][br][bc] = b0;
        *(float4*)&Bs[0][br + 8][bc] = b1;
    }
    __syncthreads();

    const int KT = K / 16;
    int cur = 0;
    for (int kt = 0; kt < KT; kt++) {
        float4 a0, a1, b0, b1;
        const bool has = (kt + 1 < KT);
        if (has) {
            const int k0 = (kt + 1) * 16;
            a0 = *(const float4*)&A[(size_t)(m0 + ar) * K + k0 + ac];
            a1 = *(const float4*)&A[(size_t)(m0 + ar + 64) * K + k0 + ac];
            b0 = *(const float4*)&B[(size_t)(k0 + br) * N + n0 + bc];
            b1 = *(const float4*)&B[(size_t)(k0 + br + 8) * N + n0 + bc];
        }
        #pragma unroll
        for (int ks = 0; ks < 2; ks++) {
            const int k8 = ks * 8;
            uint32_t af[2][4];
            #pragma unroll
            for (int im = 0; im < 2; im++) {
                const int m = warp_m * 32 + im * 16 + lr;
                af[im][0] = F2U(As[cur][m][k8 + lc]);
                af[im][1] = F2U(As[cur][m + 8][k8 + lc]);
                af[im][2] = F2U(As[cur][m][k8 + lc + 4]);
                af[im][3] = F2U(As[cur][m + 8][k8 + lc + 4]);
            }
            #pragma unroll
            for (int jn = 0; jn < 8; jn++) {
                const int n = warp_n * 64 + jn * 8 + lr;
                uint32_t bf0 = F2U(Bs[cur][k8 + lc][n]);
                uint32_t bf1 = F2U(Bs[cur][k8 + lc + 4][n]);
                #pragma unroll
                for (int im = 0; im < 2; im++)
                    mma8(acc[im][jn], af[im], bf0, bf1);
            }
        }
        if (has) {
            const int nxt = cur ^ 1;
            *(float4*)&As[nxt][ar][ac] = cvt4(a0);
            *(float4*)&As[nxt][ar + 64][ac] = cvt4(a1);
            *(float4*)&Bs[nxt][br][bc] = cvt4(b0);
            *(float4*)&Bs[nxt][br + 8][bc] = cvt4(b1);
            __syncthreads();
            cur = nxt;
        }
    }

    #pragma unroll
    for (int im = 0; im < 2; im++)
        #pragma unroll
        for (int jn = 0; jn < 8; jn++) {
            const int row = m0 + warp_m * 32 + im * 16 + lr;
            const int col = n0 + warp_n * 64 + jn * 8 + lc * 2;
            const float bb0 = bias[col], bb1 = bias[col + 1];
            float2 v0 = make_float2(scale * (acc[im][jn][0] + bb0),
                                    scale * (acc[im][jn][1] + bb1));
            float2 v1 = make_float2(scale * (acc[im][jn][2] + bb0),
                                    scale * (acc[im][jn][3] + bb1));
            *(float2*)&C[(size_t)row * N + col] = v0;
            *(float2*)&C[(size_t)(row + 8) * N + col] = v1;
        }
}

// ---------------- pass 1: per-key-column softmax stats (no score store) ----------------
// Block: (T-block of 64) x g. 128 threads, 4 warps; warp w owns 16 T-rows (m16 x n64).
// K tile resident; stream Q tiles for t-blocks >= T-block; online (m, Z) per T row.
__global__ __launch_bounds__(128) void stats_pass(
    const float* __restrict__ Q, const float* __restrict__ Km,
    float* __restrict__ gm, float* __restrict__ gzi)
{
    const int g = blockIdx.y;
    const int b = g >> 5, hq = g & 31, h = hq >> 2;
    const int Tb = blockIdx.x;                 // Tb=0 runs longest; launches first
    const int T0 = Tb * 64;

    __shared__ float Ks[64][68];
    __shared__ float Qs[64][68];

    const int tid = threadIdx.x;
    const int lane = tid & 31, w = tid >> 5;
    const int lr = lane >> 2, lc = lane & 3;
    const int r = tid >> 4, c = (tid & 15) * 4;

    // K tile resident (rows T0..T0+63)
    #pragma unroll
    for (int p = 0; p < 8; p++) {
        const int row = p * 8 + r;
        *(float4*)&Ks[row][c] =
            cvt4(*(const float4*)&Km[(size_t)(b * Sn + T0 + row) * (HKVn * HDn) + h * HDn + c]);
    }

    const int Trow0 = T0 + w * 16 + lr;
    const int Trow1 = Trow0 + 8;

    float m0 = NEGBIG, z0 = 0.f, m1 = NEGBIG, z1 = 0.f;

    for (int tb = Tb; tb < NTB; tb++) {
        __syncthreads();
        #pragma unroll
        for (int p = 0; p < 8; p++) {
            const int row = p * 8 + r;
            *(float4*)&Qs[row][c] =
                cvt4(*(const float4*)&Q[(size_t)(b * Sn + tb * 64 + row) * (HQn * HDn) + hq * HDn + c]);
        }
        __syncthreads();

        float acc[8][4];
        #pragma unroll
        for (int j = 0; j < 8; j++)
            #pragma unroll
            for (int q = 0; q < 4; q++) acc[j][q] = 0.f;

        #pragma unroll
        for (int ks = 0; ks < 8; ks++) {
            const int k8 = ks * 8;
            uint32_t af[4];
            af[0] = F2U(Ks[w * 16 + lr][k8 + lc]);
            af[1] = F2U(Ks[w * 16 + 8 + lr][k8 + lc]);
            af[2] = F2U(Ks[w * 16 + lr][k8 + lc + 4]);
            af[3] = F2U(Ks[w * 16 + 8 + lr][k8 + lc + 4]);
            #pragma unroll
            for (int jn = 0; jn < 8; jn++) {
                uint32_t bf0 = F2U(Qs[jn * 8 + lr][k8 + lc]);
                uint32_t bf1 = F2U(Qs[jn * 8 + lr][k8 + lc + 4]);
                mma8(acc[jn], af, bf0, bf1);
            }
        }

        // online stats per row (mask only matters on the diagonal tile)
        const int tbase = tb * 64 + lc * 2;
        float tm0 = NEGBIG, tm1 = NEGBIG;
        float va[8][4];
        #pragma unroll
        for (int jn = 0; jn < 8; jn++) {
            const int tcol = tbase + jn * 8;
            va[jn][0] = (tcol     >= Trow0) ? acc[jn][0] : NEGBIG;
            va[jn][1] = (tcol + 1 >= Trow0) ? acc[jn][1] : NEGBIG;
            va[jn][2] = (tcol     >= Trow1) ? acc[jn][2] : NEGBIG;
            va[jn][3] = (tcol + 1 >= Trow1) ? acc[jn][3] : NEGBIG;
            tm0 = fmaxf(tm0, fmaxf(va[jn][0], va[jn][1]));
            tm1 = fmaxf(tm1, fmaxf(va[jn][2], va[jn][3]));
        }
        const float nm0 = fmaxf(m0, tm0);
        const float nm1 = fmaxf(m1, tm1);
        float s0 = 0.f, s1 = 0.f;
        #pragma unroll
        for (int jn = 0; jn < 8; jn++) {
            s0 += __expf(va[jn][0] - nm0) + __expf(va[jn][1] - nm0);
            s1 += __expf(va[jn][2] - nm1) + __expf(va[jn][3] - nm1);
        }
        z0 = z0 * __expf(m0 - nm0) + s0; m0 = nm0;
        z1 = z1 * __expf(m1 - nm1) + s1; m1 = nm1;
    }

    // merge across the quad (lanes sharing a row)
    #pragma unroll
    for (int off = 1; off < 4; off <<= 1) {
        float mo = __shfl_xor_sync(0xffffffffu, m0, off);
        float zo = __shfl_xor_sync(0xffffffffu, z0, off);
        float mn = fmaxf(m0, mo);
        z0 = z0 * __expf(m0 - mn) + zo * __expf(mo - mn); m0 = mn;
        mo = __shfl_xor_sync(0xffffffffu, m1, off);
        zo = __shfl_xor_sync(0xffffffffu, z1, off);
        mn = fmaxf(m1, mo);
        z1 = z1 * __expf(m1 - mn) + zo * __expf(mo - mn); m1 = mn;
    }
    if (lc == 0) {
        gm[g * Sn + Trow0] = m0;  gzi[g * Sn + Trow0] = 1.0f / z0;
        gm[g * Sn + Trow1] = m1;  gzi[g * Sn + Trow1] = 1.0f / z1;
    }
}

// ---------------- pass 2: recompute S, apply softmax, accumulate O = P @ V ----------------
// Block: (t-block of 64) x g, longest-first. 128 threads, 4 warps (2x2).
__global__ __launch_bounds__(128) void out_pass(
    const float* __restrict__ Q, const float* __restrict__ Km,
    const float* __restrict__ V,
    const float* __restrict__ gm, const float* __restrict__ gzi,
    float* __restrict__ O)
{
    extern __shared__ float sm[];
    float (*Qs)[68] = (float(*)[68])sm;                       // [t][d]
    float (*Ks)[68] = (float(*)[68])(sm + 64 * 68);           // [T][d]
    float (*Ps)[68] = (float(*)[68])(sm + 2 * 64 * 68);       // [t][T]
    float (*Vs)[72] = (float(*)[72])(sm + 3 * 64 * 68);       // [T][d]
    float* s_m  = sm + 3 * 64 * 68 + 64 * 72;
    float* s_zi = s_m + 64;

    const int g = blockIdx.y;
    const int b = g >> 5, hq = g & 31, h = hq >> 2;
    const int tblk = (NTB - 1) - blockIdx.x;   // longest blocks launch first
    const int t0 = tblk * 64;

    const int tid = threadIdx.x;
    const int lane = tid & 31, wid = tid >> 5;
    const int warp_m = wid & 1, warp_n = wid >> 1;
    const int lr = lane >> 2, lc = lane & 3;
    const int r = tid >> 4, c = (tid & 15) * 4;

    // Q tile resident
    #pragma unroll
    for (int p = 0; p < 8; p++) {
        const int row = p * 8 + r;
        *(float4*)&Qs[row][c] =
            cvt4(*(const float4*)&Q[(size_t)(b * Sn + t0 + row) * (HQn * HDn) + hq * HDn + c]);
    }

    float acc2[2][4][4];
    #pragma unroll
    for (int i = 0; i < 2; i++)
        #pragma unroll
        for (int j = 0; j < 4; j++)
            #pragma unroll
            for (int q = 0; q < 4; q++) acc2[i][j][q] = 0.f;

    for (int Tb = 0; Tb <= tblk; Tb++) {
        const int T0 = Tb * 64;
        __syncthreads();
        #pragma unroll
        for (int p = 0; p < 8; p++) {
            const int row = p * 8 + r;
            *(float4*)&Ks[row][c] =
                cvt4(*(const float4*)&Km[(size_t)(b * Sn + T0 + row) * (HKVn * HDn) + h * HDn + c]);
            *(float4*)&Vs[row][c] =
                cvt4(*(const float4*)&V[(size_t)(b * Sn + T0 + row) * (HKVn * HDn) + h * HDn + c]);
        }
        if (tid < 64) {
            s_m[tid]  = gm[g * Sn + T0 + tid];
            s_zi[tid] = gzi[g * Sn + T0 + tid];
        }
        __syncthreads();

        // stage 1: S[t][T] = Q . K
        float acc1[2][4][4];
        #pragma unroll
        for (int i = 0; i < 2; i++)
            #pragma unroll
            for (int j = 0; j < 4; j++)
                #pragma unroll
                for (int q = 0; q < 4; q++) acc1[i][j][q] = 0.f;

        #pragma unroll
        for (int ks = 0; ks < 8; ks++) {
            const int k8 = ks * 8;
            uint32_t af[2][4];
            #pragma unroll
            for (int im = 0; im < 2; im++) {
                const int m = warp_m * 32 + im * 16 + lr;
                af[im][0] = F2U(Qs[m][k8 + lc]);
                af[im][1] = F2U(Qs[m + 8][k8 + lc]);
                af[im][2] = F2U(Qs[m][k8 + lc + 4]);
                af[im][3] = F2U(Qs[m + 8][k8 + lc + 4]);
            }
            #pragma unroll
            for (int jn = 0; jn < 4; jn++) {
                const int n = warp_n * 32 + jn * 8 + lr;
                uint32_t bf0 = F2U(Ks[n][k8 + lc]);
                uint32_t bf1 = F2U(Ks[n][k8 + lc + 4]);
                #pragma unroll
                for (int im = 0; im < 2; im++)
                    mma8(acc1[im][jn], af[im], bf0, bf1);
            }
        }

        // softmax apply -> Ps
        const bool diag = (Tb == tblk);
        #pragma unroll
        for (int im = 0; im < 2; im++) {
            const int trow = warp_m * 32 + im * 16 + lr;
            #pragma unroll
            for (int jn = 0; jn < 4; jn++) {
                const int Tcol = warp_n * 32 + jn * 8 + lc * 2;
                const float mm0 = s_m[Tcol],     zi0 = s_zi[Tcol];
                const float mm1 = s_m[Tcol + 1], zi1 = s_zi[Tcol + 1];
                float p00 = __expf(acc1[im][jn][0] - mm0) * zi0;
                float p01 = __expf(acc1[im][jn][1] - mm1) * zi1;
                float p10 = __expf(acc1[im][jn][2] - mm0) * zi0;
                float p11 = __expf(acc1[im][jn][3] - mm1) * zi1;
                if (diag) {
                    if (trow < Tcol)         p00 = 0.f;
                    if (trow < Tcol + 1)     p01 = 0.f;
                    if (trow + 8 < Tcol)     p10 = 0.f;
                    if (trow + 8 < Tcol + 1) p11 = 0.f;
                }
                *(float2*)&Ps[trow][Tcol]     = make_float2(f2tf(p00), f2tf(p01));
                *(float2*)&Ps[trow + 8][Tcol] = make_float2(f2tf(p10), f2tf(p11));
            }
        }
        __syncthreads();

        // stage 2: O += P @ V
        #pragma unroll
        for (int ks = 0; ks < 8; ks++) {
            const int k8 = ks * 8;
            uint32_t af[2][4];
            #pragma unroll
            for (int im = 0; im < 2; im++) {
                const int m = warp_m * 32 + im * 16 + lr;
                af[im][0] = F2U(Ps[m][k8 + lc]);
                af[im][1] = F2U(Ps[m + 8][k8 + lc]);
                af[im][2] = F2U(Ps[m][k8 + lc + 4]);
                af[im][3] = F2U(Ps[m + 8][k8 + lc + 4]);
            }
            #pragma unroll
            for (int jn = 0; jn < 4; jn++) {
                const int n = warp_n * 32 + jn * 8 + lr;
                uint32_t bf0 = F2U(Vs[k8 + lc][n]);
                uint32_t bf1 = F2U(Vs[k8 + lc + 4][n]);
                #pragma unroll
                for (int im = 0; im < 2; im++)
                    mma8(acc2[im][jn], af[im], bf0, bf1);
            }
        }
    }

    #pragma unroll
    for (int im = 0; im < 2; im++)
        #pragma unroll
        for (int jn = 0; jn < 4; jn++) {
            const int row = t0 + warp_m * 32 + im * 16 + lr;
            const int col = hq * HDn + warp_n * 32 + jn * 8 + lc * 2;
            *(float2*)&O[(size_t)(b * Sn + row) * (HQn * HDn) + col] =
                make_float2(acc2[im][jn][0], acc2[im][jn][1]);
            *(float2*)&O[(size_t)(b * Sn + row + 8) * (HQn * HDn) + col] =
                make_float2(acc2[im][jn][2], acc2[im][jn][3]);
        }
}

#define OUTPASS_SMEM ((3 * 64 * 68 + 64 * 72 + 128) * 4)

// ---------------- launch ----------------
extern "C" void kernel_launch(void* const* d_in, const int* in_sizes, int n_in,
                              void* d_out, int out_size) {
    const float* x    = (const float*)d_in[0];
    const float* ln_g = (const float*)d_in[1];
    const float* ln_b = (const float*)d_in[2];
    const float* Wq   = (const float*)d_in[3];
    const float* bq   = (const float*)d_in[4];
    const float* Wk   = (const float*)d_in[5];
    const float* bk   = (const float*)d_in[6];
    const float* Wv   = (const float*)d_in[7];
    const float* bv   = (const float*)d_in[8];
    const float* Wo   = (const float*)d_in[9];
    const float* bo   = (const float*)d_in[10];
    float* out = (float*)d_out;

    float *xn, *q, *k, *v, *attn, *m, *zi;
    cudaGetSymbolAddress((void**)&xn,   g_xn);
    cudaGetSymbolAddress((void**)&q,    g_q);
    cudaGetSymbolAddress((void**)&k,    g_k);
    cudaGetSymbolAddress((void**)&v,    g_v);
    cudaGetSymbolAddress((void**)&attn, g_attn);
    cudaGetSymbolAddress((void**)&m,    g_m);
    cudaGetSymbolAddress((void**)&zi,   g_zi);

    cudaFuncSetAttribute(out_pass, cudaFuncAttributeMaxDynamicSharedMemorySize, OUTPASS_SMEM);

    ln_kernel<<<ROWS, 256>>>(x, ln_g, ln_b, xn);

    gemm_nn_tf32<<<dim3(2048 / 128, ROWS / 128), 256>>>(xn, Wq, bq, q, ROWS, 2048, 2048, 0.125f);
    gemm_nn_tf32<<<dim3(512 / 128,  ROWS / 128), 256>>>(xn, Wk, bk, k, ROWS, 512, 2048, 1.0f);
    gemm_nn_tf32<<<dim3(512 / 128,  ROWS / 128), 256>>>(xn, Wv, bv, v, ROWS, 512, 2048, 1.0f);

    stats_pass<<<dim3(NTB, NG), 128>>>(q, k, m, zi);
    out_pass<<<dim3(NTB, NG), 128, OUTPASS_SMEM>>>(q, k, v, m, zi, attn);

    gemm_nn_tf32<<<dim3(2048 / 128, ROWS / 128), 256>>>(attn, Wo, bo, out, ROWS, 2048, 2048, 1.0f);
}

// round 6
// speedup vs baseline: 4.1012x; 1.0036x over previous
#include <cuda_runtime.h>
#include <cuda_bf16.h>
#include <cstdint>
#include <math.h>

#define Bn 2
#define Sn 2048
#define Dn 2048
#define HQn 32
#define HKVn 8
#define HDn 64
#define ROWS (Bn * Sn)      // 4096
#define NG   (Bn * HQn)     // 64 attention "heads"
#define NTB64 (Sn / 64)     // 32
#define NTB128 (Sn / 128)   // 16

// ---------------- scratch ----------------
__device__ float g_xn[ROWS * Dn];
__device__ float g_q[ROWS * (HQn * HDn)];
__device__ float g_k[ROWS * (HKVn * HDn)];
__device__ float g_v[ROWS * (HKVn * HDn)];
__device__ float g_attn[ROWS * (HQn * HDn)];
__device__ float g_m[NG * Sn];
__device__ float g_zi[NG * Sn];

// ---------------- tf32 helpers ----------------
__device__ __forceinline__ float f2tf(float x) {
    uint32_t r;
    asm("cvt.rna.tf32.f32 %0, %1;" : "=r"(r) : "f"(x));
    return __uint_as_float(r);
}
__device__ __forceinline__ float4 cvt4(float4 v) {
    v.x = f2tf(v.x); v.y = f2tf(v.y); v.z = f2tf(v.z); v.w = f2tf(v.w);
    return v;
}
__device__ __forceinline__ void mma8(float* c, const uint32_t* a, uint32_t b0, uint32_t b1) {
    asm volatile(
        "mma.sync.aligned.m16n8k8.row.col.f32.tf32.tf32.f32 "
        "{%0,%1,%2,%3}, {%4,%5,%6,%7}, {%8,%9}, {%0,%1,%2,%3};"
        : "+f"(c[0]), "+f"(c[1]), "+f"(c[2]), "+f"(c[3])
        : "r"(a[0]), "r"(a[1]), "r"(a[2]), "r"(a[3]), "r"(b0), "r"(b1));
}
#define F2U(x) __float_as_uint(x)
#define NEGBIG (-1e30f)

// ---------------- LayerNorm ----------------
__global__ void ln_kernel(const float* __restrict__ x,
                          const float* __restrict__ gamma,
                          const float* __restrict__ beta,
                          float* __restrict__ xn) {
    const int row = blockIdx.x;
    const float* xr = x + (size_t)row * Dn;
    float* outr = xn + (size_t)row * Dn;
    __shared__ float red[256];
    const int tid = threadIdx.x;

    float s = 0.f;
    for (int c = tid; c < Dn; c += 256) s += xr[c];
    red[tid] = s; __syncthreads();
    for (int off = 128; off > 0; off >>= 1) {
        if (tid < off) red[tid] += red[tid + off];
        __syncthreads();
    }
    const float mu = red[0] * (1.0f / Dn);
    __syncthreads();

    float v = 0.f;
    for (int c = tid; c < Dn; c += 256) { float d = xr[c] - mu; v += d * d; }
    red[tid] = v; __syncthreads();
    for (int off = 128; off > 0; off >>= 1) {
        if (tid < off) red[tid] += red[tid + off];
        __syncthreads();
    }
    const float rstd = rsqrtf(red[0] * (1.0f / Dn) + 1e-5f);
    __syncthreads();

    for (int c = tid; c < Dn; c += 256)
        outr[c] = (xr[c] - mu) * rstd * gamma[c] + beta[c];
}

// ---------------- tf32 NN GEMM, BM=128, BN template (128 or 64) ----------------
template<int BN>
__global__ __launch_bounds__(256, 2) void gemm_nn_tf32(
    const float* __restrict__ A, const float* __restrict__ B,
    const float* __restrict__ bias, float* __restrict__ C,
    int M, int N, int K, float scale)
{
    constexpr int WN = BN / 2;       // per warp_n cols
    constexpr int JN = WN / 8;       // jn loop
    constexpr int BSTR = BN + 8;     // 136 / 72, both == 8 mod 32
    constexpr int NB = BN / 64;      // float4 loads of B per thread (2 / 1)

    __shared__ float As[2][128][20];
    __shared__ float Bs[2][16][BSTR];

    const int tid = threadIdx.x;
    const int lane = tid & 31, wid = tid >> 5;
    const int warp_m = wid & 3, warp_n = wid >> 2;
    const int m0 = blockIdx.y * 128, n0 = blockIdx.x * BN;

    const int ar = tid >> 2, ac = (tid & 3) * 4;
    const int lr = lane >> 2, lc = lane & 3;

    float acc[2][JN][4];
    #pragma unroll
    for (int i = 0; i < 2; i++)
        #pragma unroll
        for (int j = 0; j < JN; j++)
            #pragma unroll
            for (int q = 0; q < 4; q++) acc[i][j][q] = 0.f;

    {
        float4 a0 = cvt4(*(const float4*)&A[(size_t)(m0 + ar) * K + ac]);
        float4 a1 = cvt4(*(const float4*)&A[(size_t)(m0 + ar + 64) * K + ac]);
        *(float4*)&As[0][ar][ac] = a0;
        *(float4*)&As[0][ar + 64][ac] = a1;
        #pragma unroll
        for (int i = 0; i < NB; i++) {
            const int idx = i * 256 + tid;
            const int brr = idx / (BN / 4);
            const int bcc = (idx % (BN / 4)) * 4;
            *(float4*)&Bs[0][brr][bcc] =
                cvt4(*(const float4*)&B[(size_t)brr * N + n0 + bcc]);
        }
    }
    __syncthreads();

    const int KT = K / 16;
    int cur = 0;
    for (int kt = 0; kt < KT; kt++) {
        float4 a0, a1, bb[NB];
        const bool has = (kt + 1 < KT);
        if (has) {
            const int k0 = (kt + 1) * 16;
            a0 = *(const float4*)&A[(size_t)(m0 + ar) * K + k0 + ac];
            a1 = *(const float4*)&A[(size_t)(m0 + ar + 64) * K + k0 + ac];
            #pragma unroll
            for (int i = 0; i < NB; i++) {
                const int idx = i * 256 + tid;
                const int brr = idx / (BN / 4);
                const int bcc = (idx % (BN / 4)) * 4;
                bb[i] = *(const float4*)&B[(size_t)(k0 + brr) * N + n0 + bcc];
            }
        }
        #pragma unroll
        for (int ks = 0; ks < 2; ks++) {
            const int k8 = ks * 8;
            uint32_t af[2][4];
            #pragma unroll
            for (int im = 0; im < 2; im++) {
                const int m = warp_m * 32 + im * 16 + lr;
                af[im][0] = F2U(As[cur][m][k8 + lc]);
                af[im][1] = F2U(As[cur][m + 8][k8 + lc]);
                af[im][2] = F2U(As[cur][m][k8 + lc + 4]);
                af[im][3] = F2U(As[cur][m + 8][k8 + lc + 4]);
            }
            #pragma unroll
            for (int jn = 0; jn < JN; jn++) {
                const int n = warp_n * WN + jn * 8 + lr;
                uint32_t bf0 = F2U(Bs[cur][k8 + lc][n]);
                uint32_t bf1 = F2U(Bs[cur][k8 + lc + 4][n]);
                #pragma unroll
                for (int im = 0; im < 2; im++)
                    mma8(acc[im][jn], af[im], bf0, bf1);
            }
        }
        if (has) {
            const int nxt = cur ^ 1;
            *(float4*)&As[nxt][ar][ac] = cvt4(a0);
            *(float4*)&As[nxt][ar + 64][ac] = cvt4(a1);
            #pragma unroll
            for (int i = 0; i < NB; i++) {
                const int idx = i * 256 + tid;
                const int brr = idx / (BN / 4);
                const int bcc = (idx % (BN / 4)) * 4;
                *(float4*)&Bs[nxt][brr][bcc] = cvt4(bb[i]);
            }
            __syncthreads();
            cur = nxt;
        }
    }

    #pragma unroll
    for (int im = 0; im < 2; im++)
        #pragma unroll
        for (int jn = 0; jn < JN; jn++) {
            const int row = m0 + warp_m * 32 + im * 16 + lr;
            const int col = n0 + warp_n * WN + jn * 8 + lc * 2;
            const float bb0 = bias[col], bb1 = bias[col + 1];
            float2 v0 = make_float2(scale * (acc[im][jn][0] + bb0),
                                    scale * (acc[im][jn][1] + bb1));
            float2 v1 = make_float2(scale * (acc[im][jn][2] + bb0),
                                    scale * (acc[im][jn][3] + bb1));
            *(float2*)&C[(size_t)row * N + col] = v0;
            *(float2*)&C[(size_t)(row + 8) * N + col] = v1;
        }
}

// ---------------- pass 1: column softmax stats; T-tile 128, 256 threads ----------------
// warp w owns 16 T-rows; stream Q 64-tiles for t >= T region.
__global__ __launch_bounds__(256) void stats_pass(
    const float* __restrict__ Q, const float* __restrict__ Km,
    float* __restrict__ gm, float* __restrict__ gzi)
{
    extern __shared__ float sm[];
    float (*Ks)[68] = (float(*)[68])sm;               // [128][68]
    float (*Qs)[68] = (float(*)[68])(sm + 128 * 68);  // [64][68]

    const int g = blockIdx.y;
    const int b = g >> 5, hq = g & 31, h = hq >> 2;
    const int Tb = blockIdx.x;            // 0 = longest, launches first
    const int T0 = Tb * 128;

    const int tid = threadIdx.x;
    const int lane = tid & 31, w = tid >> 5;
    const int lr = lane >> 2, lc = lane & 3;
    const int r = tid >> 4, c = (tid & 15) * 4;

    #pragma unroll
    for (int p = 0; p < 8; p++) {
        const int row = p * 16 + r;
        *(float4*)&Ks[row][c] =
            cvt4(*(const float4*)&Km[(size_t)(b * Sn + T0 + row) * (HKVn * HDn) + h * HDn + c]);
    }

    const int Trow0 = T0 + w * 16 + lr;
    const int Trow1 = Trow0 + 8;

    float m0 = NEGBIG, z0 = 0.f, m1 = NEGBIG, z1 = 0.f;

    for (int tb = 2 * Tb; tb < NTB64; tb++) {
        __syncthreads();
        #pragma unroll
        for (int p = 0; p < 4; p++) {
            const int row = p * 16 + r;
            *(float4*)&Qs[row][c] =
                cvt4(*(const float4*)&Q[(size_t)(b * Sn + tb * 64 + row) * (HQn * HDn) + hq * HDn + c]);
        }
        __syncthreads();

        float acc[8][4];
        #pragma unroll
        for (int j = 0; j < 8; j++)
            #pragma unroll
            for (int q = 0; q < 4; q++) acc[j][q] = 0.f;

        #pragma unroll
        for (int ks = 0; ks < 8; ks++) {
            const int k8 = ks * 8;
            uint32_t af[4];
            af[0] = F2U(Ks[w * 16 + lr][k8 + lc]);
            af[1] = F2U(Ks[w * 16 + 8 + lr][k8 + lc]);
            af[2] = F2U(Ks[w * 16 + lr][k8 + lc + 4]);
            af[3] = F2U(Ks[w * 16 + 8 + lr][k8 + lc + 4]);
            #pragma unroll
            for (int jn = 0; jn < 8; jn++) {
                uint32_t bf0 = F2U(Qs[jn * 8 + lr][k8 + lc]);
                uint32_t bf1 = F2U(Qs[jn * 8 + lr][k8 + lc + 4]);
                mma8(acc[jn], af, bf0, bf1);
            }
        }

        const int tbase = tb * 64 + lc * 2;
        float tm0 = NEGBIG, tm1 = NEGBIG;
        float va[8][4];
        #pragma unroll
        for (int jn = 0; jn < 8; jn++) {
            const int tcol = tbase + jn * 8;
            va[jn][0] = (tcol     >= Trow0) ? acc[jn][0] : NEGBIG;
            va[jn][1] = (tcol + 1 >= Trow0) ? acc[jn][1] : NEGBIG;
            va[jn][2] = (tcol     >= Trow1) ? acc[jn][2] : NEGBIG;
            va[jn][3] = (tcol + 1 >= Trow1) ? acc[jn][3] : NEGBIG;
            tm0 = fmaxf(tm0, fmaxf(va[jn][0], va[jn][1]));
            tm1 = fmaxf(tm1, fmaxf(va[jn][2], va[jn][3]));
        }
        const float nm0 = fmaxf(m0, tm0);
        const float nm1 = fmaxf(m1, tm1);
        float s0 = 0.f, s1 = 0.f;
        #pragma unroll
        for (int jn = 0; jn < 8; jn++) {
            s0 += __expf(va[jn][0] - nm0) + __expf(va[jn][1] - nm0);
            s1 += __expf(va[jn][2] - nm1) + __expf(va[jn][3] - nm1);
        }
        z0 = z0 * __expf(m0 - nm0) + s0; m0 = nm0;
        z1 = z1 * __expf(m1 - nm1) + s1; m1 = nm1;
    }

    #pragma unroll
    for (int off = 1; off < 4; off <<= 1) {
        float mo = __shfl_xor_sync(0xffffffffu, m0, off);
        float zo = __shfl_xor_sync(0xffffffffu, z0, off);
        float mn = fmaxf(m0, mo);
        z0 = z0 * __expf(m0 - mn) + zo * __expf(mo - mn); m0 = mn;
        mo = __shfl_xor_sync(0xffffffffu, m1, off);
        zo = __shfl_xor_sync(0xffffffffu, z1, off);
        mn = fmaxf(m1, mo);
        z1 = z1 * __expf(m1 - mn) + zo * __expf(mo - mn); m1 = mn;
    }
    if (lc == 0) {
        gm[g * Sn + Trow0] = m0;  gzi[g * Sn + Trow0] = 1.0f / z0;
        gm[g * Sn + Trow1] = m1;  gzi[g * Sn + Trow1] = 1.0f / z1;
    }
}
#define STATS_SMEM ((128 * 68 + 64 * 68) * 4)

// ---------------- pass 2: recompute S, softmax apply, O = P @ V ----------------
// t-tile 128 x d 64, 256 threads (8 warps 4x2). Stream K/V 64-tiles, T <= t.
__global__ __launch_bounds__(256) void out_pass(
    const float* __restrict__ Q, const float* __restrict__ Km,
    const float* __restrict__ V,
    const float* __restrict__ gm, const float* __restrict__ gzi,
    float* __restrict__ O)
{
    extern __shared__ float sm[];
    float (*Qs)[68] = (float(*)[68])sm;                          // [128][68]
    float (*Ks)[68] = (float(*)[68])(sm + 128 * 68);             // [64][68]
    float (*Ps)[68] = (float(*)[68])(sm + 128 * 68 + 64 * 68);   // [128][68]
    float (*Vs)[72] = (float(*)[72])(sm + 2 * 128 * 68 + 64 * 68); // [64][72]
    float* s_m  = sm + 2 * 128 * 68 + 64 * 68 + 64 * 72;
    float* s_zi = s_m + 64;

    const int g = blockIdx.y;
    const int b = g >> 5, hq = g & 31, h = hq >> 2;
    const int tblk = (NTB128 - 1) - blockIdx.x;   // longest first
    const int t0 = tblk * 128;

    const int tid = threadIdx.x;
    const int lane = tid & 31, wid = tid >> 5;
    const int warp_m = wid & 3, warp_n = wid >> 2;
    const int lr = lane >> 2, lc = lane & 3;
    const int r = tid >> 4, c = (tid & 15) * 4;

    #pragma unroll
    for (int p = 0; p < 8; p++) {
        const int row = p * 16 + r;
        *(float4*)&Qs[row][c] =
            cvt4(*(const float4*)&Q[(size_t)(b * Sn + t0 + row) * (HQn * HDn) + hq * HDn + c]);
    }

    float acc2[2][4][4];
    #pragma unroll
    for (int i = 0; i < 2; i++)
        #pragma unroll
        for (int j = 0; j < 4; j++)
            #pragma unroll
            for (int q = 0; q < 4; q++) acc2[i][j][q] = 0.f;

    const int nT = 2 * tblk + 2;   // T 64-tiles: 0 .. 2*tblk+1
    for (int Tb = 0; Tb < nT; Tb++) {
        const int T0 = Tb * 64;
        __syncthreads();
        #pragma unroll
        for (int p = 0; p < 4; p++) {
            const int row = p * 16 + r;
            *(float4*)&Ks[row][c] =
                cvt4(*(const float4*)&Km[(size_t)(b * Sn + T0 + row) * (HKVn * HDn) + h * HDn + c]);
            *(float4*)&Vs[row][c] =
                cvt4(*(const float4*)&V[(size_t)(b * Sn + T0 + row) * (HKVn * HDn) + h * HDn + c]);
        }
        if (tid < 64) {
            s_m[tid]  = gm[g * Sn + T0 + tid];
            s_zi[tid] = gzi[g * Sn + T0 + tid];
        }
        __syncthreads();

        // stage 1: S[t][T] = Q . K
        float acc1[2][4][4];
        #pragma unroll
        for (int i = 0; i < 2; i++)
            #pragma unroll
            for (int j = 0; j < 4; j++)
                #pragma unroll
                for (int q = 0; q < 4; q++) acc1[i][j][q] = 0.f;

        #pragma unroll
        for (int ks = 0; ks < 8; ks++) {
            const int k8 = ks * 8;
            uint32_t af[2][4];
            #pragma unroll
            for (int im = 0; im < 2; im++) {
                const int m = warp_m * 32 + im * 16 + lr;
                af[im][0] = F2U(Qs[m][k8 + lc]);
                af[im][1] = F2U(Qs[m + 8][k8 + lc]);
                af[im][2] = F2U(Qs[m][k8 + lc + 4]);
                af[im][3] = F2U(Qs[m + 8][k8 + lc + 4]);
            }
            #pragma unroll
            for (int jn = 0; jn < 4; jn++) {
                const int n = warp_n * 32 + jn * 8 + lr;
                uint32_t bf0 = F2U(Ks[n][k8 + lc]);
                uint32_t bf1 = F2U(Ks[n][k8 + lc + 4]);
                #pragma unroll
                for (int im = 0; im < 2; im++)
                    mma8(acc1[im][jn], af[im], bf0, bf1);
            }
        }

        // softmax apply -> Ps
        const bool diag = (Tb >= 2 * tblk);
        #pragma unroll
        for (int im = 0; im < 2; im++) {
            const int trow = warp_m * 32 + im * 16 + lr;       // local t
            const int trg = t0 + trow;
            #pragma unroll
            for (int jn = 0; jn < 4; jn++) {
                const int Tcol = warp_n * 32 + jn * 8 + lc * 2; // local T
                const int Tg = T0 + Tcol;
                const float mm0 = s_m[Tcol],     zi0 = s_zi[Tcol];
                const float mm1 = s_m[Tcol + 1], zi1 = s_zi[Tcol + 1];
                float p00 = __expf(acc1[im][jn][0] - mm0) * zi0;
                float p01 = __expf(acc1[im][jn][1] - mm1) * zi1;
                float p10 = __expf(acc1[im][jn][2] - mm0) * zi0;
                float p11 = __expf(acc1[im][jn][3] - mm1) * zi1;
                if (diag) {
                    if (trg < Tg)         p00 = 0.f;
                    if (trg < Tg + 1)     p01 = 0.f;
                    if (trg + 8 < Tg)     p10 = 0.f;
                    if (trg + 8 < Tg + 1) p11 = 0.f;
                }
                *(float2*)&Ps[trow][Tcol]     = make_float2(f2tf(p00), f2tf(p01));
                *(float2*)&Ps[trow + 8][Tcol] = make_float2(f2tf(p10), f2tf(p11));
            }
        }
        __syncthreads();

        // stage 2: O += P @ V
        #pragma unroll
        for (int ks = 0; ks < 8; ks++) {
            const int k8 = ks * 8;
            uint32_t af[2][4];
            #pragma unroll
            for (int im = 0; im < 2; im++) {
                const int m = warp_m * 32 + im * 16 + lr;
                af[im][0] = F2U(Ps[m][k8 + lc]);
                af[im][1] = F2U(Ps[m + 8][k8 + lc]);
                af[im][2] = F2U(Ps[m][k8 + lc + 4]);
                af[im][3] = F2U(Ps[m + 8][k8 + lc + 4]);
            }
            #pragma unroll
            for (int jn = 0; jn < 4; jn++) {
                const int n = warp_n * 32 + jn * 8 + lr;
                uint32_t bf0 = F2U(Vs[k8 + lc][n]);
                uint32_t bf1 = F2U(Vs[k8 + lc + 4][n]);
                #pragma unroll
                for (int im = 0; im < 2; im++)
                    mma8(acc2[im][jn], af[im], bf0, bf1);
            }
        }
    }

    #pragma unroll
    for (int im = 0; im < 2; im++)
        #pragma unroll
        for (int jn = 0; jn < 4; jn++) {
            const int row = t0 + warp_m * 32 + im * 16 + lr;
            const int col = hq * HDn + warp_n * 32 + jn * 8 + lc * 2;
            *(float2*)&O[(size_t)(b * Sn + row) * (HQn * HDn) + col] =
                make_float2(acc2[im][jn][0], acc2[im][jn][1]);
            *(float2*)&O[(size_t)(b * Sn + row + 8) * (HQn * HDn) + col] =
                make_float2(acc2[im][jn][2], acc2[im][jn][3]);
        }
}
#define OUT_SMEM ((2 * 128 * 68 + 64 * 68 + 64 * 72 + 128) * 4)

// ---------------- launch ----------------
extern "C" void kernel_launch(void* const* d_in, const int* in_sizes, int n_in,
                              void* d_out, int out_size) {
    const float* x    = (const float*)d_in[0];
    const float* ln_g = (const float*)d_in[1];
    const float* ln_b = (const float*)d_in[2];
    const float* Wq   = (const float*)d_in[3];
    const float* bq   = (const float*)d_in[4];
    const float* Wk   = (const float*)d_in[5];
    const float* bk   = (const float*)d_in[6];
    const float* Wv   = (const float*)d_in[7];
    const float* bv   = (const float*)d_in[8];
    const float* Wo   = (const float*)d_in[9];
    const float* bo   = (const float*)d_in[10];
    float* out = (float*)d_out;

    float *xn, *q, *k, *v, *attn, *m, *zi;
    cudaGetSymbolAddress((void**)&xn,   g_xn);
    cudaGetSymbolAddress((void**)&q,    g_q);
    cudaGetSymbolAddress((void**)&k,    g_k);
    cudaGetSymbolAddress((void**)&v,    g_v);
    cudaGetSymbolAddress((void**)&attn, g_attn);
    cudaGetSymbolAddress((void**)&m,    g_m);
    cudaGetSymbolAddress((void**)&zi,   g_zi);

    cudaFuncSetAttribute(stats_pass, cudaFuncAttributeMaxDynamicSharedMemorySize, STATS_SMEM);
    cudaFuncSetAttribute(out_pass,   cudaFuncAttributeMaxDynamicSharedMemorySize, OUT_SMEM);

    ln_kernel<<<ROWS, 256>>>(x, ln_g, ln_b, xn);

    gemm_nn_tf32<128><<<dim3(2048 / 128, ROWS / 128), 256>>>(xn, Wq, bq, q, ROWS, 2048, 2048, 0.125f);
    gemm_nn_tf32<64><<<dim3(512 / 64,  ROWS / 128), 256>>>(xn, Wk, bk, k, ROWS, 512, 2048, 1.0f);
    gemm_nn_tf32<64><<<dim3(512 / 64,  ROWS / 128), 256>>>(xn, Wv, bv, v, ROWS, 512, 2048, 1.0f);

    stats_pass<<<dim3(NTB128, NG), 256, STATS_SMEM>>>(q, k, m, zi);
    out_pass<<<dim3(NTB128, NG), 256, OUT_SMEM>>>(q, k, v, m, zi, attn);

    gemm_nn_tf32<128><<<dim3(2048 / 128, ROWS / 128), 256>>>(attn, Wo, bo, out, ROWS, 2048, 2048, 1.0f);
}

// round 7
// speedup vs baseline: 4.4813x; 1.0927x over previous
#include <cuda_runtime.h>
#include <cuda_bf16.h>
#include <cstdint>
#include <math.h>

#define Bn 2
#define Sn 2048
#define Dn 2048
#define HQn 32
#define HKVn 8
#define HDn 64
#define ROWS (Bn * Sn)      // 4096
#define NG   (Bn * HQn)     // 64 attention "heads"
#define NTB64 (Sn / 64)     // 32
#define NTB128 (Sn / 128)   // 16
#define QKVW 3072           // fused q|k|v width

// ---------------- scratch ----------------
__device__ float g_xn[ROWS * Dn];
__device__ float g_qkv[(size_t)ROWS * QKVW];       // q: 0..2047, k: 2048..2559, v: 2560..3071
__device__ float g_wf[Dn * QKVW];                  // fused rounded QKV weights
__device__ float g_bf[QKVW];                       // fused bias (raw fp32)
__device__ float g_wo[Dn * Dn];                    // rounded Wo
__device__ float g_attn[ROWS * (HQn * HDn)];
__device__ float g_m[NG * Sn];
__device__ float g_zi[NG * Sn];

// ---------------- helpers ----------------
__device__ __forceinline__ float f2tf(float x) {
    uint32_t r;
    asm("cvt.rna.tf32.f32 %0, %1;" : "=r"(r) : "f"(x));
    return __uint_as_float(r);
}
__device__ __forceinline__ float4 cvt4(float4 v) {
    v.x = f2tf(v.x); v.y = f2tf(v.y); v.z = f2tf(v.z); v.w = f2tf(v.w);
    return v;
}
__device__ __forceinline__ void mma8(float* c, const uint32_t* a, uint32_t b0, uint32_t b1) {
    asm volatile(
        "mma.sync.aligned.m16n8k8.row.col.f32.tf32.tf32.f32 "
        "{%0,%1,%2,%3}, {%4,%5,%6,%7}, {%8,%9}, {%0,%1,%2,%3};"
        : "+f"(c[0]), "+f"(c[1]), "+f"(c[2]), "+f"(c[3])
        : "r"(a[0]), "r"(a[1]), "r"(a[2]), "r"(a[3]), "r"(b0), "r"(b1));
}
__device__ __forceinline__ void cpa16(void* dst_smem, const void* src) {
    uint32_t d = (uint32_t)__cvta_generic_to_shared(dst_smem);
    asm volatile("cp.async.cg.shared.global [%0], [%1], 16;" :: "r"(d), "l"(src));
}
#define CP_COMMIT() asm volatile("cp.async.commit_group;")
#define CP_WAIT(n)  asm volatile("cp.async.wait_group %0;" :: "n"(n))
#define F2U(x) __float_as_uint(x)
#define NEGBIG (-1e30f)

// ---------------- LayerNorm (tf32-rounded output) ----------------
__global__ void ln_kernel(const float* __restrict__ x,
                          const float* __restrict__ gamma,
                          const float* __restrict__ beta,
                          float* __restrict__ xn) {
    const int row = blockIdx.x;
    const float* xr = x + (size_t)row * Dn;
    float* outr = xn + (size_t)row * Dn;
    __shared__ float red[256];
    const int tid = threadIdx.x;

    float s = 0.f;
    for (int c = tid; c < Dn; c += 256) s += xr[c];
    red[tid] = s; __syncthreads();
    for (int off = 128; off > 0; off >>= 1) {
        if (tid < off) red[tid] += red[tid + off];
        __syncthreads();
    }
    const float mu = red[0] * (1.0f / Dn);
    __syncthreads();

    float v = 0.f;
    for (int c = tid; c < Dn; c += 256) { float d = xr[c] - mu; v += d * d; }
    red[tid] = v; __syncthreads();
    for (int off = 128; off > 0; off >>= 1) {
        if (tid < off) red[tid] += red[tid + off];
        __syncthreads();
    }
    const float rstd = rsqrtf(red[0] * (1.0f / Dn) + 1e-5f);
    __syncthreads();

    for (int c = tid; c < Dn; c += 256)
        outr[c] = f2tf((xr[c] - mu) * rstd * gamma[c] + beta[c]);
}

// ---------------- weight prep ----------------
__global__ void prep_qkv_w(const float* __restrict__ Wq, const float* __restrict__ Wk,
                           const float* __restrict__ Wv, float* __restrict__ Wf) {
    const int idx = (blockIdx.x * 256 + threadIdx.x) * 4;     // over 2048*3072
    const int row = idx / QKVW, col = idx % QKVW;
    const float* src;
    if (col < 2048)      src = &Wq[(size_t)row * 2048 + col];
    else if (col < 2560) src = &Wk[(size_t)row * 512 + col - 2048];
    else                 src = &Wv[(size_t)row * 512 + col - 2560];
    *(float4*)&Wf[idx] = cvt4(*(const float4*)src);
}
__global__ void prep_qkv_b(const float* __restrict__ bq, const float* __restrict__ bk,
                           const float* __restrict__ bv, float* __restrict__ bf) {
    const int col = blockIdx.x * 256 + threadIdx.x;
    if (col < QKVW)
        bf[col] = col < 2048 ? bq[col] : (col < 2560 ? bk[col - 2048] : bv[col - 2560]);
}
__global__ void prep_wo(const float* __restrict__ Wo, float* __restrict__ Wr) {
    const int idx = (blockIdx.x * 256 + threadIdx.x) * 4;     // over 2048*2048
    *(float4*)&Wr[idx] = cvt4(*(const float4*)&Wo[idx]);
}

// ---------------- cp.async 3-stage tf32 GEMM (inputs pre-rounded) ----------------
// BM=128, BN=128, BK=16, 256 threads (8 warps 4x2), warp tile 32x64.
#define STAGES 3
#define GEMM_SMEM (STAGES * (128 * 20 + 16 * 136) * 4)

__global__ __launch_bounds__(256) void gemm_cp(
    const float* __restrict__ A, const float* __restrict__ B,
    const float* __restrict__ bias, float* __restrict__ C,
    int M, int N, int K, float scale0, float scale1, int ncut, int round_out)
{
    extern __shared__ float sm[];
    float (*As)[128][20] = (float(*)[128][20])sm;
    float (*Bs)[16][136] = (float(*)[16][136])(sm + STAGES * 128 * 20);

    const int tid = threadIdx.x;
    const int lane = tid & 31, wid = tid >> 5;
    const int warp_m = wid & 3, warp_n = wid >> 2;
    const int m0 = blockIdx.y * 128, n0 = blockIdx.x * 128;

    const int ar = tid >> 2, ac = (tid & 3) * 4;   // A: 64 rows per pass x2
    const int br = tid >> 5, bc = (tid & 31) * 4;  // B: 8 rows per pass x2
    const int lr = lane >> 2, lc = lane & 3;

    const int KT = K / 16;

    float acc[2][8][4];
    #pragma unroll
    for (int i = 0; i < 2; i++)
        #pragma unroll
        for (int j = 0; j < 8; j++)
            #pragma unroll
            for (int q = 0; q < 4; q++) acc[i][j][q] = 0.f;

    // prologue: stages 0..STAGES-2
    #pragma unroll
    for (int s = 0; s < STAGES - 1; s++) {
        const int k0 = s * 16;
        const float* ap = &A[(size_t)(m0 + ar) * K + k0 + ac];
        cpa16(&As[s][ar][ac], ap);
        cpa16(&As[s][ar + 64][ac], ap + (size_t)64 * K);
        const float* bp = &B[(size_t)(k0 + br) * N + n0 + bc];
        cpa16(&Bs[s][br][bc], bp);
        cpa16(&Bs[s][br + 8][bc], bp + (size_t)8 * N);
        CP_COMMIT();
    }

    for (int kt = 0; kt < KT; kt++) {
        CP_WAIT(STAGES - 2);
        __syncthreads();

        const int nf = kt + STAGES - 1;
        if (nf < KT) {
            const int s = nf % STAGES;
            const int k0 = nf * 16;
            const float* ap = &A[(size_t)(m0 + ar) * K + k0 + ac];
            cpa16(&As[s][ar][ac], ap);
            cpa16(&As[s][ar + 64][ac], ap + (size_t)64 * K);
            const float* bp = &B[(size_t)(k0 + br) * N + n0 + bc];
            cpa16(&Bs[s][br][bc], bp);
            cpa16(&Bs[s][br + 8][bc], bp + (size_t)8 * N);
        }
        CP_COMMIT();

        const int cur = kt % STAGES;
        #pragma unroll
        for (int ks = 0; ks < 2; ks++) {
            const int k8 = ks * 8;
            uint32_t af[2][4];
            #pragma unroll
            for (int im = 0; im < 2; im++) {
                const int m = warp_m * 32 + im * 16 + lr;
                af[im][0] = F2U(As[cur][m][k8 + lc]);
                af[im][1] = F2U(As[cur][m + 8][k8 + lc]);
                af[im][2] = F2U(As[cur][m][k8 + lc + 4]);
                af[im][3] = F2U(As[cur][m + 8][k8 + lc + 4]);
            }
            #pragma unroll
            for (int jn = 0; jn < 8; jn++) {
                const int n = warp_n * 64 + jn * 8 + lr;
                uint32_t bf0 = F2U(Bs[cur][k8 + lc][n]);
                uint32_t bf1 = F2U(Bs[cur][k8 + lc + 4][n]);
                #pragma unroll
                for (int im = 0; im < 2; im++)
                    mma8(acc[im][jn], af[im], bf0, bf1);
            }
        }
    }

    #pragma unroll
    for (int im = 0; im < 2; im++)
        #pragma unroll
        for (int jn = 0; jn < 8; jn++) {
            const int row = m0 + warp_m * 32 + im * 16 + lr;
            const int col = n0 + warp_n * 64 + jn * 8 + lc * 2;
            const float sc = (col < ncut) ? scale0 : scale1;
            const float bb0 = bias[col], bb1 = bias[col + 1];
            float v00 = sc * (acc[im][jn][0] + bb0);
            float v01 = sc * (acc[im][jn][1] + bb1);
            float v10 = sc * (acc[im][jn][2] + bb0);
            float v11 = sc * (acc[im][jn][3] + bb1);
            if (round_out) { v00 = f2tf(v00); v01 = f2tf(v01); v10 = f2tf(v10); v11 = f2tf(v11); }
            *(float2*)&C[(size_t)row * N + col] = make_float2(v00, v01);
            *(float2*)&C[(size_t)(row + 8) * N + col] = make_float2(v10, v11);
        }
}

// ---------------- pass 1: column softmax stats; T-tile 128, 256 threads ----------------
__global__ __launch_bounds__(256) void stats_pass(
    const float* __restrict__ QKV,
    float* __restrict__ gm, float* __restrict__ gzi)
{
    extern __shared__ float sm[];
    float (*Ks)[68] = (float(*)[68])sm;               // [128][68]
    float (*Qs)[68] = (float(*)[68])(sm + 128 * 68);  // [64][68]

    const int g = blockIdx.y;
    const int b = g >> 5, hq = g & 31, h = hq >> 2;
    const int Tb = blockIdx.x;
    const int T0 = Tb * 128;

    const int tid = threadIdx.x;
    const int lane = tid & 31, w = tid >> 5;
    const int lr = lane >> 2, lc = lane & 3;
    const int r = tid >> 4, c = (tid & 15) * 4;

    const float* Kbase = QKV + 2048 + h * HDn;
    const float* Qbase = QKV + hq * HDn;

    #pragma unroll
    for (int p = 0; p < 8; p++) {
        const int row = p * 16 + r;
        *(float4*)&Ks[row][c] =
            *(const float4*)&Kbase[(size_t)(b * Sn + T0 + row) * QKVW + c];
    }

    const int Trow0 = T0 + w * 16 + lr;
    const int Trow1 = Trow0 + 8;

    float m0 = NEGBIG, z0 = 0.f, m1 = NEGBIG, z1 = 0.f;

    for (int tb = 2 * Tb; tb < NTB64; tb++) {
        __syncthreads();
        #pragma unroll
        for (int p = 0; p < 4; p++) {
            const int row = p * 16 + r;
            *(float4*)&Qs[row][c] =
                *(const float4*)&Qbase[(size_t)(b * Sn + tb * 64 + row) * QKVW + c];
        }
        __syncthreads();

        float acc[8][4];
        #pragma unroll
        for (int j = 0; j < 8; j++)
            #pragma unroll
            for (int q = 0; q < 4; q++) acc[j][q] = 0.f;

        #pragma unroll
        for (int ks = 0; ks < 8; ks++) {
            const int k8 = ks * 8;
            uint32_t af[4];
            af[0] = F2U(Ks[w * 16 + lr][k8 + lc]);
            af[1] = F2U(Ks[w * 16 + 8 + lr][k8 + lc]);
            af[2] = F2U(Ks[w * 16 + lr][k8 + lc + 4]);
            af[3] = F2U(Ks[w * 16 + 8 + lr][k8 + lc + 4]);
            #pragma unroll
            for (int jn = 0; jn < 8; jn++) {
                uint32_t bf0 = F2U(Qs[jn * 8 + lr][k8 + lc]);
                uint32_t bf1 = F2U(Qs[jn * 8 + lr][k8 + lc + 4]);
                mma8(acc[jn], af, bf0, bf1);
            }
        }

        const int tbase = tb * 64 + lc * 2;
        float tm0 = NEGBIG, tm1 = NEGBIG;
        float va[8][4];
        #pragma unroll
        for (int jn = 0; jn < 8; jn++) {
            const int tcol = tbase + jn * 8;
            va[jn][0] = (tcol     >= Trow0) ? acc[jn][0] : NEGBIG;
            va[jn][1] = (tcol + 1 >= Trow0) ? acc[jn][1] : NEGBIG;
            va[jn][2] = (tcol     >= Trow1) ? acc[jn][2] : NEGBIG;
            va[jn][3] = (tcol + 1 >= Trow1) ? acc[jn][3] : NEGBIG;
            tm0 = fmaxf(tm0, fmaxf(va[jn][0], va[jn][1]));
            tm1 = fmaxf(tm1, fmaxf(va[jn][2], va[jn][3]));
        }
        const float nm0 = fmaxf(m0, tm0);
        const float nm1 = fmaxf(m1, tm1);
        float s0 = 0.f, s1 = 0.f;
        #pragma unroll
        for (int jn = 0; jn < 8; jn++) {
            s0 += __expf(va[jn][0] - nm0) + __expf(va[jn][1] - nm0);
            s1 += __expf(va[jn][2] - nm1) + __expf(va[jn][3] - nm1);
        }
        z0 = z0 * __expf(m0 - nm0) + s0; m0 = nm0;
        z1 = z1 * __expf(m1 - nm1) + s1; m1 = nm1;
    }

    #pragma unroll
    for (int off = 1; off < 4; off <<= 1) {
        float mo = __shfl_xor_sync(0xffffffffu, m0, off);
        float zo = __shfl_xor_sync(0xffffffffu, z0, off);
        float mn = fmaxf(m0, mo);
        z0 = z0 * __expf(m0 - mn) + zo * __expf(mo - mn); m0 = mn;
        mo = __shfl_xor_sync(0xffffffffu, m1, off);
        zo = __shfl_xor_sync(0xffffffffu, z1, off);
        mn = fmaxf(m1, mo);
        z1 = z1 * __expf(m1 - mn) + zo * __expf(mo - mn); m1 = mn;
    }
    if (lc == 0) {
        gm[g * Sn + Trow0] = m0;  gzi[g * Sn + Trow0] = 1.0f / z0;
        gm[g * Sn + Trow1] = m1;  gzi[g * Sn + Trow1] = 1.0f / z1;
    }
}
#define STATS_SMEM ((128 * 68 + 64 * 68) * 4)

// ---------------- pass 2: recompute S, softmax apply, O = P @ V ----------------
__global__ __launch_bounds__(256) void out_pass(
    const float* __restrict__ QKV,
    const float* __restrict__ gm, const float* __restrict__ gzi,
    float* __restrict__ O)
{
    extern __shared__ float sm[];
    float (*Qs)[68] = (float(*)[68])sm;                          // [128][68]
    float (*Ks)[68] = (float(*)[68])(sm + 128 * 68);             // [64][68]
    float (*Ps)[68] = (float(*)[68])(sm + 128 * 68 + 64 * 68);   // [128][68]
    float (*Vs)[72] = (float(*)[72])(sm + 2 * 128 * 68 + 64 * 68); // [64][72]
    float* s_m  = sm + 2 * 128 * 68 + 64 * 68 + 64 * 72;
    float* s_zi = s_m + 64;

    const int g = blockIdx.y;
    const int b = g >> 5, hq = g & 31, h = hq >> 2;
    const int tblk = (NTB128 - 1) - blockIdx.x;
    const int t0 = tblk * 128;

    const int tid = threadIdx.x;
    const int lane = tid & 31, wid = tid >> 5;
    const int warp_m = wid & 3, warp_n = wid >> 2;
    const int lr = lane >> 2, lc = lane & 3;
    const int r = tid >> 4, c = (tid & 15) * 4;

    const float* Qbase = QKV + hq * HDn;
    const float* Kbase = QKV + 2048 + h * HDn;
    const float* Vbase = QKV + 2560 + h * HDn;

    #pragma unroll
    for (int p = 0; p < 8; p++) {
        const int row = p * 16 + r;
        *(float4*)&Qs[row][c] =
            *(const float4*)&Qbase[(size_t)(b * Sn + t0 + row) * QKVW + c];
    }

    float acc2[2][4][4];
    #pragma unroll
    for (int i = 0; i < 2; i++)
        #pragma unroll
        for (int j = 0; j < 4; j++)
            #pragma unroll
            for (int q = 0; q < 4; q++) acc2[i][j][q] = 0.f;

    const int nT = 2 * tblk + 2;
    for (int Tb = 0; Tb < nT; Tb++) {
        const int T0 = Tb * 64;
        __syncthreads();
        #pragma unroll
        for (int p = 0; p < 4; p++) {
            const int row = p * 16 + r;
            *(float4*)&Ks[row][c] =
                *(const float4*)&Kbase[(size_t)(b * Sn + T0 + row) * QKVW + c];
            *(float4*)&Vs[row][c] =
                *(const float4*)&Vbase[(size_t)(b * Sn + T0 + row) * QKVW + c];
        }
        if (tid < 64) {
            s_m[tid]  = gm[g * Sn + T0 + tid];
            s_zi[tid] = gzi[g * Sn + T0 + tid];
        }
        __syncthreads();

        float acc1[2][4][4];
        #pragma unroll
        for (int i = 0; i < 2; i++)
            #pragma unroll
            for (int j = 0; j < 4; j++)
                #pragma unroll
                for (int q = 0; q < 4; q++) acc1[i][j][q] = 0.f;

        #pragma unroll
        for (int ks = 0; ks < 8; ks++) {
            const int k8 = ks * 8;
            uint32_t af[2][4];
            #pragma unroll
            for (int im = 0; im < 2; im++) {
                const int m = warp_m * 32 + im * 16 + lr;
                af[im][0] = F2U(Qs[m][k8 + lc]);
                af[im][1] = F2U(Qs[m + 8][k8 + lc]);
                af[im][2] = F2U(Qs[m][k8 + lc + 4]);
                af[im][3] = F2U(Qs[m + 8][k8 + lc + 4]);
            }
            #pragma unroll
            for (int jn = 0; jn < 4; jn++) {
                const int n = warp_n * 32 + jn * 8 + lr;
                uint32_t bf0 = F2U(Ks[n][k8 + lc]);
                uint32_t bf1 = F2U(Ks[n][k8 + lc + 4]);
                #pragma unroll
                for (int im = 0; im < 2; im++)
                    mma8(acc1[im][jn], af[im], bf0, bf1);
            }
        }

        const bool diag = (Tb >= 2 * tblk);
        #pragma unroll
        for (int im = 0; im < 2; im++) {
            const int trow = warp_m * 32 + im * 16 + lr;
            const int trg = t0 + trow;
            #pragma unroll
            for (int jn = 0; jn < 4; jn++) {
                const int Tcol = warp_n * 32 + jn * 8 + lc * 2;
                const int Tg = T0 + Tcol;
                const float mm0 = s_m[Tcol],     zi0 = s_zi[Tcol];
                const float mm1 = s_m[Tcol + 1], zi1 = s_zi[Tcol + 1];
                float p00 = __expf(acc1[im][jn][0] - mm0) * zi0;
                float p01 = __expf(acc1[im][jn][1] - mm1) * zi1;
                float p10 = __expf(acc1[im][jn][2] - mm0) * zi0;
                float p11 = __expf(acc1[im][jn][3] - mm1) * zi1;
                if (diag) {
                    if (trg < Tg)         p00 = 0.f;
                    if (trg < Tg + 1)     p01 = 0.f;
                    if (trg + 8 < Tg)     p10 = 0.f;
                    if (trg + 8 < Tg + 1) p11 = 0.f;
                }
                *(float2*)&Ps[trow][Tcol]     = make_float2(f2tf(p00), f2tf(p01));
                *(float2*)&Ps[trow + 8][Tcol] = make_float2(f2tf(p10), f2tf(p11));
            }
        }
        __syncthreads();

        #pragma unroll
        for (int ks = 0; ks < 8; ks++) {
            const int k8 = ks * 8;
            uint32_t af[2][4];
            #pragma unroll
            for (int im = 0; im < 2; im++) {
                const int m = warp_m * 32 + im * 16 + lr;
                af[im][0] = F2U(Ps[m][k8 + lc]);
                af[im][1] = F2U(Ps[m + 8][k8 + lc]);
                af[im][2] = F2U(Ps[m][k8 + lc + 4]);
                af[im][3] = F2U(Ps[m + 8][k8 + lc + 4]);
            }
            #pragma unroll
            for (int jn = 0; jn < 4; jn++) {
                const int n = warp_n * 32 + jn * 8 + lr;
                uint32_t bf0 = F2U(Vs[k8 + lc][n]);
                uint32_t bf1 = F2U(Vs[k8 + lc + 4][n]);
                #pragma unroll
                for (int im = 0; im < 2; im++)
                    mma8(acc2[im][jn], af[im], bf0, bf1);
            }
        }
    }

    #pragma unroll
    for (int im = 0; im < 2; im++)
        #pragma unroll
        for (int jn = 0; jn < 4; jn++) {
            const int row = t0 + warp_m * 32 + im * 16 + lr;
            const int col = hq * HDn + warp_n * 32 + jn * 8 + lc * 2;
            *(float2*)&O[(size_t)(b * Sn + row) * (HQn * HDn) + col] =
                make_float2(f2tf(acc2[im][jn][0]), f2tf(acc2[im][jn][1]));
            *(float2*)&O[(size_t)(b * Sn + row + 8) * (HQn * HDn) + col] =
                make_float2(f2tf(acc2[im][jn][2]), f2tf(acc2[im][jn][3]));
        }
}
#define OUT_SMEM ((2 * 128 * 68 + 64 * 68 + 64 * 72 + 128) * 4)

// ---------------- launch ----------------
extern "C" void kernel_launch(void* const* d_in, const int* in_sizes, int n_in,
                              void* d_out, int out_size) {
    const float* x    = (const float*)d_in[0];
    const float* ln_g = (const float*)d_in[1];
    const float* ln_b = (const float*)d_in[2];
    const float* Wq   = (const float*)d_in[3];
    const float* bq   = (const float*)d_in[4];
    const float* Wk   = (const float*)d_in[5];
    const float* bk   = (const float*)d_in[6];
    const float* Wv   = (const float*)d_in[7];
    const float* bv   = (const float*)d_in[8];
    const float* Wo   = (const float*)d_in[9];
    const float* bo   = (const float*)d_in[10];
    float* out = (float*)d_out;

    float *xn, *qkv, *wf, *bf, *wo, *attn, *m, *zi;
    cudaGetSymbolAddress((void**)&xn,   g_xn);
    cudaGetSymbolAddress((void**)&qkv,  g_qkv);
    cudaGetSymbolAddress((void**)&wf,   g_wf);
    cudaGetSymbolAddress((void**)&bf,   g_bf);
    cudaGetSymbolAddress((void**)&wo,   g_wo);
    cudaGetSymbolAddress((void**)&attn, g_attn);
    cudaGetSymbolAddress((void**)&m,    g_m);
    cudaGetSymbolAddress((void**)&zi,   g_zi);

    cudaFuncSetAttribute(gemm_cp,    cudaFuncAttributeMaxDynamicSharedMemorySize, GEMM_SMEM);
    cudaFuncSetAttribute(stats_pass, cudaFuncAttributeMaxDynamicSharedMemorySize, STATS_SMEM);
    cudaFuncSetAttribute(out_pass,   cudaFuncAttributeMaxDynamicSharedMemorySize, OUT_SMEM);

    ln_kernel<<<ROWS, 256>>>(x, ln_g, ln_b, xn);
    prep_qkv_w<<<(Dn * QKVW / 4) / 256, 256>>>(Wq, Wk, Wv, wf);
    prep_qkv_b<<<(QKVW + 255) / 256, 256>>>(bq, bk, bv, bf);
    prep_wo<<<(Dn * Dn / 4) / 256, 256>>>(Wo, wo);

    // fused QKV projection: [4096 x 2048] @ [2048 x 3072]
    gemm_cp<<<dim3(QKVW / 128, ROWS / 128), 256, GEMM_SMEM>>>(
        xn, wf, bf, qkv, ROWS, QKVW, Dn, 0.125f, 1.0f, 2048, 1);

    stats_pass<<<dim3(NTB128, NG), 256, STATS_SMEM>>>(qkv, m, zi);
    out_pass<<<dim3(NTB128, NG), 256, OUT_SMEM>>>(qkv, m, zi, attn);

    // output projection: [4096 x 2048] @ [2048 x 2048]
    gemm_cp<<<dim3(Dn / 128, ROWS / 128), 256, GEMM_SMEM>>>(
        attn, wo, bo, out, ROWS, Dn, HQn * HDn, 1.0f, 1.0f, 0, 0);
}

// round 8
// speedup vs baseline: 4.4840x; 1.0006x over previous
#include <cuda_runtime.h>
#include <cuda_bf16.h>
#include <cstdint>
#include <math.h>

#define Bn 2
#define Sn 2048
#define Dn 2048
#define HQn 32
#define HKVn 8
#define HDn 64
#define ROWS (Bn * Sn)      // 4096
#define NG   (Bn * HQn)     // 64 attention "heads"
#define NTB64 (Sn / 64)     // 32
#define NTB128 (Sn / 128)   // 16
#define QKVW 3072           // fused q|k|v width

// ---------------- scratch ----------------
__device__ float g_xn[ROWS * Dn];
__device__ float g_qkv[(size_t)ROWS * QKVW];       // q: 0..2047, k: 2048..2559, v: 2560..3071
__device__ float g_wf[Dn * QKVW];                  // fused rounded QKV weights
__device__ float g_bf[QKVW];                       // fused bias (raw fp32)
__device__ float g_wo[Dn * Dn];                    // rounded Wo
__device__ float g_attn[ROWS * (HQn * HDn)];
__device__ float g_m[NG * Sn];
__device__ float g_zi[NG * Sn];

// ---------------- helpers ----------------
__device__ __forceinline__ float f2tf(float x) {
    uint32_t r;
    asm("cvt.rna.tf32.f32 %0, %1;" : "=r"(r) : "f"(x));
    return __uint_as_float(r);
}
__device__ __forceinline__ float4 cvt4(float4 v) {
    v.x = f2tf(v.x); v.y = f2tf(v.y); v.z = f2tf(v.z); v.w = f2tf(v.w);
    return v;
}
__device__ __forceinline__ void mma8(float* c, const uint32_t* a, uint32_t b0, uint32_t b1) {
    asm volatile(
        "mma.sync.aligned.m16n8k8.row.col.f32.tf32.tf32.f32 "
        "{%0,%1,%2,%3}, {%4,%5,%6,%7}, {%8,%9}, {%0,%1,%2,%3};"
        : "+f"(c[0]), "+f"(c[1]), "+f"(c[2]), "+f"(c[3])
        : "r"(a[0]), "r"(a[1]), "r"(a[2]), "r"(a[3]), "r"(b0), "r"(b1));
}
__device__ __forceinline__ void cpa16(void* dst_smem, const void* src) {
    uint32_t d = (uint32_t)__cvta_generic_to_shared(dst_smem);
    asm volatile("cp.async.cg.shared.global [%0], [%1], 16;" :: "r"(d), "l"(src));
}
#define CP_COMMIT() asm volatile("cp.async.commit_group;")
#define CP_WAIT(n)  asm volatile("cp.async.wait_group %0;" :: "n"(n))
#define F2U(x) __float_as_uint(x)
#define NEGBIG (-1e30f)

// ---------------- fused pre: LN + weight/bias prep (one launch) ----------------
// blocks [0,4096): LN rows; [4096,10240): qkv W; [10240,14336): Wo; [14336,14348): bias
__global__ __launch_bounds__(256) void fused_pre(
    const float* __restrict__ x, const float* __restrict__ gamma,
    const float* __restrict__ beta,
    const float* __restrict__ Wq, const float* __restrict__ Wk,
    const float* __restrict__ Wv, const float* __restrict__ Wo,
    const float* __restrict__ bq, const float* __restrict__ bk,
    const float* __restrict__ bv,
    float* __restrict__ xn, float* __restrict__ Wf,
    float* __restrict__ Wr, float* __restrict__ bf)
{
    const int blk = blockIdx.x;
    const int tid = threadIdx.x;

    if (blk < ROWS) {                 // ---- LayerNorm ----
        const int row = blk;
        const float* xr = x + (size_t)row * Dn;
        float* outr = xn + (size_t)row * Dn;
        __shared__ float red[256];

        float s = 0.f;
        for (int c = tid; c < Dn; c += 256) s += xr[c];
        red[tid] = s; __syncthreads();
        for (int off = 128; off > 0; off >>= 1) {
            if (tid < off) red[tid] += red[tid + off];
            __syncthreads();
        }
        const float mu = red[0] * (1.0f / Dn);
        __syncthreads();

        float v = 0.f;
        for (int c = tid; c < Dn; c += 256) { float d = xr[c] - mu; v += d * d; }
        red[tid] = v; __syncthreads();
        for (int off = 128; off > 0; off >>= 1) {
            if (tid < off) red[tid] += red[tid + off];
            __syncthreads();
        }
        const float rstd = rsqrtf(red[0] * (1.0f / Dn) + 1e-5f);
        __syncthreads();

        for (int c = tid; c < Dn; c += 256)
            outr[c] = f2tf((xr[c] - mu) * rstd * gamma[c] + beta[c]);
    } else if (blk < ROWS + 6144) {   // ---- QKV weight fuse+round ----
        const int idx = ((blk - ROWS) * 256 + tid) * 4;
        const int row = idx / QKVW, col = idx % QKVW;
        const float* src;
        if (col < 2048)      src = &Wq[(size_t)row * 2048 + col];
        else if (col < 2560) src = &Wk[(size_t)row * 512 + col - 2048];
        else                 src = &Wv[(size_t)row * 512 + col - 2560];
        *(float4*)&Wf[idx] = cvt4(*(const float4*)src);
    } else if (blk < ROWS + 6144 + 4096) {   // ---- Wo round ----
        const int idx = ((blk - ROWS - 6144) * 256 + tid) * 4;
        *(float4*)&Wr[idx] = cvt4(*(const float4*)&Wo[idx]);
    } else {                          // ---- bias fuse ----
        const int col = (blk - ROWS - 6144 - 4096) * 256 + tid;
        if (col < QKVW)
            bf[col] = col < 2048 ? bq[col] : (col < 2560 ? bk[col - 2048] : bv[col - 2560]);
    }
}

// ---------------- cp.async 3-stage tf32 GEMM (inputs pre-rounded) ----------------
#define STAGES 3
#define GEMM_SMEM (STAGES * (128 * 20 + 16 * 136) * 4)

__global__ __launch_bounds__(256) void gemm_cp(
    const float* __restrict__ A, const float* __restrict__ B,
    const float* __restrict__ bias, float* __restrict__ C,
    int M, int N, int K, float scale0, float scale1, int ncut, int round_out)
{
    extern __shared__ float sm[];
    float (*As)[128][20] = (float(*)[128][20])sm;
    float (*Bs)[16][136] = (float(*)[16][136])(sm + STAGES * 128 * 20);

    const int tid = threadIdx.x;
    const int lane = tid & 31, wid = tid >> 5;
    const int warp_m = wid & 3, warp_n = wid >> 2;
    const int m0 = blockIdx.y * 128, n0 = blockIdx.x * 128;

    const int ar = tid >> 2, ac = (tid & 3) * 4;
    const int br = tid >> 5, bc = (tid & 31) * 4;
    const int lr = lane >> 2, lc = lane & 3;

    const int KT = K / 16;

    float acc[2][8][4];
    #pragma unroll
    for (int i = 0; i < 2; i++)
        #pragma unroll
        for (int j = 0; j < 8; j++)
            #pragma unroll
            for (int q = 0; q < 4; q++) acc[i][j][q] = 0.f;

    #pragma unroll
    for (int s = 0; s < STAGES - 1; s++) {
        const int k0 = s * 16;
        const float* ap = &A[(size_t)(m0 + ar) * K + k0 + ac];
        cpa16(&As[s][ar][ac], ap);
        cpa16(&As[s][ar + 64][ac], ap + (size_t)64 * K);
        const float* bp = &B[(size_t)(k0 + br) * N + n0 + bc];
        cpa16(&Bs[s][br][bc], bp);
        cpa16(&Bs[s][br + 8][bc], bp + (size_t)8 * N);
        CP_COMMIT();
    }

    for (int kt = 0; kt < KT; kt++) {
        CP_WAIT(STAGES - 2);
        __syncthreads();

        const int nf = kt + STAGES - 1;
        if (nf < KT) {
            const int s = nf % STAGES;
            const int k0 = nf * 16;
            const float* ap = &A[(size_t)(m0 + ar) * K + k0 + ac];
            cpa16(&As[s][ar][ac], ap);
            cpa16(&As[s][ar + 64][ac], ap + (size_t)64 * K);
            const float* bp = &B[(size_t)(k0 + br) * N + n0 + bc];
            cpa16(&Bs[s][br][bc], bp);
            cpa16(&Bs[s][br + 8][bc], bp + (size_t)8 * N);
        }
        CP_COMMIT();

        const int cur = kt % STAGES;
        #pragma unroll
        for (int ks = 0; ks < 2; ks++) {
            const int k8 = ks * 8;
            uint32_t af[2][4];
            #pragma unroll
            for (int im = 0; im < 2; im++) {
                const int m = warp_m * 32 + im * 16 + lr;
                af[im][0] = F2U(As[cur][m][k8 + lc]);
                af[im][1] = F2U(As[cur][m + 8][k8 + lc]);
                af[im][2] = F2U(As[cur][m][k8 + lc + 4]);
                af[im][3] = F2U(As[cur][m + 8][k8 + lc + 4]);
            }
            #pragma unroll
            for (int jn = 0; jn < 8; jn++) {
                const int n = warp_n * 64 + jn * 8 + lr;
                uint32_t bf0 = F2U(Bs[cur][k8 + lc][n]);
                uint32_t bf1 = F2U(Bs[cur][k8 + lc + 4][n]);
                #pragma unroll
                for (int im = 0; im < 2; im++)
                    mma8(acc[im][jn], af[im], bf0, bf1);
            }
        }
    }

    #pragma unroll
    for (int im = 0; im < 2; im++)
        #pragma unroll
        for (int jn = 0; jn < 8; jn++) {
            const int row = m0 + warp_m * 32 + im * 16 + lr;
            const int col = n0 + warp_n * 64 + jn * 8 + lc * 2;
            const float sc = (col < ncut) ? scale0 : scale1;
            const float bb0 = bias[col], bb1 = bias[col + 1];
            float v00 = sc * (acc[im][jn][0] + bb0);
            float v01 = sc * (acc[im][jn][1] + bb1);
            float v10 = sc * (acc[im][jn][2] + bb0);
            float v11 = sc * (acc[im][jn][3] + bb1);
            if (round_out) { v00 = f2tf(v00); v01 = f2tf(v01); v10 = f2tf(v10); v11 = f2tf(v11); }
            *(float2*)&C[(size_t)row * N + col] = make_float2(v00, v01);
            *(float2*)&C[(size_t)(row + 8) * N + col] = make_float2(v10, v11);
        }
}

// ---------------- pass 1: column softmax stats; K resident, Q double-buffered ----------------
__global__ __launch_bounds__(256) void stats_pass(
    const float* __restrict__ QKV,
    float* __restrict__ gm, float* __restrict__ gzi)
{
    extern __shared__ float sm[];
    float (*Ks)[68] = (float(*)[68])sm;                       // [128][68]
    float (*Qs)[64][68] = (float(*)[64][68])(sm + 128 * 68);  // [2][64][68]

    const int g = blockIdx.y;
    const int b = g >> 5, hq = g & 31, h = hq >> 2;
    const int Tb = blockIdx.x;
    const int T0 = Tb * 128;

    const int tid = threadIdx.x;
    const int lane = tid & 31, w = tid >> 5;
    const int lr = lane >> 2, lc = lane & 3;
    const int r = tid >> 4, c = (tid & 15) * 4;

    const float* Kbase = QKV + 2048 + h * HDn;
    const float* Qbase = QKV + hq * HDn;

    #pragma unroll
    for (int p = 0; p < 8; p++) {
        const int row = p * 16 + r;
        *(float4*)&Ks[row][c] =
            *(const float4*)&Kbase[(size_t)(b * Sn + T0 + row) * QKVW + c];
    }

    const int tb0 = 2 * Tb;
    // prologue: Q tile tb0 -> buf 0
    #pragma unroll
    for (int p = 0; p < 4; p++) {
        const int row = p * 16 + r;
        cpa16(&Qs[0][row][c], &Qbase[(size_t)(b * Sn + tb0 * 64 + row) * QKVW + c]);
    }
    CP_COMMIT();

    const int Trow0 = T0 + w * 16 + lr;
    const int Trow1 = Trow0 + 8;

    float m0 = NEGBIG, z0 = 0.f, m1 = NEGBIG, z1 = 0.f;

    for (int tb = tb0; tb < NTB64; tb++) {
        const int cur = (tb - tb0) & 1;
        __syncthreads();   // frees the other buffer
        if (tb + 1 < NTB64) {
            #pragma unroll
            for (int p = 0; p < 4; p++) {
                const int row = p * 16 + r;
                cpa16(&Qs[cur ^ 1][row][c],
                      &Qbase[(size_t)(b * Sn + (tb + 1) * 64 + row) * QKVW + c]);
            }
        }
        CP_COMMIT();
        CP_WAIT(1);
        __syncthreads();

        float acc[8][4];
        #pragma unroll
        for (int j = 0; j < 8; j++)
            #pragma unroll
            for (int q = 0; q < 4; q++) acc[j][q] = 0.f;

        #pragma unroll
        for (int ks = 0; ks < 8; ks++) {
            const int k8 = ks * 8;
            uint32_t af[4];
            af[0] = F2U(Ks[w * 16 + lr][k8 + lc]);
            af[1] = F2U(Ks[w * 16 + 8 + lr][k8 + lc]);
            af[2] = F2U(Ks[w * 16 + lr][k8 + lc + 4]);
            af[3] = F2U(Ks[w * 16 + 8 + lr][k8 + lc + 4]);
            #pragma unroll
            for (int jn = 0; jn < 8; jn++) {
                uint32_t bf0 = F2U(Qs[cur][jn * 8 + lr][k8 + lc]);
                uint32_t bf1 = F2U(Qs[cur][jn * 8 + lr][k8 + lc + 4]);
                mma8(acc[jn], af, bf0, bf1);
            }
        }

        const int tbase = tb * 64 + lc * 2;
        float tm0 = NEGBIG, tm1 = NEGBIG;
        float va[8][4];
        #pragma unroll
        for (int jn = 0; jn < 8; jn++) {
            const int tcol = tbase + jn * 8;
            va[jn][0] = (tcol     >= Trow0) ? acc[jn][0] : NEGBIG;
            va[jn][1] = (tcol + 1 >= Trow0) ? acc[jn][1] : NEGBIG;
            va[jn][2] = (tcol     >= Trow1) ? acc[jn][2] : NEGBIG;
            va[jn][3] = (tcol + 1 >= Trow1) ? acc[jn][3] : NEGBIG;
            tm0 = fmaxf(tm0, fmaxf(va[jn][0], va[jn][1]));
            tm1 = fmaxf(tm1, fmaxf(va[jn][2], va[jn][3]));
        }
        const float nm0 = fmaxf(m0, tm0);
        const float nm1 = fmaxf(m1, tm1);
        float s0 = 0.f, s1 = 0.f;
        #pragma unroll
        for (int jn = 0; jn < 8; jn++) {
            s0 += __expf(va[jn][0] - nm0) + __expf(va[jn][1] - nm0);
            s1 += __expf(va[jn][2] - nm1) + __expf(va[jn][3] - nm1);
        }
        z0 = z0 * __expf(m0 - nm0) + s0; m0 = nm0;
        z1 = z1 * __expf(m1 - nm1) + s1; m1 = nm1;
    }

    #pragma unroll
    for (int off = 1; off < 4; off <<= 1) {
        float mo = __shfl_xor_sync(0xffffffffu, m0, off);
        float zo = __shfl_xor_sync(0xffffffffu, z0, off);
        float mn = fmaxf(m0, mo);
        z0 = z0 * __expf(m0 - mn) + zo * __expf(mo - mn); m0 = mn;
        mo = __shfl_xor_sync(0xffffffffu, m1, off);
        zo = __shfl_xor_sync(0xffffffffu, z1, off);
        mn = fmaxf(m1, mo);
        z1 = z1 * __expf(m1 - mn) + zo * __expf(mo - mn); m1 = mn;
    }
    if (lc == 0) {
        gm[g * Sn + Trow0] = m0;  gzi[g * Sn + Trow0] = 1.0f / z0;
        gm[g * Sn + Trow1] = m1;  gzi[g * Sn + Trow1] = 1.0f / z1;
    }
}
#define STATS_SMEM ((128 * 68 + 2 * 64 * 68) * 4)

// ---------------- pass 2: Q resident, K/V/stats double-buffered via cp.async ----------------
__global__ __launch_bounds__(256) void out_pass(
    const float* __restrict__ QKV,
    const float* __restrict__ gm, const float* __restrict__ gzi,
    float* __restrict__ O)
{
    extern __shared__ float sm[];
    float (*Qs)[68] = (float(*)[68])sm;                              // [128][68]
    float (*Ks)[64][68] = (float(*)[64][68])(sm + 128 * 68);         // [2][64][68]
    float (*Vs)[64][72] = (float(*)[64][72])(sm + 128 * 68 + 2 * 64 * 68); // [2][64][72]
    float (*Ps)[68] = (float(*)[68])(sm + 128 * 68 + 2 * 64 * 68 + 2 * 64 * 72); // [128][68]
    float* s_st = sm + 2 * 128 * 68 + 2 * 64 * 68 + 2 * 64 * 72;     // [2][128]: m 0..63, zi 64..127

    const int g = blockIdx.y;
    const int b = g >> 5, hq = g & 31, h = hq >> 2;
    const int tblk = (NTB128 - 1) - blockIdx.x;
    const int t0 = tblk * 128;

    const int tid = threadIdx.x;
    const int lane = tid & 31, wid = tid >> 5;
    const int warp_m = wid & 3, warp_n = wid >> 2;
    const int lr = lane >> 2, lc = lane & 3;
    const int r = tid >> 4, c = (tid & 15) * 4;

    const float* Qbase = QKV + hq * HDn;
    const float* Kbase = QKV + 2048 + h * HDn;
    const float* Vbase = QKV + 2560 + h * HDn;

    #pragma unroll
    for (int p = 0; p < 8; p++) {
        const int row = p * 16 + r;
        *(float4*)&Qs[row][c] =
            *(const float4*)&Qbase[(size_t)(b * Sn + t0 + row) * QKVW + c];
    }

    // prologue: tile 0 -> buf 0
    #pragma unroll
    for (int p = 0; p < 4; p++) {
        const int row = p * 16 + r;
        cpa16(&Ks[0][row][c], &Kbase[(size_t)(b * Sn + row) * QKVW + c]);
        cpa16(&Vs[0][row][c], &Vbase[(size_t)(b * Sn + row) * QKVW + c]);
    }
    if (tid < 16)      cpa16(&s_st[tid * 4],      &gm[g * Sn + tid * 4]);
    else if (tid < 32) cpa16(&s_st[64 + (tid - 16) * 4], &gzi[g * Sn + (tid - 16) * 4]);
    CP_COMMIT();

    float acc2[2][4][4];
    #pragma unroll
    for (int i = 0; i < 2; i++)
        #pragma unroll
        for (int j = 0; j < 4; j++)
            #pragma unroll
            for (int q = 0; q < 4; q++) acc2[i][j][q] = 0.f;

    const int nT = 2 * tblk + 2;
    for (int Tb = 0; Tb < nT; Tb++) {
        const int T0 = Tb * 64;
        const int cur = Tb & 1;
        __syncthreads();   // frees the other buffer
        if (Tb + 1 < nT) {
            const int Tn = (Tb + 1) * 64;
            #pragma unroll
            for (int p = 0; p < 4; p++) {
                const int row = p * 16 + r;
                cpa16(&Ks[cur ^ 1][row][c], &Kbase[(size_t)(b * Sn + Tn + row) * QKVW + c]);
                cpa16(&Vs[cur ^ 1][row][c], &Vbase[(size_t)(b * Sn + Tn + row) * QKVW + c]);
            }
            if (tid < 16)
                cpa16(&s_st[(cur ^ 1) * 128 + tid * 4], &gm[g * Sn + Tn + tid * 4]);
            else if (tid < 32)
                cpa16(&s_st[(cur ^ 1) * 128 + 64 + (tid - 16) * 4], &gzi[g * Sn + Tn + (tid - 16) * 4]);
        }
        CP_COMMIT();
        CP_WAIT(1);
        __syncthreads();

        const float* smv = &s_st[cur * 128];

        float acc1[2][4][4];
        #pragma unroll
        for (int i = 0; i < 2; i++)
            #pragma unroll
            for (int j = 0; j < 4; j++)
                #pragma unroll
                for (int q = 0; q < 4; q++) acc1[i][j][q] = 0.f;

        #pragma unroll
        for (int ks = 0; ks < 8; ks++) {
            const int k8 = ks * 8;
            uint32_t af[2][4];
            #pragma unroll
            for (int im = 0; im < 2; im++) {
                const int m = warp_m * 32 + im * 16 + lr;
                af[im][0] = F2U(Qs[m][k8 + lc]);
                af[im][1] = F2U(Qs[m + 8][k8 + lc]);
                af[im][2] = F2U(Qs[m][k8 + lc + 4]);
                af[im][3] = F2U(Qs[m + 8][k8 + lc + 4]);
            }
            #pragma unroll
            for (int jn = 0; jn < 4; jn++) {
                const int n = warp_n * 32 + jn * 8 + lr;
                uint32_t bf0 = F2U(Ks[cur][n][k8 + lc]);
                uint32_t bf1 = F2U(Ks[cur][n][k8 + lc + 4]);
                #pragma unroll
                for (int im = 0; im < 2; im++)
                    mma8(acc1[im][jn], af[im], bf0, bf1);
            }
        }

        const bool diag = (Tb >= 2 * tblk);
        #pragma unroll
        for (int im = 0; im < 2; im++) {
            const int trow = warp_m * 32 + im * 16 + lr;
            const int trg = t0 + trow;
            #pragma unroll
            for (int jn = 0; jn < 4; jn++) {
                const int Tcol = warp_n * 32 + jn * 8 + lc * 2;
                const int Tg = T0 + Tcol;
                const float mm0 = smv[Tcol],      zi0 = smv[64 + Tcol];
                const float mm1 = smv[Tcol + 1],  zi1 = smv[64 + Tcol + 1];
                float p00 = __expf(acc1[im][jn][0] - mm0) * zi0;
                float p01 = __expf(acc1[im][jn][1] - mm1) * zi1;
                float p10 = __expf(acc1[im][jn][2] - mm0) * zi0;
                float p11 = __expf(acc1[im][jn][3] - mm1) * zi1;
                if (diag) {
                    if (trg < Tg)         p00 = 0.f;
                    if (trg < Tg + 1)     p01 = 0.f;
                    if (trg + 8 < Tg)     p10 = 0.f;
                    if (trg + 8 < Tg + 1) p11 = 0.f;
                }
                *(float2*)&Ps[trow][Tcol]     = make_float2(f2tf(p00), f2tf(p01));
                *(float2*)&Ps[trow + 8][Tcol] = make_float2(f2tf(p10), f2tf(p11));
            }
        }
        __syncthreads();

        #pragma unroll
        for (int ks = 0; ks < 8; ks++) {
            const int k8 = ks * 8;
            uint32_t af[2][4];
            #pragma unroll
            for (int im = 0; im < 2; im++) {
                const int m = warp_m * 32 + im * 16 + lr;
                af[im][0] = F2U(Ps[m][k8 + lc]);
                af[im][1] = F2U(Ps[m + 8][k8 + lc]);
                af[im][2] = F2U(Ps[m][k8 + lc + 4]);
                af[im][3] = F2U(Ps[m + 8][k8 + lc + 4]);
            }
            #pragma unroll
            for (int jn = 0; jn < 4; jn++) {
                const int n = warp_n * 32 + jn * 8 + lr;
                uint32_t bf0 = F2U(Vs[cur][k8 + lc][n]);
                uint32_t bf1 = F2U(Vs[cur][k8 + lc + 4][n]);
                #pragma unroll
                for (int im = 0; im < 2; im++)
                    mma8(acc2[im][jn], af[im], bf0, bf1);
            }
        }
    }

    #pragma unroll
    for (int im = 0; im < 2; im++)
        #pragma unroll
        for (int jn = 0; jn < 4; jn++) {
            const int row = t0 + warp_m * 32 + im * 16 + lr;
            const int col = hq * HDn + warp_n * 32 + jn * 8 + lc * 2;
            *(float2*)&O[(size_t)(b * Sn + row) * (HQn * HDn) + col] =
                make_float2(f2tf(acc2[im][jn][0]), f2tf(acc2[im][jn][1]));
            *(float2*)&O[(size_t)(b * Sn + row + 8) * (HQn * HDn) + col] =
                make_float2(f2tf(acc2[im][jn][2]), f2tf(acc2[im][jn][3]));
        }
}
#define OUT_SMEM ((2 * 128 * 68 + 2 * 64 * 68 + 2 * 64 * 72 + 256) * 4)

// ---------------- launch ----------------
extern "C" void kernel_launch(void* const* d_in, const int* in_sizes, int n_in,
                              void* d_out, int out_size) {
    const float* x    = (const float*)d_in[0];
    const float* ln_g = (const float*)d_in[1];
    const float* ln_b = (const float*)d_in[2];
    const float* Wq   = (const float*)d_in[3];
    const float* bq   = (const float*)d_in[4];
    const float* Wk   = (const float*)d_in[5];
    const float* bk   = (const float*)d_in[6];
    const float* Wv   = (const float*)d_in[7];
    const float* bv   = (const float*)d_in[8];
    const float* Wo   = (const float*)d_in[9];
    const float* bo   = (const float*)d_in[10];
    float* out = (float*)d_out;

    float *xn, *qkv, *wf, *bf, *wo, *attn, *m, *zi;
    cudaGetSymbolAddress((void**)&xn,   g_xn);
    cudaGetSymbolAddress((void**)&qkv,  g_qkv);
    cudaGetSymbolAddress((void**)&wf,   g_wf);
    cudaGetSymbolAddress((void**)&bf,   g_bf);
    cudaGetSymbolAddress((void**)&wo,   g_wo);
    cudaGetSymbolAddress((void**)&attn, g_attn);
    cudaGetSymbolAddress((void**)&m,    g_m);
    cudaGetSymbolAddress((void**)&zi,   g_zi);

    cudaFuncSetAttribute(gemm_cp,    cudaFuncAttributeMaxDynamicSharedMemorySize, GEMM_SMEM);
    cudaFuncSetAttribute(stats_pass, cudaFuncAttributeMaxDynamicSharedMemorySize, STATS_SMEM);
    cudaFuncSetAttribute(out_pass,   cudaFuncAttributeMaxDynamicSharedMemorySize, OUT_SMEM);

    fused_pre<<<ROWS + 6144 + 4096 + 12, 256>>>(
        x, ln_g, ln_b, Wq, Wk, Wv, Wo, bq, bk, bv, xn, wf, wo, bf);

    gemm_cp<<<dim3(QKVW / 128, ROWS / 128), 256, GEMM_SMEM>>>(
        xn, wf, bf, qkv, ROWS, QKVW, Dn, 0.125f, 1.0f, 2048, 1);

    stats_pass<<<dim3(NTB128, NG), 256, STATS_SMEM>>>(qkv, m, zi);
    out_pass<<<dim3(NTB128, NG), 256, OUT_SMEM>>>(qkv, m, zi, attn);

    gemm_cp<<<dim3(Dn / 128, ROWS / 128), 256, GEMM_SMEM>>>(
        attn, wo, bo, out, ROWS, Dn, HQn * HDn, 1.0f, 1.0f, 0, 0);
}

// round 9
// speedup vs baseline: 4.6235x; 1.0311x over previous
#include <cuda_runtime.h>
#include <cuda_bf16.h>
#include <cstdint>
#include <math.h>

#define Bn 2
#define Sn 2048
#define Dn 2048
#define HQn 32
#define HKVn 8
#define HDn 64
#define ROWS (Bn * Sn)      // 4096
#define NG   (Bn * HQn)     // 64 attention "heads"
#define NTB64 (Sn / 64)     // 32
#define NTB128 (Sn / 128)   // 16
#define QKVW 3072           // fused q|k|v width

// ---------------- scratch ----------------
__device__ float g_xn[ROWS * Dn];
__device__ float g_qkv[(size_t)ROWS * QKVW];       // q: 0..2047, k: 2048..2559, v: 2560..3071
__device__ float g_wf[Dn * QKVW];                  // fused rounded QKV weights
__device__ float g_bf[QKVW];                       // fused bias (raw fp32)
__device__ float g_wo[Dn * Dn];                    // rounded Wo
__device__ float g_attn[ROWS * (HQn * HDn)];
__device__ float g_m[NG * Sn];
__device__ float g_zi[NG * Sn];

// ---------------- helpers ----------------
__device__ __forceinline__ float f2tf(float x) {
    uint32_t r;
    asm("cvt.rna.tf32.f32 %0, %1;" : "=r"(r) : "f"(x));
    return __uint_as_float(r);
}
__device__ __forceinline__ float4 cvt4(float4 v) {
    v.x = f2tf(v.x); v.y = f2tf(v.y); v.z = f2tf(v.z); v.w = f2tf(v.w);
    return v;
}
__device__ __forceinline__ void mma8(float* c, const uint32_t* a, uint32_t b0, uint32_t b1) {
    asm volatile(
        "mma.sync.aligned.m16n8k8.row.col.f32.tf32.tf32.f32 "
        "{%0,%1,%2,%3}, {%4,%5,%6,%7}, {%8,%9}, {%0,%1,%2,%3};"
        : "+f"(c[0]), "+f"(c[1]), "+f"(c[2]), "+f"(c[3])
        : "r"(a[0]), "r"(a[1]), "r"(a[2]), "r"(a[3]), "r"(b0), "r"(b1));
}
__device__ __forceinline__ void cpa16(void* dst_smem, const void* src) {
    uint32_t d = (uint32_t)__cvta_generic_to_shared(dst_smem);
    asm volatile("cp.async.cg.shared.global [%0], [%1], 16;" :: "r"(d), "l"(src));
}
#define CP_COMMIT() asm volatile("cp.async.commit_group;")
#define CP_WAIT(n)  asm volatile("cp.async.wait_group %0;" :: "n"(n))
#define F2U(x) __float_as_uint(x)
#define NEGBIG (-1e30f)

// ---------------- fused pre: LN + weight/bias prep ----------------
__global__ __launch_bounds__(256) void fused_pre(
    const float* __restrict__ x, const float* __restrict__ gamma,
    const float* __restrict__ beta,
    const float* __restrict__ Wq, const float* __restrict__ Wk,
    const float* __restrict__ Wv, const float* __restrict__ Wo,
    const float* __restrict__ bq, const float* __restrict__ bk,
    const float* __restrict__ bv,
    float* __restrict__ xn, float* __restrict__ Wf,
    float* __restrict__ Wr, float* __restrict__ bf)
{
    const int blk = blockIdx.x;
    const int tid = threadIdx.x;

    if (blk < ROWS) {
        const int row = blk;
        const float* xr = x + (size_t)row * Dn;
        float* outr = xn + (size_t)row * Dn;
        __shared__ float red[256];

        float s = 0.f;
        for (int c = tid; c < Dn; c += 256) s += xr[c];
        red[tid] = s; __syncthreads();
        for (int off = 128; off > 0; off >>= 1) {
            if (tid < off) red[tid] += red[tid + off];
            __syncthreads();
        }
        const float mu = red[0] * (1.0f / Dn);
        __syncthreads();

        float v = 0.f;
        for (int c = tid; c < Dn; c += 256) { float d = xr[c] - mu; v += d * d; }
        red[tid] = v; __syncthreads();
        for (int off = 128; off > 0; off >>= 1) {
            if (tid < off) red[tid] += red[tid + off];
            __syncthreads();
        }
        const float rstd = rsqrtf(red[0] * (1.0f / Dn) + 1e-5f);
        __syncthreads();

        for (int c = tid; c < Dn; c += 256)
            outr[c] = f2tf((xr[c] - mu) * rstd * gamma[c] + beta[c]);
    } else if (blk < ROWS + 6144) {
        const int idx = ((blk - ROWS) * 256 + tid) * 4;
        const int row = idx / QKVW, col = idx % QKVW;
        const float* src;
        if (col < 2048)      src = &Wq[(size_t)row * 2048 + col];
        else if (col < 2560) src = &Wk[(size_t)row * 512 + col - 2048];
        else                 src = &Wv[(size_t)row * 512 + col - 2560];
        *(float4*)&Wf[idx] = cvt4(*(const float4*)src);
    } else if (blk < ROWS + 6144 + 4096) {
        const int idx = ((blk - ROWS - 6144) * 256 + tid) * 4;
        *(float4*)&Wr[idx] = cvt4(*(const float4*)&Wo[idx]);
    } else {
        const int col = (blk - ROWS - 6144 - 4096) * 256 + tid;
        if (col < QKVW)
            bf[col] = col < 2048 ? bq[col] : (col < 2560 ? bk[col - 2048] : bv[col - 2560]);
    }
}

// ---------------- cp.async 3-stage tf32 GEMM ----------------
#define STAGES 3
#define GEMM_SMEM (STAGES * (128 * 20 + 16 * 136) * 4)

__global__ __launch_bounds__(256, 2) void gemm_cp(
    const float* __restrict__ A, const float* __restrict__ B,
    const float* __restrict__ bias, float* __restrict__ C,
    int M, int N, int K, float scale0, float scale1, int ncut, int round_out)
{
    extern __shared__ float sm[];
    float (*As)[128][20] = (float(*)[128][20])sm;
    float (*Bs)[16][136] = (float(*)[16][136])(sm + STAGES * 128 * 20);

    const int tid = threadIdx.x;
    const int lane = tid & 31, wid = tid >> 5;
    const int warp_m = wid & 3, warp_n = wid >> 2;
    const int m0 = blockIdx.y * 128, n0 = blockIdx.x * 128;

    const int ar = tid >> 2, ac = (tid & 3) * 4;
    const int br = tid >> 5, bc = (tid & 31) * 4;
    const int lr = lane >> 2, lc = lane & 3;

    const int KT = K / 16;

    float acc[2][8][4];
    #pragma unroll
    for (int i = 0; i < 2; i++)
        #pragma unroll
        for (int j = 0; j < 8; j++)
            #pragma unroll
            for (int q = 0; q < 4; q++) acc[i][j][q] = 0.f;

    #pragma unroll
    for (int s = 0; s < STAGES - 1; s++) {
        const int k0 = s * 16;
        const float* ap = &A[(size_t)(m0 + ar) * K + k0 + ac];
        cpa16(&As[s][ar][ac], ap);
        cpa16(&As[s][ar + 64][ac], ap + (size_t)64 * K);
        const float* bp = &B[(size_t)(k0 + br) * N + n0 + bc];
        cpa16(&Bs[s][br][bc], bp);
        cpa16(&Bs[s][br + 8][bc], bp + (size_t)8 * N);
        CP_COMMIT();
    }

    for (int kt = 0; kt < KT; kt++) {
        CP_WAIT(STAGES - 2);
        __syncthreads();

        const int nf = kt + STAGES - 1;
        if (nf < KT) {
            const int s = nf % STAGES;
            const int k0 = nf * 16;
            const float* ap = &A[(size_t)(m0 + ar) * K + k0 + ac];
            cpa16(&As[s][ar][ac], ap);
            cpa16(&As[s][ar + 64][ac], ap + (size_t)64 * K);
            const float* bp = &B[(size_t)(k0 + br) * N + n0 + bc];
            cpa16(&Bs[s][br][bc], bp);
            cpa16(&Bs[s][br + 8][bc], bp + (size_t)8 * N);
        }
        CP_COMMIT();

        const int cur = kt % STAGES;
        #pragma unroll
        for (int ks = 0; ks < 2; ks++) {
            const int k8 = ks * 8;
            uint32_t af[2][4];
            #pragma unroll
            for (int im = 0; im < 2; im++) {
                const int m = warp_m * 32 + im * 16 + lr;
                af[im][0] = F2U(As[cur][m][k8 + lc]);
                af[im][1] = F2U(As[cur][m + 8][k8 + lc]);
                af[im][2] = F2U(As[cur][m][k8 + lc + 4]);
                af[im][3] = F2U(As[cur][m + 8][k8 + lc + 4]);
            }
            #pragma unroll
            for (int jn = 0; jn < 8; jn++) {
                const int n = warp_n * 64 + jn * 8 + lr;
                uint32_t bf0 = F2U(Bs[cur][k8 + lc][n]);
                uint32_t bf1 = F2U(Bs[cur][k8 + lc + 4][n]);
                #pragma unroll
                for (int im = 0; im < 2; im++)
                    mma8(acc[im][jn], af[im], bf0, bf1);
            }
        }
    }

    #pragma unroll
    for (int im = 0; im < 2; im++)
        #pragma unroll
        for (int jn = 0; jn < 8; jn++) {
            const int row = m0 + warp_m * 32 + im * 16 + lr;
            const int col = n0 + warp_n * 64 + jn * 8 + lc * 2;
            const float sc = (col < ncut) ? scale0 : scale1;
            const float bb0 = bias[col], bb1 = bias[col + 1];
            float v00 = sc * (acc[im][jn][0] + bb0);
            float v01 = sc * (acc[im][jn][1] + bb1);
            float v10 = sc * (acc[im][jn][2] + bb0);
            float v11 = sc * (acc[im][jn][3] + bb1);
            if (round_out) { v00 = f2tf(v00); v01 = f2tf(v01); v10 = f2tf(v10); v11 = f2tf(v11); }
            *(float2*)&C[(size_t)row * N + col] = make_float2(v00, v01);
            *(float2*)&C[(size_t)(row + 8) * N + col] = make_float2(v10, v11);
        }
}

// ---------------- pass 1: column softmax stats; K resident, Q double-buffered ----------------
__global__ __launch_bounds__(256, 2) void stats_pass(
    const float* __restrict__ QKV,
    float* __restrict__ gm, float* __restrict__ gzi)
{
    extern __shared__ float sm[];
    float (*Ks)[68] = (float(*)[68])sm;                       // [128][68]
    float (*Qs)[64][68] = (float(*)[64][68])(sm + 128 * 68);  // [2][64][68]

    const int g = blockIdx.y;
    const int b = g >> 5, hq = g & 31, h = hq >> 2;
    const int Tb = blockIdx.x;
    const int T0 = Tb * 128;

    const int tid = threadIdx.x;
    const int lane = tid & 31, w = tid >> 5;
    const int lr = lane >> 2, lc = lane & 3;
    const int r = tid >> 4, c = (tid & 15) * 4;

    const float* Kbase = QKV + 2048 + h * HDn;
    const float* Qbase = QKV + hq * HDn;

    #pragma unroll
    for (int p = 0; p < 8; p++) {
        const int row = p * 16 + r;
        *(float4*)&Ks[row][c] =
            *(const float4*)&Kbase[(size_t)(b * Sn + T0 + row) * QKVW + c];
    }

    const int tb0 = 2 * Tb;
    #pragma unroll
    for (int p = 0; p < 4; p++) {
        const int row = p * 16 + r;
        cpa16(&Qs[0][row][c], &Qbase[(size_t)(b * Sn + tb0 * 64 + row) * QKVW + c]);
    }
    CP_COMMIT();

    const int Trow0 = T0 + w * 16 + lr;
    const int Trow1 = Trow0 + 8;

    float m0 = NEGBIG, z0 = 0.f, m1 = NEGBIG, z1 = 0.f;

    for (int tb = tb0; tb < NTB64; tb++) {
        const int cur = (tb - tb0) & 1;
        __syncthreads();
        if (tb + 1 < NTB64) {
            #pragma unroll
            for (int p = 0; p < 4; p++) {
                const int row = p * 16 + r;
                cpa16(&Qs[cur ^ 1][row][c],
                      &Qbase[(size_t)(b * Sn + (tb + 1) * 64 + row) * QKVW + c]);
            }
        }
        CP_COMMIT();
        CP_WAIT(1);
        __syncthreads();

        float acc[8][4];
        #pragma unroll
        for (int j = 0; j < 8; j++)
            #pragma unroll
            for (int q = 0; q < 4; q++) acc[j][q] = 0.f;

        #pragma unroll
        for (int ks = 0; ks < 8; ks++) {
            const int k8 = ks * 8;
            uint32_t af[4];
            af[0] = F2U(Ks[w * 16 + lr][k8 + lc]);
            af[1] = F2U(Ks[w * 16 + 8 + lr][k8 + lc]);
            af[2] = F2U(Ks[w * 16 + lr][k8 + lc + 4]);
            af[3] = F2U(Ks[w * 16 + 8 + lr][k8 + lc + 4]);
            #pragma unroll
            for (int jn = 0; jn < 8; jn++) {
                uint32_t bf0 = F2U(Qs[cur][jn * 8 + lr][k8 + lc]);
                uint32_t bf1 = F2U(Qs[cur][jn * 8 + lr][k8 + lc + 4]);
                mma8(acc[jn], af, bf0, bf1);
            }
        }

        const int tbase = tb * 64 + lc * 2;
        float tm0 = NEGBIG, tm1 = NEGBIG;
        float va[8][4];
        #pragma unroll
        for (int jn = 0; jn < 8; jn++) {
            const int tcol = tbase + jn * 8;
            va[jn][0] = (tcol     >= Trow0) ? acc[jn][0] : NEGBIG;
            va[jn][1] = (tcol + 1 >= Trow0) ? acc[jn][1] : NEGBIG;
            va[jn][2] = (tcol     >= Trow1) ? acc[jn][2] : NEGBIG;
            va[jn][3] = (tcol + 1 >= Trow1) ? acc[jn][3] : NEGBIG;
            tm0 = fmaxf(tm0, fmaxf(va[jn][0], va[jn][1]));
            tm1 = fmaxf(tm1, fmaxf(va[jn][2], va[jn][3]));
        }
        const float nm0 = fmaxf(m0, tm0);
        const float nm1 = fmaxf(m1, tm1);
        float s0 = 0.f, s1 = 0.f;
        #pragma unroll
        for (int jn = 0; jn < 8; jn++) {
            s0 += __expf(va[jn][0] - nm0) + __expf(va[jn][1] - nm0);
            s1 += __expf(va[jn][2] - nm1) + __expf(va[jn][3] - nm1);
        }
        z0 = z0 * __expf(m0 - nm0) + s0; m0 = nm0;
        z1 = z1 * __expf(m1 - nm1) + s1; m1 = nm1;
    }

    #pragma unroll
    for (int off = 1; off < 4; off <<= 1) {
        float mo = __shfl_xor_sync(0xffffffffu, m0, off);
        float zo = __shfl_xor_sync(0xffffffffu, z0, off);
        float mn = fmaxf(m0, mo);
        z0 = z0 * __expf(m0 - mn) + zo * __expf(mo - mn); m0 = mn;
        mo = __shfl_xor_sync(0xffffffffu, m1, off);
        zo = __shfl_xor_sync(0xffffffffu, z1, off);
        mn = fmaxf(m1, mo);
        z1 = z1 * __expf(m1 - mn) + zo * __expf(mo - mn); m1 = mn;
    }
    if (lc == 0) {
        gm[g * Sn + Trow0] = m0;  gzi[g * Sn + Trow0] = 1.0f / z0;
        gm[g * Sn + Trow1] = m1;  gzi[g * Sn + Trow1] = 1.0f / z1;
    }
}
#define STATS_SMEM ((128 * 68 + 2 * 64 * 68) * 4)

// ---------------- pass 2: single-buffered K/V with split prefetch; 2 CTAs/SM ----------------
// group order: A(K+stats) then B(V), alternating; every CP_WAIT(1) retires the oldest.
__global__ __launch_bounds__(256, 2) void out_pass(
    const float* __restrict__ QKV,
    const float* __restrict__ gm, const float* __restrict__ gzi,
    float* __restrict__ O)
{
    extern __shared__ float sm[];
    float (*Qs)[68] = (float(*)[68])sm;                          // [128][68]
    float (*Ks)[68] = (float(*)[68])(sm + 128 * 68);             // [64][68]
    float (*Vs)[72] = (float(*)[72])(sm + 128 * 68 + 64 * 68);   // [64][72]
    float (*Ps)[68] = (float(*)[68])(sm + 128 * 68 + 64 * 68 + 64 * 72); // [128][68]
    float* s_st = sm + 2 * 128 * 68 + 64 * 68 + 64 * 72;         // [128]: m 0..63, zi 64..127

    const int g = blockIdx.y;
    const int b = g >> 5, hq = g & 31, h = hq >> 2;
    const int tblk = (NTB128 - 1) - blockIdx.x;
    const int t0 = tblk * 128;

    const int tid = threadIdx.x;
    const int lane = tid & 31, wid = tid >> 5;
    const int warp_m = wid & 3, warp_n = wid >> 2;
    const int lr = lane >> 2, lc = lane & 3;
    const int r = tid >> 4, c = (tid & 15) * 4;

    const float* Qbase = QKV + hq * HDn;
    const float* Kbase = QKV + 2048 + h * HDn;
    const float* Vbase = QKV + 2560 + h * HDn;

    #pragma unroll
    for (int p = 0; p < 8; p++) {
        const int row = p * 16 + r;
        *(float4*)&Qs[row][c] =
            *(const float4*)&Qbase[(size_t)(b * Sn + t0 + row) * QKVW + c];
    }

    // prologue: group A0 = K(0) + stats(0)
    #pragma unroll
    for (int p = 0; p < 4; p++) {
        const int row = p * 16 + r;
        cpa16(&Ks[row][c], &Kbase[(size_t)(b * Sn + row) * QKVW + c]);
    }
    if (tid < 16)      cpa16(&s_st[tid * 4],             &gm[g * Sn + tid * 4]);
    else if (tid < 32) cpa16(&s_st[64 + (tid - 16) * 4], &gzi[g * Sn + (tid - 16) * 4]);
    CP_COMMIT();

    float acc2[2][4][4];
    #pragma unroll
    for (int i = 0; i < 2; i++)
        #pragma unroll
        for (int j = 0; j < 4; j++)
            #pragma unroll
            for (int q = 0; q < 4; q++) acc2[i][j][q] = 0.f;

    const int nT = 2 * tblk + 2;
    for (int Tb = 0; Tb < nT; Tb++) {
        const int T0 = Tb * 64;

        __syncthreads();                           // (1) prev stage2 done: Vs, Ps free
        // group B_Tb = V(Tb)
        #pragma unroll
        for (int p = 0; p < 4; p++) {
            const int row = p * 16 + r;
            cpa16(&Vs[row][c], &Vbase[(size_t)(b * Sn + T0 + row) * QKVW + c]);
        }
        CP_COMMIT();
        CP_WAIT(1);                                // A_Tb done: K(Tb) + stats(Tb)
        __syncthreads();                           // (2)

        // stage 1: S = Q . K
        float acc1[2][4][4];
        #pragma unroll
        for (int i = 0; i < 2; i++)
            #pragma unroll
            for (int j = 0; j < 4; j++)
                #pragma unroll
                for (int q = 0; q < 4; q++) acc1[i][j][q] = 0.f;

        #pragma unroll
        for (int ks = 0; ks < 8; ks++) {
            const int k8 = ks * 8;
            uint32_t af[2][4];
            #pragma unroll
            for (int im = 0; im < 2; im++) {
                const int m = warp_m * 32 + im * 16 + lr;
                af[im][0] = F2U(Qs[m][k8 + lc]);
                af[im][1] = F2U(Qs[m + 8][k8 + lc]);
                af[im][2] = F2U(Qs[m][k8 + lc + 4]);
                af[im][3] = F2U(Qs[m + 8][k8 + lc + 4]);
            }
            #pragma unroll
            for (int jn = 0; jn < 4; jn++) {
                const int n = warp_n * 32 + jn * 8 + lr;
                uint32_t bf0 = F2U(Ks[n][k8 + lc]);
                uint32_t bf1 = F2U(Ks[n][k8 + lc + 4]);
                #pragma unroll
                for (int im = 0; im < 2; im++)
                    mma8(acc1[im][jn], af[im], bf0, bf1);
            }
        }

        // softmax apply -> Ps (reads s_st of Tb)
        const bool diag = (Tb >= 2 * tblk);
        #pragma unroll
        for (int im = 0; im < 2; im++) {
            const int trow = warp_m * 32 + im * 16 + lr;
            const int trg = t0 + trow;
            #pragma unroll
            for (int jn = 0; jn < 4; jn++) {
                const int Tcol = warp_n * 32 + jn * 8 + lc * 2;
                const int Tg = T0 + Tcol;
                const float mm0 = s_st[Tcol],      zi0 = s_st[64 + Tcol];
                const float mm1 = s_st[Tcol + 1],  zi1 = s_st[64 + Tcol + 1];
                float p00 = __expf(acc1[im][jn][0] - mm0) * zi0;
                float p01 = __expf(acc1[im][jn][1] - mm1) * zi1;
                float p10 = __expf(acc1[im][jn][2] - mm0) * zi0;
                float p11 = __expf(acc1[im][jn][3] - mm1) * zi1;
                if (diag) {
                    if (trg < Tg)         p00 = 0.f;
                    if (trg < Tg + 1)     p01 = 0.f;
                    if (trg + 8 < Tg)     p10 = 0.f;
                    if (trg + 8 < Tg + 1) p11 = 0.f;
                }
                *(float2*)&Ps[trow][Tcol]     = make_float2(f2tf(p00), f2tf(p01));
                *(float2*)&Ps[trow + 8][Tcol] = make_float2(f2tf(p10), f2tf(p11));
            }
        }
        __syncthreads();                           // (3) Ps ready; Ks, s_st free

        // group A_{Tb+1} = K(Tb+1) + stats(Tb+1)
        if (Tb + 1 < nT) {
            const int Tn = (Tb + 1) * 64;
            #pragma unroll
            for (int p = 0; p < 4; p++) {
                const int row = p * 16 + r;
                cpa16(&Ks[row][c], &Kbase[(size_t)(b * Sn + Tn + row) * QKVW + c]);
            }
            if (tid < 16)      cpa16(&s_st[tid * 4],             &gm[g * Sn + Tn + tid * 4]);
            else if (tid < 32) cpa16(&s_st[64 + (tid - 16) * 4], &gzi[g * Sn + Tn + (tid - 16) * 4]);
        }
        CP_COMMIT();
        CP_WAIT(1);                                // B_Tb done: V(Tb)
        __syncthreads();                           // (4)

        // stage 2: O += P @ V
        #pragma unroll
        for (int ks = 0; ks < 8; ks++) {
            const int k8 = ks * 8;
            uint32_t af[2][4];
            #pragma unroll
            for (int im = 0; im < 2; im++) {
                const int m = warp_m * 32 + im * 16 + lr;
                af[im][0] = F2U(Ps[m][k8 + lc]);
                af[im][1] = F2U(Ps[m + 8][k8 + lc]);
                af[im][2] = F2U(Ps[m][k8 + lc + 4]);
                af[im][3] = F2U(Ps[m + 8][k8 + lc + 4]);
            }
            #pragma unroll
            for (int jn = 0; jn < 4; jn++) {
                const int n = warp_n * 32 + jn * 8 + lr;
                uint32_t bf0 = F2U(Vs[k8 + lc][n]);
                uint32_t bf1 = F2U(Vs[k8 + lc + 4][n]);
                #pragma unroll
                for (int im = 0; im < 2; im++)
                    mma8(acc2[im][jn], af[im], bf0, bf1);
            }
        }
    }

    #pragma unroll
    for (int im = 0; im < 2; im++)
        #pragma unroll
        for (int jn = 0; jn < 4; jn++) {
            const int row = t0 + warp_m * 32 + im * 16 + lr;
            const int col = hq * HDn + warp_n * 32 + jn * 8 + lc * 2;
            *(float2*)&O[(size_t)(b * Sn + row) * (HQn * HDn) + col] =
                make_float2(f2tf(acc2[im][jn][0]), f2tf(acc2[im][jn][1]));
            *(float2*)&O[(size_t)(b * Sn + row + 8) * (HQn * HDn) + col] =
                make_float2(f2tf(acc2[im][jn][2]), f2tf(acc2[im][jn][3]));
        }
}
#define OUT_SMEM ((2 * 128 * 68 + 64 * 68 + 64 * 72 + 128) * 4)

// ---------------- launch ----------------
extern "C" void kernel_launch(void* const* d_in, const int* in_sizes, int n_in,
                              void* d_out, int out_size) {
    const float* x    = (const float*)d_in[0];
    const float* ln_g = (const float*)d_in[1];
    const float* ln_b = (const float*)d_in[2];
    const float* Wq   = (const float*)d_in[3];
    const float* bq   = (const float*)d_in[4];
    const float* Wk   = (const float*)d_in[5];
    const float* bk   = (const float*)d_in[6];
    const float* Wv   = (const float*)d_in[7];
    const float* bv   = (const float*)d_in[8];
    const float* Wo   = (const float*)d_in[9];
    const float* bo   = (const float*)d_in[10];
    float* out = (float*)d_out;

    float *xn, *qkv, *wf, *bf, *wo, *attn, *m, *zi;
    cudaGetSymbolAddress((void**)&xn,   g_xn);
    cudaGetSymbolAddress((void**)&qkv,  g_qkv);
    cudaGetSymbolAddress((void**)&wf,   g_wf);
    cudaGetSymbolAddress((void**)&bf,   g_bf);
    cudaGetSymbolAddress((void**)&wo,   g_wo);
    cudaGetSymbolAddress((void**)&attn, g_attn);
    cudaGetSymbolAddress((void**)&m,    g_m);
    cudaGetSymbolAddress((void**)&zi,   g_zi);

    cudaFuncSetAttribute(gemm_cp,    cudaFuncAttributeMaxDynamicSharedMemorySize, GEMM_SMEM);
    cudaFuncSetAttribute(stats_pass, cudaFuncAttributeMaxDynamicSharedMemorySize, STATS_SMEM);
    cudaFuncSetAttribute(out_pass,   cudaFuncAttributeMaxDynamicSharedMemorySize, OUT_SMEM);

    fused_pre<<<ROWS + 6144 + 4096 + 12, 256>>>(
        x, ln_g, ln_b, Wq, Wk, Wv, Wo, bq, bk, bv, xn, wf, wo, bf);

    gemm_cp<<<dim3(QKVW / 128, ROWS / 128), 256, GEMM_SMEM>>>(
        xn, wf, bf, qkv, ROWS, QKVW, Dn, 0.125f, 1.0f, 2048, 1);

    stats_pass<<<dim3(NTB128, NG), 256, STATS_SMEM>>>(qkv, m, zi);
    out_pass<<<dim3(NTB128, NG), 256, OUT_SMEM>>>(qkv, m, zi, attn);

    gemm_cp<<<dim3(Dn / 128, ROWS / 128), 256, GEMM_SMEM>>>(
        attn, wo, bo, out, ROWS, Dn, HQn * HDn, 1.0f, 1.0f, 0, 0);
}

// round 10
// speedup vs baseline: 4.7618x; 1.0299x over previous
#include <cuda_runtime.h>
#include <cuda_bf16.h>
#include <cstdint>
#include <math.h>

#define Bn 2
#define Sn 2048
#define Dn 2048
#define HQn 32
#define HKVn 8
#define HDn 64
#define ROWS (Bn * Sn)      // 4096
#define NG   (Bn * HQn)     // 64 attention "heads"
#define NTB64 (Sn / 64)     // 32
#define NTB128 (Sn / 128)   // 16
#define QKVW 3072           // fused q|k|v width
#define QSCALE 0.18033688011112042f   // 0.125 * log2(e)

// ---------------- scratch ----------------
__device__ float g_xn[ROWS * Dn];
__device__ float g_qkv[(size_t)ROWS * QKVW];
__device__ float g_wf[Dn * QKVW];
__device__ float g_bf[QKVW];
__device__ float g_wo[Dn * Dn];
__device__ float g_attn[ROWS * (HQn * HDn)];
__device__ float g_m[NG * Sn];
__device__ float g_zi[NG * Sn];

// ---------------- helpers ----------------
__device__ __forceinline__ float f2tf(float x) {
    uint32_t r;
    asm("cvt.rna.tf32.f32 %0, %1;" : "=r"(r) : "f"(x));
    return __uint_as_float(r);
}
__device__ __forceinline__ float4 cvt4(float4 v) {
    v.x = f2tf(v.x); v.y = f2tf(v.y); v.z = f2tf(v.z); v.w = f2tf(v.w);
    return v;
}
__device__ __forceinline__ float fex2(float x) {   // 2^x, MUFU.EX2
    float r;
    asm("ex2.approx.ftz.f32 %0, %1;" : "=f"(r) : "f"(x));
    return r;
}
__device__ __forceinline__ void mma8(float* c, const uint32_t* a, uint32_t b0, uint32_t b1) {
    asm volatile(
        "mma.sync.aligned.m16n8k8.row.col.f32.tf32.tf32.f32 "
        "{%0,%1,%2,%3}, {%4,%5,%6,%7}, {%8,%9}, {%0,%1,%2,%3};"
        : "+f"(c[0]), "+f"(c[1]), "+f"(c[2]), "+f"(c[3])
        : "r"(a[0]), "r"(a[1]), "r"(a[2]), "r"(a[3]), "r"(b0), "r"(b1));
}
__device__ __forceinline__ void cpa16(void* dst_smem, const void* src) {
    uint32_t d = (uint32_t)__cvta_generic_to_shared(dst_smem);
    asm volatile("cp.async.cg.shared.global [%0], [%1], 16;" :: "r"(d), "l"(src));
}
#define CP_COMMIT() asm volatile("cp.async.commit_group;")
#define CP_WAIT(n)  asm volatile("cp.async.wait_group %0;" :: "n"(n))
#define F2U(x) __float_as_uint(x)
#define NEGBIG (-1e30f)

// ---------------- fused pre: LN + weight/bias prep ----------------
__global__ __launch_bounds__(256) void fused_pre(
    const float* __restrict__ x, const float* __restrict__ gamma,
    const float* __restrict__ beta,
    const float* __restrict__ Wq, const float* __restrict__ Wk,
    const float* __restrict__ Wv, const float* __restrict__ Wo,
    const float* __restrict__ bq, const float* __restrict__ bk,
    const float* __restrict__ bv,
    float* __restrict__ xn, float* __restrict__ Wf,
    float* __restrict__ Wr, float* __restrict__ bf)
{
    const int blk = blockIdx.x;
    const int tid = threadIdx.x;

    if (blk < ROWS) {
        const int row = blk;
        const float* xr = x + (size_t)row * Dn;
        float* outr = xn + (size_t)row * Dn;
        __shared__ float red[256];

        float s = 0.f;
        for (int c = tid; c < Dn; c += 256) s += xr[c];
        red[tid] = s; __syncthreads();
        for (int off = 128; off > 0; off >>= 1) {
            if (tid < off) red[tid] += red[tid + off];
            __syncthreads();
        }
        const float mu = red[0] * (1.0f / Dn);
        __syncthreads();

        float v = 0.f;
        for (int c = tid; c < Dn; c += 256) { float d = xr[c] - mu; v += d * d; }
        red[tid] = v; __syncthreads();
        for (int off = 128; off > 0; off >>= 1) {
            if (tid < off) red[tid] += red[tid + off];
            __syncthreads();
        }
        const float rstd = rsqrtf(red[0] * (1.0f / Dn) + 1e-5f);
        __syncthreads();

        for (int c = tid; c < Dn; c += 256)
            outr[c] = f2tf((xr[c] - mu) * rstd * gamma[c] + beta[c]);
    } else if (blk < ROWS + 6144) {
        const int idx = ((blk - ROWS) * 256 + tid) * 4;
        const int row = idx / QKVW, col = idx % QKVW;
        const float* src;
        if (col < 2048)      src = &Wq[(size_t)row * 2048 + col];
        else if (col < 2560) src = &Wk[(size_t)row * 512 + col - 2048];
        else                 src = &Wv[(size_t)row * 512 + col - 2560];
        *(float4*)&Wf[idx] = cvt4(*(const float4*)src);
    } else if (blk < ROWS + 6144 + 4096) {
        const int idx = ((blk - ROWS - 6144) * 256 + tid) * 4;
        *(float4*)&Wr[idx] = cvt4(*(const float4*)&Wo[idx]);
    } else {
        const int col = (blk - ROWS - 6144 - 4096) * 256 + tid;
        if (col < QKVW)
            bf[col] = col < 2048 ? bq[col] : (col < 2560 ? bk[col - 2048] : bv[col - 2560]);
    }
}

// ---------------- cp.async 3-stage tf32 GEMM ----------------
#define STAGES 3
#define GEMM_SMEM (STAGES * (128 * 20 + 16 * 136) * 4)

__global__ __launch_bounds__(256, 2) void gemm_cp(
    const float* __restrict__ A, const float* __restrict__ B,
    const float* __restrict__ bias, float* __restrict__ C,
    int M, int N, int K, float scale0, float scale1, int ncut, int round_out)
{
    extern __shared__ float sm[];
    float (*As)[128][20] = (float(*)[128][20])sm;
    float (*Bs)[16][136] = (float(*)[16][136])(sm + STAGES * 128 * 20);

    const int tid = threadIdx.x;
    const int lane = tid & 31, wid = tid >> 5;
    const int warp_m = wid & 3, warp_n = wid >> 2;
    const int m0 = blockIdx.y * 128, n0 = blockIdx.x * 128;

    const int ar = tid >> 2, ac = (tid & 3) * 4;
    const int br = tid >> 5, bc = (tid & 31) * 4;
    const int lr = lane >> 2, lc = lane & 3;

    const int KT = K / 16;

    float acc[2][8][4];
    #pragma unroll
    for (int i = 0; i < 2; i++)
        #pragma unroll
        for (int j = 0; j < 8; j++)
            #pragma unroll
            for (int q = 0; q < 4; q++) acc[i][j][q] = 0.f;

    #pragma unroll
    for (int s = 0; s < STAGES - 1; s++) {
        const int k0 = s * 16;
        const float* ap = &A[(size_t)(m0 + ar) * K + k0 + ac];
        cpa16(&As[s][ar][ac], ap);
        cpa16(&As[s][ar + 64][ac], ap + (size_t)64 * K);
        const float* bp = &B[(size_t)(k0 + br) * N + n0 + bc];
        cpa16(&Bs[s][br][bc], bp);
        cpa16(&Bs[s][br + 8][bc], bp + (size_t)8 * N);
        CP_COMMIT();
    }

    for (int kt = 0; kt < KT; kt++) {
        CP_WAIT(STAGES - 2);
        __syncthreads();

        const int nf = kt + STAGES - 1;
        if (nf < KT) {
            const int s = nf % STAGES;
            const int k0 = nf * 16;
            const float* ap = &A[(size_t)(m0 + ar) * K + k0 + ac];
            cpa16(&As[s][ar][ac], ap);
            cpa16(&As[s][ar + 64][ac], ap + (size_t)64 * K);
            const float* bp = &B[(size_t)(k0 + br) * N + n0 + bc];
            cpa16(&Bs[s][br][bc], bp);
            cpa16(&Bs[s][br + 8][bc], bp + (size_t)8 * N);
        }
        CP_COMMIT();

        const int cur = kt % STAGES;
        #pragma unroll
        for (int ks = 0; ks < 2; ks++) {
            const int k8 = ks * 8;
            uint32_t af[2][4];
            #pragma unroll
            for (int im = 0; im < 2; im++) {
                const int m = warp_m * 32 + im * 16 + lr;
                af[im][0] = F2U(As[cur][m][k8 + lc]);
                af[im][1] = F2U(As[cur][m + 8][k8 + lc]);
                af[im][2] = F2U(As[cur][m][k8 + lc + 4]);
                af[im][3] = F2U(As[cur][m + 8][k8 + lc + 4]);
            }
            #pragma unroll
            for (int jn = 0; jn < 8; jn++) {
                const int n = warp_n * 64 + jn * 8 + lr;
                uint32_t bf0 = F2U(Bs[cur][k8 + lc][n]);
                uint32_t bf1 = F2U(Bs[cur][k8 + lc + 4][n]);
                #pragma unroll
                for (int im = 0; im < 2; im++)
                    mma8(acc[im][jn], af[im], bf0, bf1);
            }
        }
    }

    #pragma unroll
    for (int im = 0; im < 2; im++)
        #pragma unroll
        for (int jn = 0; jn < 8; jn++) {
            const int row = m0 + warp_m * 32 + im * 16 + lr;
            const int col = n0 + warp_n * 64 + jn * 8 + lc * 2;
            const float sc = (col < ncut) ? scale0 : scale1;
            const float bb0 = bias[col], bb1 = bias[col + 1];
            float v00 = sc * (acc[im][jn][0] + bb0);
            float v01 = sc * (acc[im][jn][1] + bb1);
            float v10 = sc * (acc[im][jn][2] + bb0);
            float v11 = sc * (acc[im][jn][3] + bb1);
            if (round_out) { v00 = f2tf(v00); v01 = f2tf(v01); v10 = f2tf(v10); v11 = f2tf(v11); }
            *(float2*)&C[(size_t)row * N + col] = make_float2(v00, v01);
            *(float2*)&C[(size_t)(row + 8) * N + col] = make_float2(v10, v11);
        }
}

// ---------------- pass 1: column softmax stats (exp2 domain) ----------------
// K resident [128][72], Q double-buffered; paired 64-bit fragment loads.
__global__ __launch_bounds__(256, 2) void stats_pass(
    const float* __restrict__ QKV,
    float* __restrict__ gm, float* __restrict__ gzi)
{
    extern __shared__ float sm[];
    float (*Ks)[72] = (float(*)[72])sm;                       // [128][72]
    float (*Qs)[64][72] = (float(*)[64][72])(sm + 128 * 72);  // [2][64][72]

    const int g = blockIdx.y;
    const int b = g >> 5, hq = g & 31, h = hq >> 2;
    const int Tb = blockIdx.x;
    const int T0 = Tb * 128;

    const int tid = threadIdx.x;
    const int lane = tid & 31, w = tid >> 5;
    const int lr = lane >> 2, lc = lane & 3;
    const int r = tid >> 4, c = (tid & 15) * 4;

    const float* Kbase = QKV + 2048 + h * HDn;
    const float* Qbase = QKV + hq * HDn;

    #pragma unroll
    for (int p = 0; p < 8; p++) {
        const int row = p * 16 + r;
        *(float4*)&Ks[row][c] =
            *(const float4*)&Kbase[(size_t)(b * Sn + T0 + row) * QKVW + c];
    }

    const int tb0 = 2 * Tb;
    #pragma unroll
    for (int p = 0; p < 4; p++) {
        const int row = p * 16 + r;
        cpa16(&Qs[0][row][c], &Qbase[(size_t)(b * Sn + tb0 * 64 + row) * QKVW + c]);
    }
    CP_COMMIT();

    const int Trow0 = T0 + w * 16 + lr;
    const int Trow1 = Trow0 + 8;

    float m0 = NEGBIG, z0 = 0.f, m1 = NEGBIG, z1 = 0.f;

    for (int tb = tb0; tb < NTB64; tb++) {
        const int cur = (tb - tb0) & 1;
        __syncthreads();
        if (tb + 1 < NTB64) {
            #pragma unroll
            for (int p = 0; p < 4; p++) {
                const int row = p * 16 + r;
                cpa16(&Qs[cur ^ 1][row][c],
                      &Qbase[(size_t)(b * Sn + (tb + 1) * 64 + row) * QKVW + c]);
            }
        }
        CP_COMMIT();
        CP_WAIT(1);
        __syncthreads();

        float acc[8][4];
        #pragma unroll
        for (int j = 0; j < 8; j++)
            #pragma unroll
            for (int q = 0; q < 4; q++) acc[j][q] = 0.f;

        #pragma unroll
        for (int ks = 0; ks < 8; ks++) {
            const int k8 = ks * 8;
            uint32_t af[4];
            // paired 64-bit loads: physical cols (2lc, 2lc+1) -> slots (lc, lc+4)
            const float2 a0p = *(const float2*)&Ks[w * 16 + lr][k8 + 2 * lc];
            const float2 a1p = *(const float2*)&Ks[w * 16 + 8 + lr][k8 + 2 * lc];
            af[0] = F2U(a0p.x); af[2] = F2U(a0p.y);
            af[1] = F2U(a1p.x); af[3] = F2U(a1p.y);
            #pragma unroll
            for (int jn = 0; jn < 8; jn++) {
                const float2 bp = *(const float2*)&Qs[cur][jn * 8 + lr][k8 + 2 * lc];
                mma8(acc[jn], af, F2U(bp.x), F2U(bp.y));
            }
        }

        if (tb > tb0 + 1) {
            // fully unmasked fast path
            float tm0 = NEGBIG, tm1 = NEGBIG;
            #pragma unroll
            for (int jn = 0; jn < 8; jn++) {
                tm0 = fmaxf(tm0, fmaxf(acc[jn][0], acc[jn][1]));
                tm1 = fmaxf(tm1, fmaxf(acc[jn][2], acc[jn][3]));
            }
            const float nm0 = fmaxf(m0, tm0);
            const float nm1 = fmaxf(m1, tm1);
            float s0 = 0.f, s1 = 0.f;
            #pragma unroll
            for (int jn = 0; jn < 8; jn++) {
                s0 += fex2(acc[jn][0] - nm0) + fex2(acc[jn][1] - nm0);
                s1 += fex2(acc[jn][2] - nm1) + fex2(acc[jn][3] - nm1);
            }
            z0 = z0 * fex2(m0 - nm0) + s0; m0 = nm0;
            z1 = z1 * fex2(m1 - nm1) + s1; m1 = nm1;
        } else {
            const int tbase = tb * 64 + lc * 2;
            float tm0 = NEGBIG, tm1 = NEGBIG;
            float va[8][4];
            #pragma unroll
            for (int jn = 0; jn < 8; jn++) {
                const int tcol = tbase + jn * 8;
                va[jn][0] = (tcol     >= Trow0) ? acc[jn][0] : NEGBIG;
                va[jn][1] = (tcol + 1 >= Trow0) ? acc[jn][1] : NEGBIG;
                va[jn][2] = (tcol     >= Trow1) ? acc[jn][2] : NEGBIG;
                va[jn][3] = (tcol + 1 >= Trow1) ? acc[jn][3] : NEGBIG;
                tm0 = fmaxf(tm0, fmaxf(va[jn][0], va[jn][1]));
                tm1 = fmaxf(tm1, fmaxf(va[jn][2], va[jn][3]));
            }
            const float nm0 = fmaxf(m0, tm0);
            const float nm1 = fmaxf(m1, tm1);
            float s0 = 0.f, s1 = 0.f;
            #pragma unroll
            for (int jn = 0; jn < 8; jn++) {
                s0 += fex2(va[jn][0] - nm0) + fex2(va[jn][1] - nm0);
                s1 += fex2(va[jn][2] - nm1) + fex2(va[jn][3] - nm1);
            }
            z0 = z0 * fex2(m0 - nm0) + s0; m0 = nm0;
            z1 = z1 * fex2(m1 - nm1) + s1; m1 = nm1;
        }
    }

    #pragma unroll
    for (int off = 1; off < 4; off <<= 1) {
        float mo = __shfl_xor_sync(0xffffffffu, m0, off);
        float zo = __shfl_xor_sync(0xffffffffu, z0, off);
        float mn = fmaxf(m0, mo);
        z0 = z0 * fex2(m0 - mn) + zo * fex2(mo - mn); m0 = mn;
        mo = __shfl_xor_sync(0xffffffffu, m1, off);
        zo = __shfl_xor_sync(0xffffffffu, z1, off);
        mn = fmaxf(m1, mo);
        z1 = z1 * fex2(m1 - mn) + zo * fex2(mo - mn); m1 = mn;
    }
    if (lc == 0) {
        gm[g * Sn + Trow0] = m0;  gzi[g * Sn + Trow0] = 1.0f / z0;
        gm[g * Sn + Trow1] = m1;  gzi[g * Sn + Trow1] = 1.0f / z1;
    }
}
#define STATS_SMEM ((128 * 72 + 2 * 64 * 72) * 4)

// ---------------- pass 2: exp2 softmax apply, O = P @ V ----------------
__global__ __launch_bounds__(256, 2) void out_pass(
    const float* __restrict__ QKV,
    const float* __restrict__ gm, const float* __restrict__ gzi,
    float* __restrict__ O)
{
    extern __shared__ float sm[];
    float (*Qs)[72] = (float(*)[72])sm;                          // [128][72]
    float (*Ks)[72] = (float(*)[72])(sm + 128 * 72);             // [64][72]
    float (*Vs)[72] = (float(*)[72])(sm + 128 * 72 + 64 * 72);   // [64][72]
    float (*Ps)[72] = (float(*)[72])(sm + 128 * 72 + 2 * 64 * 72); // [128][72]
    float* s_st = sm + 2 * 128 * 72 + 2 * 64 * 72;               // [128]

    const int g = blockIdx.y;
    const int b = g >> 5, hq = g & 31, h = hq >> 2;
    const int tblk = (NTB128 - 1) - blockIdx.x;
    const int t0 = tblk * 128;

    const int tid = threadIdx.x;
    const int lane = tid & 31, wid = tid >> 5;
    const int warp_m = wid & 3, warp_n = wid >> 2;
    const int lr = lane >> 2, lc = lane & 3;
    const int r = tid >> 4, c = (tid & 15) * 4;

    const float* Qbase = QKV + hq * HDn;
    const float* Kbase = QKV + 2048 + h * HDn;
    const float* Vbase = QKV + 2560 + h * HDn;

    #pragma unroll
    for (int p = 0; p < 8; p++) {
        const int row = p * 16 + r;
        *(float4*)&Qs[row][c] =
            *(const float4*)&Qbase[(size_t)(b * Sn + t0 + row) * QKVW + c];
    }

    // prologue: group A0 = K(0) + stats(0)
    #pragma unroll
    for (int p = 0; p < 4; p++) {
        const int row = p * 16 + r;
        cpa16(&Ks[row][c], &Kbase[(size_t)(b * Sn + row) * QKVW + c]);
    }
    if (tid < 16)      cpa16(&s_st[tid * 4],             &gm[g * Sn + tid * 4]);
    else if (tid < 32) cpa16(&s_st[64 + (tid - 16) * 4], &gzi[g * Sn + (tid - 16) * 4]);
    CP_COMMIT();

    float acc2[2][4][4];
    #pragma unroll
    for (int i = 0; i < 2; i++)
        #pragma unroll
        for (int j = 0; j < 4; j++)
            #pragma unroll
            for (int q = 0; q < 4; q++) acc2[i][j][q] = 0.f;

    const int nT = 2 * tblk + 2;
    for (int Tb = 0; Tb < nT; Tb++) {
        const int T0 = Tb * 64;

        __syncthreads();
        #pragma unroll
        for (int p = 0; p < 4; p++) {
            const int row = p * 16 + r;
            cpa16(&Vs[row][c], &Vbase[(size_t)(b * Sn + T0 + row) * QKVW + c]);
        }
        CP_COMMIT();
        CP_WAIT(1);                                // K(Tb) + stats(Tb)
        __syncthreads();

        // stage 1: S = Q . K   (paired 64-bit fragment loads, exp2 domain)
        float acc1[2][4][4];
        #pragma unroll
        for (int i = 0; i < 2; i++)
            #pragma unroll
            for (int j = 0; j < 4; j++)
                #pragma unroll
                for (int q = 0; q < 4; q++) acc1[i][j][q] = 0.f;

        #pragma unroll
        for (int ks = 0; ks < 8; ks++) {
            const int k8 = ks * 8;
            uint32_t af[2][4];
            #pragma unroll
            for (int im = 0; im < 2; im++) {
                const int m = warp_m * 32 + im * 16 + lr;
                const float2 a0p = *(const float2*)&Qs[m][k8 + 2 * lc];
                const float2 a1p = *(const float2*)&Qs[m + 8][k8 + 2 * lc];
                af[im][0] = F2U(a0p.x); af[im][2] = F2U(a0p.y);
                af[im][1] = F2U(a1p.x); af[im][3] = F2U(a1p.y);
            }
            #pragma unroll
            for (int jn = 0; jn < 4; jn++) {
                const int n = warp_n * 32 + jn * 8 + lr;
                const float2 bp = *(const float2*)&Ks[n][k8 + 2 * lc];
                #pragma unroll
                for (int im = 0; im < 2; im++)
                    mma8(acc1[im][jn], af[im], F2U(bp.x), F2U(bp.y));
            }
        }

        const bool diag = (Tb >= 2 * tblk);
        #pragma unroll
        for (int im = 0; im < 2; im++) {
            const int trow = warp_m * 32 + im * 16 + lr;
            const int trg = t0 + trow;
            #pragma unroll
            for (int jn = 0; jn < 4; jn++) {
                const int Tcol = warp_n * 32 + jn * 8 + lc * 2;
                const int Tg = T0 + Tcol;
                const float mm0 = s_st[Tcol],      zi0 = s_st[64 + Tcol];
                const float mm1 = s_st[Tcol + 1],  zi1 = s_st[64 + Tcol + 1];
                float p00 = fex2(acc1[im][jn][0] - mm0) * zi0;
                float p01 = fex2(acc1[im][jn][1] - mm1) * zi1;
                float p10 = fex2(acc1[im][jn][2] - mm0) * zi0;
                float p11 = fex2(acc1[im][jn][3] - mm1) * zi1;
                if (diag) {
                    if (trg < Tg)         p00 = 0.f;
                    if (trg < Tg + 1)     p01 = 0.f;
                    if (trg + 8 < Tg)     p10 = 0.f;
                    if (trg + 8 < Tg + 1) p11 = 0.f;
                }
                *(float2*)&Ps[trow][Tcol]     = make_float2(f2tf(p00), f2tf(p01));
                *(float2*)&Ps[trow + 8][Tcol] = make_float2(f2tf(p10), f2tf(p11));
            }
        }
        __syncthreads();                           // Ps ready; Ks, s_st free

        if (Tb + 1 < nT) {
            const int Tn = (Tb + 1) * 64;
            #pragma unroll
            for (int p = 0; p < 4; p++) {
                const int row = p * 16 + r;
                cpa16(&Ks[row][c], &Kbase[(size_t)(b * Sn + Tn + row) * QKVW + c]);
            }
            if (tid < 16)      cpa16(&s_st[tid * 4],             &gm[g * Sn + Tn + tid * 4]);
            else if (tid < 32) cpa16(&s_st[64 + (tid - 16) * 4], &gzi[g * Sn + Tn + (tid - 16) * 4]);
        }
        CP_COMMIT();
        CP_WAIT(1);                                // V(Tb)
        __syncthreads();

        // stage 2: O += P @ V  (unchanged logical k-layout)
        #pragma unroll
        for (int ks = 0; ks < 8; ks++) {
            const int k8 = ks * 8;
            uint32_t af[2][4];
            #pragma unroll
            for (int im = 0; im < 2; im++) {
                const int m = warp_m * 32 + im * 16 + lr;
                af[im][0] = F2U(Ps[m][k8 + lc]);
                af[im][1] = F2U(Ps[m + 8][k8 + lc]);
                af[im][2] = F2U(Ps[m][k8 + lc + 4]);
                af[im][3] = F2U(Ps[m + 8][k8 + lc + 4]);
            }
            #pragma unroll
            for (int jn = 0; jn < 4; jn++) {
                const int n = warp_n * 32 + jn * 8 + lr;
                uint32_t bf0 = F2U(Vs[k8 + lc][n]);
                uint32_t bf1 = F2U(Vs[k8 + lc + 4][n]);
                #pragma unroll
                for (int im = 0; im < 2; im++)
                    mma8(acc2[im][jn], af[im], bf0, bf1);
            }
        }
    }

    #pragma unroll
    for (int im = 0; im < 2; im++)
        #pragma unroll
        for (int jn = 0; jn < 4; jn++) {
            const int row = t0 + warp_m * 32 + im * 16 + lr;
            const int col = hq * HDn + warp_n * 32 + jn * 8 + lc * 2;
            *(float2*)&O[(size_t)(b * Sn + row) * (HQn * HDn) + col] =
                make_float2(f2tf(acc2[im][jn][0]), f2tf(acc2[im][jn][1]));
            *(float2*)&O[(size_t)(b * Sn + row + 8) * (HQn * HDn) + col] =
                make_float2(f2tf(acc2[im][jn][2]), f2tf(acc2[im][jn][3]));
        }
}
#define OUT_SMEM ((2 * 128 * 72 + 2 * 64 * 72 + 128) * 4)

// ---------------- launch ----------------
extern "C" void kernel_launch(void* const* d_in, const int* in_sizes, int n_in,
                              void* d_out, int out_size) {
    const float* x    = (const float*)d_in[0];
    const float* ln_g = (const float*)d_in[1];
    const float* ln_b = (const float*)d_in[2];
    const float* Wq   = (const float*)d_in[3];
    const float* bq   = (const float*)d_in[4];
    const float* Wk   = (const float*)d_in[5];
    const float* bk   = (const float*)d_in[6];
    const float* Wv   = (const float*)d_in[7];
    const float* bv   = (const float*)d_in[8];
    const float* Wo   = (const float*)d_in[9];
    const float* bo   = (const float*)d_in[10];
    float* out = (float*)d_out;

    float *xn, *qkv, *wf, *bf, *wo, *attn, *m, *zi;
    cudaGetSymbolAddress((void**)&xn,   g_xn);
    cudaGetSymbolAddress((void**)&qkv,  g_qkv);
    cudaGetSymbolAddress((void**)&wf,   g_wf);
    cudaGetSymbolAddress((void**)&bf,   g_bf);
    cudaGetSymbolAddress((void**)&wo,   g_wo);
    cudaGetSymbolAddress((void**)&attn, g_attn);
    cudaGetSymbolAddress((void**)&m,    g_m);
    cudaGetSymbolAddress((void**)&zi,   g_zi);

    cudaFuncSetAttribute(gemm_cp,    cudaFuncAttributeMaxDynamicSharedMemorySize, GEMM_SMEM);
    cudaFuncSetAttribute(stats_pass, cudaFuncAttributeMaxDynamicSharedMemorySize, STATS_SMEM);
    cudaFuncSetAttribute(out_pass,   cudaFuncAttributeMaxDynamicSharedMemorySize, OUT_SMEM);

    fused_pre<<<ROWS + 6144 + 4096 + 12, 256>>>(
        x, ln_g, ln_b, Wq, Wk, Wv, Wo, bq, bk, bv, xn, wf, wo, bf);

    // Q pre-scaled by 0.125*log2(e) so softmax runs in exp2 domain
    gemm_cp<<<dim3(QKVW / 128, ROWS / 128), 256, GEMM_SMEM>>>(
        xn, wf, bf, qkv, ROWS, QKVW, Dn, QSCALE, 1.0f, 2048, 1);

    stats_pass<<<dim3(NTB128, NG), 256, STATS_SMEM>>>(qkv, m, zi);
    out_pass<<<dim3(NTB128, NG), 256, OUT_SMEM>>>(qkv, m, zi, attn);

    gemm_cp<<<dim3(Dn / 128, ROWS / 128), 256, GEMM_SMEM>>>(
        attn, wo, bo, out, ROWS, Dn, HQn * HDn, 1.0f, 1.0f, 0, 0);
}

// round 11
// speedup vs baseline: 4.8935x; 1.0277x over previous
#include <cuda_runtime.h>
#include <cuda_bf16.h>
#include <cstdint>
#include <math.h>

#define Bn 2
#define Sn 2048
#define Dn 2048
#define HQn 32
#define HKVn 8
#define HDn 64
#define ROWS (Bn * Sn)      // 4096
#define NG   (Bn * HQn)     // 64 attention "heads"
#define NTB64 (Sn / 64)     // 32
#define NTB128 (Sn / 128)   // 16
#define QKVW 3072           // fused q|k|v width
#define QSCALE 0.18033688011112042f   // 0.125 * log2(e)

// ---------------- scratch ----------------
__device__ float g_xn[ROWS * Dn];
__device__ float g_qkv[(size_t)ROWS * QKVW];
__device__ float g_wf[Dn * QKVW];
__device__ float g_bf[QKVW];
__device__ float g_wo[Dn * Dn];
__device__ float g_attn[ROWS * (HQn * HDn)];
__device__ float g_m[NG * Sn];
__device__ float g_zi[NG * Sn];

// ---------------- helpers ----------------
__device__ __forceinline__ float f2tf(float x) {
    uint32_t r;
    asm("cvt.rna.tf32.f32 %0, %1;" : "=r"(r) : "f"(x));
    return __uint_as_float(r);
}
__device__ __forceinline__ float4 cvt4(float4 v) {
    v.x = f2tf(v.x); v.y = f2tf(v.y); v.z = f2tf(v.z); v.w = f2tf(v.w);
    return v;
}
__device__ __forceinline__ float fex2(float x) {
    float r;
    asm("ex2.approx.ftz.f32 %0, %1;" : "=f"(r) : "f"(x));
    return r;
}
__device__ __forceinline__ void mma8(float* c, const uint32_t* a, uint32_t b0, uint32_t b1) {
    asm volatile(
        "mma.sync.aligned.m16n8k8.row.col.f32.tf32.tf32.f32 "
        "{%0,%1,%2,%3}, {%4,%5,%6,%7}, {%8,%9}, {%0,%1,%2,%3};"
        : "+f"(c[0]), "+f"(c[1]), "+f"(c[2]), "+f"(c[3])
        : "r"(a[0]), "r"(a[1]), "r"(a[2]), "r"(a[3]), "r"(b0), "r"(b1));
}
__device__ __forceinline__ void cpa16(void* dst_smem, const void* src) {
    uint32_t d = (uint32_t)__cvta_generic_to_shared(dst_smem);
    asm volatile("cp.async.cg.shared.global [%0], [%1], 16;" :: "r"(d), "l"(src));
}
#define CP_COMMIT() asm volatile("cp.async.commit_group;")
#define CP_WAIT(n)  asm volatile("cp.async.wait_group %0;" :: "n"(n))
#define F2U(x) __float_as_uint(x)
#define NEGBIG (-1e30f)

// ---------------- fused pre: LN + weight/bias prep ----------------
__global__ __launch_bounds__(256) void fused_pre(
    const float* __restrict__ x, const float* __restrict__ gamma,
    const float* __restrict__ beta,
    const float* __restrict__ Wq, const float* __restrict__ Wk,
    const float* __restrict__ Wv, const float* __restrict__ Wo,
    const float* __restrict__ bq, const float* __restrict__ bk,
    const float* __restrict__ bv,
    float* __restrict__ xn, float* __restrict__ Wf,
    float* __restrict__ Wr, float* __restrict__ bf)
{
    const int blk = blockIdx.x;
    const int tid = threadIdx.x;

    if (blk < ROWS) {
        const int row = blk;
        const float* xr = x + (size_t)row * Dn;
        float* outr = xn + (size_t)row * Dn;
        __shared__ float red[256];

        float s = 0.f;
        for (int c = tid; c < Dn; c += 256) s += xr[c];
        red[tid] = s; __syncthreads();
        for (int off = 128; off > 0; off >>= 1) {
            if (tid < off) red[tid] += red[tid + off];
            __syncthreads();
        }
        const float mu = red[0] * (1.0f / Dn);
        __syncthreads();

        float v = 0.f;
        for (int c = tid; c < Dn; c += 256) { float d = xr[c] - mu; v += d * d; }
        red[tid] = v; __syncthreads();
        for (int off = 128; off > 0; off >>= 1) {
            if (tid < off) red[tid] += red[tid + off];
            __syncthreads();
        }
        const float rstd = rsqrtf(red[0] * (1.0f / Dn) + 1e-5f);
        __syncthreads();

        for (int c = tid; c < Dn; c += 256)
            outr[c] = f2tf((xr[c] - mu) * rstd * gamma[c] + beta[c]);
    } else if (blk < ROWS + 6144) {
        const int idx = ((blk - ROWS) * 256 + tid) * 4;
        const int row = idx / QKVW, col = idx % QKVW;
        const float* src;
        if (col < 2048)      src = &Wq[(size_t)row * 2048 + col];
        else if (col < 2560) src = &Wk[(size_t)row * 512 + col - 2048];
        else                 src = &Wv[(size_t)row * 512 + col - 2560];
        *(float4*)&Wf[idx] = cvt4(*(const float4*)src);
    } else if (blk < ROWS + 6144 + 4096) {
        const int idx = ((blk - ROWS - 6144) * 256 + tid) * 4;
        *(float4*)&Wr[idx] = cvt4(*(const float4*)&Wo[idx]);
    } else {
        const int col = (blk - ROWS - 6144 - 4096) * 256 + tid;
        if (col < QKVW)
            bf[col] = col < 2048 ? bq[col] : (col < 2560 ? bk[col - 2048] : bv[col - 2560]);
    }
}

// ---------------- cp.async 3-stage tf32 GEMM ----------------
#define STAGES 3
#define GEMM_SMEM (STAGES * (128 * 20 + 16 * 136) * 4)

__global__ __launch_bounds__(256, 2) void gemm_cp(
    const float* __restrict__ A, const float* __restrict__ B,
    const float* __restrict__ bias, float* __restrict__ C,
    int M, int N, int K, float scale0, float scale1, int ncut, int round_out)
{
    extern __shared__ float sm[];
    float (*As)[128][20] = (float(*)[128][20])sm;
    float (*Bs)[16][136] = (float(*)[16][136])(sm + STAGES * 128 * 20);

    const int tid = threadIdx.x;
    const int lane = tid & 31, wid = tid >> 5;
    const int warp_m = wid & 3, warp_n = wid >> 2;
    const int m0 = blockIdx.y * 128, n0 = blockIdx.x * 128;

    const int ar = tid >> 2, ac = (tid & 3) * 4;
    const int br = tid >> 5, bc = (tid & 31) * 4;
    const int lr = lane >> 2, lc = lane & 3;

    const int KT = K / 16;

    float acc[2][8][4];
    #pragma unroll
    for (int i = 0; i < 2; i++)
        #pragma unroll
        for (int j = 0; j < 8; j++)
            #pragma unroll
            for (int q = 0; q < 4; q++) acc[i][j][q] = 0.f;

    #pragma unroll
    for (int s = 0; s < STAGES - 1; s++) {
        const int k0 = s * 16;
        const float* ap = &A[(size_t)(m0 + ar) * K + k0 + ac];
        cpa16(&As[s][ar][ac], ap);
        cpa16(&As[s][ar + 64][ac], ap + (size_t)64 * K);
        const float* bp = &B[(size_t)(k0 + br) * N + n0 + bc];
        cpa16(&Bs[s][br][bc], bp);
        cpa16(&Bs[s][br + 8][bc], bp + (size_t)8 * N);
        CP_COMMIT();
    }

    for (int kt = 0; kt < KT; kt++) {
        CP_WAIT(STAGES - 2);
        __syncthreads();

        const int nf = kt + STAGES - 1;
        if (nf < KT) {
            const int s = nf % STAGES;
            const int k0 = nf * 16;
            const float* ap = &A[(size_t)(m0 + ar) * K + k0 + ac];
            cpa16(&As[s][ar][ac], ap);
            cpa16(&As[s][ar + 64][ac], ap + (size_t)64 * K);
            const float* bp = &B[(size_t)(k0 + br) * N + n0 + bc];
            cpa16(&Bs[s][br][bc], bp);
            cpa16(&Bs[s][br + 8][bc], bp + (size_t)8 * N);
        }
        CP_COMMIT();

        const int cur = kt % STAGES;
        #pragma unroll
        for (int ks = 0; ks < 2; ks++) {
            const int k8 = ks * 8;
            uint32_t af[2][4];
            #pragma unroll
            for (int im = 0; im < 2; im++) {
                const int m = warp_m * 32 + im * 16 + lr;
                af[im][0] = F2U(As[cur][m][k8 + lc]);
                af[im][1] = F2U(As[cur][m + 8][k8 + lc]);
                af[im][2] = F2U(As[cur][m][k8 + lc + 4]);
                af[im][3] = F2U(As[cur][m + 8][k8 + lc + 4]);
            }
            #pragma unroll
            for (int jn = 0; jn < 8; jn++) {
                const int n = warp_n * 64 + jn * 8 + lr;
                uint32_t bf0 = F2U(Bs[cur][k8 + lc][n]);
                uint32_t bf1 = F2U(Bs[cur][k8 + lc + 4][n]);
                #pragma unroll
                for (int im = 0; im < 2; im++)
                    mma8(acc[im][jn], af[im], bf0, bf1);
            }
        }
    }

    #pragma unroll
    for (int im = 0; im < 2; im++)
        #pragma unroll
        for (int jn = 0; jn < 8; jn++) {
            const int row = m0 + warp_m * 32 + im * 16 + lr;
            const int col = n0 + warp_n * 64 + jn * 8 + lc * 2;
            const float sc = (col < ncut) ? scale0 : scale1;
            const float bb0 = bias[col], bb1 = bias[col + 1];
            float v00 = sc * (acc[im][jn][0] + bb0);
            float v01 = sc * (acc[im][jn][1] + bb1);
            float v10 = sc * (acc[im][jn][2] + bb0);
            float v11 = sc * (acc[im][jn][3] + bb1);
            if (round_out) { v00 = f2tf(v00); v01 = f2tf(v01); v10 = f2tf(v10); v11 = f2tf(v11); }
            *(float2*)&C[(size_t)row * N + col] = make_float2(v00, v01);
            *(float2*)&C[(size_t)(row + 8) * N + col] = make_float2(v10, v11);
        }
}

// ---------------- pass 1: column softmax stats (exp2 domain) ----------------
__global__ __launch_bounds__(256, 2) void stats_pass(
    const float* __restrict__ QKV,
    float* __restrict__ gm, float* __restrict__ gzi)
{
    extern __shared__ float sm[];
    float (*Ks)[72] = (float(*)[72])sm;                       // [128][72]
    float (*Qs)[64][72] = (float(*)[64][72])(sm + 128 * 72);  // [2][64][72]

    const int g = blockIdx.y;
    const int b = g >> 5, hq = g & 31, h = hq >> 2;
    const int Tb = blockIdx.x;
    const int T0 = Tb * 128;

    const int tid = threadIdx.x;
    const int lane = tid & 31, w = tid >> 5;
    const int lr = lane >> 2, lc = lane & 3;
    const int r = tid >> 4, c = (tid & 15) * 4;

    const float* Kbase = QKV + 2048 + h * HDn;
    const float* Qbase = QKV + hq * HDn;

    #pragma unroll
    for (int p = 0; p < 8; p++) {
        const int row = p * 16 + r;
        *(float4*)&Ks[row][c] =
            *(const float4*)&Kbase[(size_t)(b * Sn + T0 + row) * QKVW + c];
    }

    const int tb0 = 2 * Tb;
    #pragma unroll
    for (int p = 0; p < 4; p++) {
        const int row = p * 16 + r;
        cpa16(&Qs[0][row][c], &Qbase[(size_t)(b * Sn + tb0 * 64 + row) * QKVW + c]);
    }
    CP_COMMIT();

    const int Trow0 = T0 + w * 16 + lr;
    const int Trow1 = Trow0 + 8;

    float m0 = NEGBIG, z0 = 0.f, m1 = NEGBIG, z1 = 0.f;

    for (int tb = tb0; tb < NTB64; tb++) {
        const int cur = (tb - tb0) & 1;
        __syncthreads();
        if (tb + 1 < NTB64) {
            #pragma unroll
            for (int p = 0; p < 4; p++) {
                const int row = p * 16 + r;
                cpa16(&Qs[cur ^ 1][row][c],
                      &Qbase[(size_t)(b * Sn + (tb + 1) * 64 + row) * QKVW + c]);
            }
        }
        CP_COMMIT();
        CP_WAIT(1);
        __syncthreads();

        float acc[8][4];
        #pragma unroll
        for (int j = 0; j < 8; j++)
            #pragma unroll
            for (int q = 0; q < 4; q++) acc[j][q] = 0.f;

        #pragma unroll
        for (int ks = 0; ks < 8; ks++) {
            const int k8 = ks * 8;
            uint32_t af[4];
            const float2 a0p = *(const float2*)&Ks[w * 16 + lr][k8 + 2 * lc];
            const float2 a1p = *(const float2*)&Ks[w * 16 + 8 + lr][k8 + 2 * lc];
            af[0] = F2U(a0p.x); af[2] = F2U(a0p.y);
            af[1] = F2U(a1p.x); af[3] = F2U(a1p.y);
            #pragma unroll
            for (int jn = 0; jn < 8; jn++) {
                const float2 bp = *(const float2*)&Qs[cur][jn * 8 + lr][k8 + 2 * lc];
                mma8(acc[jn], af, F2U(bp.x), F2U(bp.y));
            }
        }

        if (tb > tb0 + 1) {
            float tm0 = NEGBIG, tm1 = NEGBIG;
            #pragma unroll
            for (int jn = 0; jn < 8; jn++) {
                tm0 = fmaxf(tm0, fmaxf(acc[jn][0], acc[jn][1]));
                tm1 = fmaxf(tm1, fmaxf(acc[jn][2], acc[jn][3]));
            }
            const float nm0 = fmaxf(m0, tm0);
            const float nm1 = fmaxf(m1, tm1);
            float s0 = 0.f, s1 = 0.f;
            #pragma unroll
            for (int jn = 0; jn < 8; jn++) {
                s0 += fex2(acc[jn][0] - nm0) + fex2(acc[jn][1] - nm0);
                s1 += fex2(acc[jn][2] - nm1) + fex2(acc[jn][3] - nm1);
            }
            z0 = z0 * fex2(m0 - nm0) + s0; m0 = nm0;
            z1 = z1 * fex2(m1 - nm1) + s1; m1 = nm1;
        } else {
            const int tbase = tb * 64 + lc * 2;
            float tm0 = NEGBIG, tm1 = NEGBIG;
            float va[8][4];
            #pragma unroll
            for (int jn = 0; jn < 8; jn++) {
                const int tcol = tbase + jn * 8;
                va[jn][0] = (tcol     >= Trow0) ? acc[jn][0] : NEGBIG;
                va[jn][1] = (tcol + 1 >= Trow0) ? acc[jn][1] : NEGBIG;
                va[jn][2] = (tcol     >= Trow1) ? acc[jn][2] : NEGBIG;
                va[jn][3] = (tcol + 1 >= Trow1) ? acc[jn][3] : NEGBIG;
                tm0 = fmaxf(tm0, fmaxf(va[jn][0], va[jn][1]));
                tm1 = fmaxf(tm1, fmaxf(va[jn][2], va[jn][3]));
            }
            const float nm0 = fmaxf(m0, tm0);
            const float nm1 = fmaxf(m1, tm1);
            float s0 = 0.f, s1 = 0.f;
            #pragma unroll
            for (int jn = 0; jn < 8; jn++) {
                s0 += fex2(va[jn][0] - nm0) + fex2(va[jn][1] - nm0);
                s1 += fex2(va[jn][2] - nm1) + fex2(va[jn][3] - nm1);
            }
            z0 = z0 * fex2(m0 - nm0) + s0; m0 = nm0;
            z1 = z1 * fex2(m1 - nm1) + s1; m1 = nm1;
        }
    }

    #pragma unroll
    for (int off = 1; off < 4; off <<= 1) {
        float mo = __shfl_xor_sync(0xffffffffu, m0, off);
        float zo = __shfl_xor_sync(0xffffffffu, z0, off);
        float mn = fmaxf(m0, mo);
        z0 = z0 * fex2(m0 - mn) + zo * fex2(mo - mn); m0 = mn;
        mo = __shfl_xor_sync(0xffffffffu, m1, off);
        zo = __shfl_xor_sync(0xffffffffu, z1, off);
        mn = fmaxf(m1, mo);
        z1 = z1 * fex2(m1 - mn) + zo * fex2(mo - mn); m1 = mn;
    }
    if (lc == 0) {
        gm[g * Sn + Trow0] = m0;  gzi[g * Sn + Trow0] = 1.0f / z0;
        gm[g * Sn + Trow1] = m1;  gzi[g * Sn + Trow1] = 1.0f / z1;
    }
}
#define STATS_SMEM ((128 * 72 + 2 * 64 * 72) * 4)

// ---------------- pass 2: register-P flash; warp = 16t x full 64T ----------------
// K/V/stats fully double-buffered, one cp group per iteration, 2 syncs/iter.
__global__ __launch_bounds__(256, 2) void out_pass(
    const float* __restrict__ QKV,
    const float* __restrict__ gm, const float* __restrict__ gzi,
    float* __restrict__ O)
{
    extern __shared__ float sm[];
    float (*Qs)[72] = (float(*)[72])sm;                              // [128][72]
    float (*Ks)[64][72] = (float(*)[64][72])(sm + 128 * 72);         // [2][64][72]
    float (*Vs)[64][68] = (float(*)[64][68])(sm + 128 * 72 + 2 * 64 * 72); // [2][64][68]
    float* s_st = sm + 128 * 72 + 2 * 64 * 72 + 2 * 64 * 68;         // [2][128]

    const int g = blockIdx.y;
    const int b = g >> 5, hq = g & 31, h = hq >> 2;
    const int tblk = (NTB128 - 1) - blockIdx.x;
    const int t0 = tblk * 128;

    const int tid = threadIdx.x;
    const int lane = tid & 31, w = tid >> 5;     // warp owns t rows w*16 .. w*16+15
    const int lr = lane >> 2, lc = lane & 3;
    const int r = tid >> 4, c = (tid & 15) * 4;

    const float* Qbase = QKV + hq * HDn;
    const float* Kbase = QKV + 2048 + h * HDn;
    const float* Vbase = QKV + 2560 + h * HDn;

    #pragma unroll
    for (int p = 0; p < 8; p++) {
        const int row = p * 16 + r;
        *(float4*)&Qs[row][c] =
            *(const float4*)&Qbase[(size_t)(b * Sn + t0 + row) * QKVW + c];
    }

    // prologue: tile 0 (K + V + stats) -> buf 0
    #pragma unroll
    for (int p = 0; p < 4; p++) {
        const int row = p * 16 + r;
        cpa16(&Ks[0][row][c], &Kbase[(size_t)(b * Sn + row) * QKVW + c]);
        cpa16(&Vs[0][row][c], &Vbase[(size_t)(b * Sn + row) * QKVW + c]);
    }
    if (tid < 16)      cpa16(&s_st[tid * 4],             &gm[g * Sn + tid * 4]);
    else if (tid < 32) cpa16(&s_st[64 + (tid - 16) * 4], &gzi[g * Sn + (tid - 16) * 4]);
    CP_COMMIT();

    float acc2[8][4];
    #pragma unroll
    for (int j = 0; j < 8; j++)
        #pragma unroll
        for (int q = 0; q < 4; q++) acc2[j][q] = 0.f;

    const int trg0 = t0 + w * 16 + lr;
    const int trg1 = trg0 + 8;

    const int nT = 2 * tblk + 2;
    for (int Tb = 0; Tb < nT; Tb++) {
        const int T0 = Tb * 64;
        const int cur = Tb & 1;

        __syncthreads();                  // all warps done with buffer cur^1 (iter Tb-1)
        if (Tb + 1 < nT) {
            const int Tn = (Tb + 1) * 64;
            const int nxt = cur ^ 1;
            #pragma unroll
            for (int p = 0; p < 4; p++) {
                const int row = p * 16 + r;
                cpa16(&Ks[nxt][row][c], &Kbase[(size_t)(b * Sn + Tn + row) * QKVW + c]);
                cpa16(&Vs[nxt][row][c], &Vbase[(size_t)(b * Sn + Tn + row) * QKVW + c]);
            }
            if (tid < 16)      cpa16(&s_st[nxt * 128 + tid * 4],             &gm[g * Sn + Tn + tid * 4]);
            else if (tid < 32) cpa16(&s_st[nxt * 128 + 64 + (tid - 16) * 4], &gzi[g * Sn + Tn + (tid - 16) * 4]);
        }
        CP_COMMIT();
        CP_WAIT(1);                       // retires cp(Tb) — prefetched one iter ago
        __syncthreads();

        // stage 1: S = Q . K  (warp: 16 t-rows x full 64 T; paired 64-bit loads)
        float acc1[8][4];
        #pragma unroll
        for (int j = 0; j < 8; j++)
            #pragma unroll
            for (int q = 0; q < 4; q++) acc1[j][q] = 0.f;

        #pragma unroll
        for (int ks = 0; ks < 8; ks++) {
            const int k8 = ks * 8;
            uint32_t af[4];
            const float2 q0 = *(const float2*)&Qs[w * 16 + lr][k8 + 2 * lc];
            const float2 q1 = *(const float2*)&Qs[w * 16 + 8 + lr][k8 + 2 * lc];
            af[0] = F2U(q0.x); af[2] = F2U(q0.y);
            af[1] = F2U(q1.x); af[3] = F2U(q1.y);
            #pragma unroll
            for (int jn = 0; jn < 8; jn++) {
                const float2 kp = *(const float2*)&Ks[cur][jn * 8 + lr][k8 + 2 * lc];
                mma8(acc1[jn], af, F2U(kp.x), F2U(kp.y));
            }
        }

        // softmax apply IN REGISTERS -> P fragments (tf32-rounded)
        const float* smv = &s_st[cur * 128];
        const bool diag = (Tb >= 2 * tblk);
        #pragma unroll
        for (int jn = 0; jn < 8; jn++) {
            const int Tcol = jn * 8 + 2 * lc;
            const int Tg = T0 + Tcol;
            const float2 mm = *(const float2*)&smv[Tcol];
            const float2 zz = *(const float2*)&smv[64 + Tcol];
            float p00 = fex2(acc1[jn][0] - mm.x) * zz.x;   // (trg0, Tg)
            float p01 = fex2(acc1[jn][1] - mm.y) * zz.y;   // (trg0, Tg+1)
            float p10 = fex2(acc1[jn][2] - mm.x) * zz.x;   // (trg1, Tg)
            float p11 = fex2(acc1[jn][3] - mm.y) * zz.y;   // (trg1, Tg+1)
            if (diag) {
                if (trg0 < Tg)     p00 = 0.f;
                if (trg0 < Tg + 1) p01 = 0.f;
                if (trg1 < Tg)     p10 = 0.f;
                if (trg1 < Tg + 1) p11 = 0.f;
            }
            acc1[jn][0] = f2tf(p00);
            acc1[jn][1] = f2tf(p01);
            acc1[jn][2] = f2tf(p10);
            acc1[jn][3] = f2tf(p11);
        }

        // stage 2: O += P @ V   (A = P fragments in registers; V rows k-paired)
        #pragma unroll
        for (int kt = 0; kt < 8; kt++) {
            uint32_t af[4];
            af[0] = F2U(acc1[kt][0]);   // (lr,   k-slot lc)   = P(trg0, Tg)
            af[1] = F2U(acc1[kt][2]);   // (lr+8, k-slot lc)   = P(trg1, Tg)
            af[2] = F2U(acc1[kt][1]);   // (lr,   k-slot lc+4) = P(trg0, Tg+1)
            af[3] = F2U(acc1[kt][3]);   // (lr+8, k-slot lc+4) = P(trg1, Tg+1)
            const int krow = kt * 8 + 2 * lc;
            #pragma unroll
            for (int dn = 0; dn < 8; dn++) {
                const int d = dn * 8 + lr;
                const uint32_t bf0 = F2U(Vs[cur][krow][d]);
                const uint32_t bf1 = F2U(Vs[cur][krow + 1][d]);
                mma8(acc2[dn], af, bf0, bf1);
            }
        }
    }

    #pragma unroll
    for (int dn = 0; dn < 8; dn++) {
        const int col = hq * HDn + dn * 8 + lc * 2;
        *(float2*)&O[(size_t)(b * Sn + trg0) * (HQn * HDn) + col] =
            make_float2(f2tf(acc2[dn][0]), f2tf(acc2[dn][1]));
        *(float2*)&O[(size_t)(b * Sn + trg1) * (HQn * HDn) + col] =
            make_float2(f2tf(acc2[dn][2]), f2tf(acc2[dn][3]));
    }
}
#define OUT_SMEM ((128 * 72 + 2 * 64 * 72 + 2 * 64 * 68 + 256) * 4)

// ---------------- launch ----------------
extern "C" void kernel_launch(void* const* d_in, const int* in_sizes, int n_in,
                              void* d_out, int out_size) {
    const float* x    = (const float*)d_in[0];
    const float* ln_g = (const float*)d_in[1];
    const float* ln_b = (const float*)d_in[2];
    const float* Wq   = (const float*)d_in[3];
    const float* bq   = (const float*)d_in[4];
    const float* Wk   = (const float*)d_in[5];
    const float* bk   = (const float*)d_in[6];
    const float* Wv   = (const float*)d_in[7];
    const float* bv   = (const float*)d_in[8];
    const float* Wo   = (const float*)d_in[9];
    const float* bo   = (const float*)d_in[10];
    float* out = (float*)d_out;

    float *xn, *qkv, *wf, *bf, *wo, *attn, *m, *zi;
    cudaGetSymbolAddress((void**)&xn,   g_xn);
    cudaGetSymbolAddress((void**)&qkv,  g_qkv);
    cudaGetSymbolAddress((void**)&wf,   g_wf);
    cudaGetSymbolAddress((void**)&bf,   g_bf);
    cudaGetSymbolAddress((void**)&wo,   g_wo);
    cudaGetSymbolAddress((void**)&attn, g_attn);
    cudaGetSymbolAddress((void**)&m,    g_m);
    cudaGetSymbolAddress((void**)&zi,   g_zi);

    cudaFuncSetAttribute(gemm_cp,    cudaFuncAttributeMaxDynamicSharedMemorySize, GEMM_SMEM);
    cudaFuncSetAttribute(stats_pass, cudaFuncAttributeMaxDynamicSharedMemorySize, STATS_SMEM);
    cudaFuncSetAttribute(out_pass,   cudaFuncAttributeMaxDynamicSharedMemorySize, OUT_SMEM);

    fused_pre<<<ROWS + 6144 + 4096 + 12, 256>>>(
        x, ln_g, ln_b, Wq, Wk, Wv, Wo, bq, bk, bv, xn, wf, wo, bf);

    gemm_cp<<<dim3(QKVW / 128, ROWS / 128), 256, GEMM_SMEM>>>(
        xn, wf, bf, qkv, ROWS, QKVW, Dn, QSCALE, 1.0f, 2048, 1);

    stats_pass<<<dim3(NTB128, NG), 256, STATS_SMEM>>>(qkv, m, zi);
    out_pass<<<dim3(NTB128, NG), 256, OUT_SMEM>>>(qkv, m, zi, attn);

    gemm_cp<<<dim3(Dn / 128, ROWS / 128), 256, GEMM_SMEM>>>(
        attn, wo, bo, out, ROWS, Dn, HQn * HDn, 1.0f, 1.0f, 0, 0);
}